// round 5
// baseline (speedup 1.0000x reference)
#include <cuda_runtime.h>
#include <cuda_bf16.h>
#include <math.h>
#include <stdint.h>

#define M_TOK 32768
#define DMODEL 1024
#define CD 256
#define NC 4096

#define FLAG_THRESH 1.5e-3f

// ---------------------------------------------------------------------------
// Static device scratch
// ---------------------------------------------------------------------------
__device__ float g_half_norm[NC];
__device__ unsigned short g_x_hi[(size_t)M_TOK * DMODEL];
__device__ unsigned short g_x_lo[(size_t)M_TOK * DMODEL];
__device__ unsigned short g_w_hi[(size_t)CD * DMODEL];   // transposed [n][k]
__device__ unsigned short g_w_lo[(size_t)CD * DMODEL];
__device__ unsigned short g_z_hi[(size_t)M_TOK * CD];
__device__ unsigned short g_cb_hi[(size_t)NC * CD];
__device__ int g_flag_count;
__device__ int g_flag_list[M_TOK];

// ---------------------------------------------------------------------------
// PTX helpers
// ---------------------------------------------------------------------------
__device__ __forceinline__ uint32_t smem_u32(const void* p) {
    uint32_t a;
    asm("{ .reg .u64 t; cvta.to.shared.u64 t, %1; cvt.u32.u64 %0, t; }" : "=r"(a) : "l"(p));
    return a;
}
__device__ __forceinline__ void cp16(uint32_t dst, const void* src) {
    asm volatile("cp.async.cg.shared.global [%0], [%1], 16;" :: "r"(dst), "l"(src));
}
#define CP_COMMIT() asm volatile("cp.async.commit_group;" ::: "memory")
#define CP_WAIT(n)  asm volatile("cp.async.wait_group %0;" :: "n"(n) : "memory")

#define LDSM4(r0, r1, r2, r3, addr) \
    asm volatile("ldmatrix.sync.aligned.m8n8.x4.shared.b16 {%0,%1,%2,%3}, [%4];" \
                 : "=r"(r0), "=r"(r1), "=r"(r2), "=r"(r3) : "r"(addr))
#define LDSM2(r0, r1, addr) \
    asm volatile("ldmatrix.sync.aligned.m8n8.x2.shared.b16 {%0,%1}, [%2];" \
                 : "=r"(r0), "=r"(r1) : "r"(addr))

#define MMA16816(c, a, b) \
    asm volatile("mma.sync.aligned.m16n8k16.row.col.f32.bf16.bf16.f32 " \
                 "{%0,%1,%2,%3}, {%4,%5,%6,%7}, {%8,%9}, {%0,%1,%2,%3};" \
                 : "+f"((c)[0]), "+f"((c)[1]), "+f"((c)[2]), "+f"((c)[3]) \
                 : "r"((a)[0]), "r"((a)[1]), "r"((a)[2]), "r"((a)[3]), \
                   "r"((b)[0]), "r"((b)[1]))

// ---------------------------------------------------------------------------
// hi/lo bf16 split helpers
// ---------------------------------------------------------------------------
__device__ __forceinline__ void split4(float4 v, uint2& hi, uint2& lo) {
    float f[4] = {v.x, v.y, v.z, v.w};
    unsigned short h[4], l[4];
#pragma unroll
    for (int i = 0; i < 4; i++) {
        __nv_bfloat16 hb = __float2bfloat16(f[i]);
        h[i] = __bfloat16_as_ushort(hb);
        l[i] = __bfloat16_as_ushort(__float2bfloat16(f[i] - __bfloat162float(hb)));
    }
    hi.x = (uint32_t)h[0] | ((uint32_t)h[1] << 16);
    hi.y = (uint32_t)h[2] | ((uint32_t)h[3] << 16);
    lo.x = (uint32_t)l[0] | ((uint32_t)l[1] << 16);
    lo.y = (uint32_t)l[2] | ((uint32_t)l[3] << 16);
}

// ---------------------------------------------------------------------------
// Prep kernels
// ---------------------------------------------------------------------------
__global__ __launch_bounds__(256)
void conv_x_kernel(const float* __restrict__ x) {
    size_t gid = (size_t)blockIdx.x * 256 + threadIdx.x;
    float4 v = *(const float4*)&x[gid * 4];
    uint2 hi, lo; split4(v, hi, lo);
    *(uint2*)&g_x_hi[gid * 4] = hi;
    *(uint2*)&g_x_lo[gid * 4] = lo;
}

__global__ __launch_bounds__(256)
void conv_w_kernel(const float* __restrict__ W) {
    size_t gid = (size_t)blockIdx.x * 256 + threadIdx.x;
    int n = (int)(gid >> 10);
    int k = (int)(gid & 1023);
    float v = W[(size_t)k * CD + n];
    __nv_bfloat16 hb = __float2bfloat16(v);
    g_w_hi[gid] = __bfloat16_as_ushort(hb);
    g_w_lo[gid] = __bfloat16_as_ushort(__float2bfloat16(v - __bfloat162float(hb)));
}

__global__ __launch_bounds__(256)
void conv_z_kernel(const float* __restrict__ z) {
    size_t gid = (size_t)blockIdx.x * 256 + threadIdx.x;   // over M*CD/4
    float4 v = *(const float4*)&z[gid * 4];
    unsigned short h[4];
    float f[4] = {v.x, v.y, v.z, v.w};
#pragma unroll
    for (int i = 0; i < 4; i++) h[i] = __bfloat16_as_ushort(__float2bfloat16(f[i]));
    uint2 hi;
    hi.x = (uint32_t)h[0] | ((uint32_t)h[1] << 16);
    hi.y = (uint32_t)h[2] | ((uint32_t)h[3] << 16);
    *(uint2*)&g_z_hi[gid * 4] = hi;
}

__global__ __launch_bounds__(256)
void conv_cb_kernel(const float* __restrict__ cb) {
    size_t gid = (size_t)blockIdx.x * 256 + threadIdx.x;   // over NC*CD/4
    float4 v = *(const float4*)&cb[gid * 4];
    unsigned short h[4];
    float f[4] = {v.x, v.y, v.z, v.w};
#pragma unroll
    for (int i = 0; i < 4; i++) h[i] = __bfloat16_as_ushort(__float2bfloat16(f[i]));
    uint2 hi;
    hi.x = (uint32_t)h[0] | ((uint32_t)h[1] << 16);
    hi.y = (uint32_t)h[2] | ((uint32_t)h[3] << 16);
    *(uint2*)&g_cb_hi[gid * 4] = hi;
}

__global__ __launch_bounds__(256)
void normalize_kernel(float* __restrict__ z) {
    const int warp = threadIdx.x >> 5;
    const int lane = threadIdx.x & 31;
    const int row  = blockIdx.x * 8 + warp;
    float4* z4 = (float4*)z;
    size_t base = (size_t)row * 64;
    float4 v0 = z4[base + lane];
    float4 v1 = z4[base + 32 + lane];
    float s = v0.x*v0.x + v0.y*v0.y + v0.z*v0.z + v0.w*v0.w
            + v1.x*v1.x + v1.y*v1.y + v1.z*v1.z + v1.w*v1.w;
#pragma unroll
    for (int o = 16; o > 0; o >>= 1) s += __shfl_xor_sync(0xFFFFFFFFu, s, o);
    float inv = 1.0f / (sqrtf(s) + 1e-6f);
    v0.x *= inv; v0.y *= inv; v0.z *= inv; v0.w *= inv;
    v1.x *= inv; v1.y *= inv; v1.z *= inv; v1.w *= inv;
    z4[base + lane]      = v0;
    z4[base + 32 + lane] = v1;
}

__global__ __launch_bounds__(256)
void halfnorm_kernel(const float* __restrict__ cb) {
    const int warp = threadIdx.x >> 5;
    const int lane = threadIdx.x & 31;
    const int code = blockIdx.x * 8 + warp;
    const float4* c4 = (const float4*)cb;
    size_t base = (size_t)code * 64;
    float4 v0 = c4[base + lane];
    float4 v1 = c4[base + 32 + lane];
    float s = v0.x*v0.x + v0.y*v0.y + v0.z*v0.z + v0.w*v0.w
            + v1.x*v1.x + v1.y*v1.y + v1.z*v1.z + v1.w*v1.w;
#pragma unroll
    for (int o = 16; o > 0; o >>= 1) s += __shfl_xor_sync(0xFFFFFFFFu, s, o);
    if (lane == 0) g_half_norm[code] = 0.5f * s;
}

__global__ void reset_kernel() { g_flag_count = 0; }

// ---------------------------------------------------------------------------
// GEMM1 (mma.sync, 3-pass bf16 split) — unchanged (known good)
// ---------------------------------------------------------------------------
#define G1_SMEM (4 * 18432 + 4 * 18432)

__device__ __forceinline__ void g1_load(uint32_t XS, uint32_t WS, int buf, int kc,
                                        int rowBase, int colBase, int t) {
#pragma unroll
    for (int q = 0; q < 8; q++) {
        int i = t + 256 * q;
        int hl = i >> 10, r = (i >> 3) & 127, cc = i & 7;
        const unsigned short* src = (hl ? g_x_lo : g_x_hi)
            + (size_t)(rowBase + r) * DMODEL + kc * 64 + cc * 8;
        cp16(XS + (buf * 2 + hl) * 18432 + r * 144 + cc * 16, src);
    }
#pragma unroll
    for (int q = 0; q < 8; q++) {
        int i = t + 256 * q;
        int hl = i >> 10, r = (i >> 3) & 127, cc = i & 7;
        const unsigned short* src = (hl ? g_w_lo : g_w_hi)
            + (size_t)(colBase + r) * DMODEL + kc * 64 + cc * 8;
        cp16(WS + (buf * 2 + hl) * 18432 + r * 144 + cc * 16, src);
    }
}

__global__ __launch_bounds__(256, 1)
void gemm1_mma_kernel(const float* __restrict__ bias, float* __restrict__ z) {
    extern __shared__ unsigned char smem[];
    const uint32_t sb = smem_u32(smem);
    const uint32_t XS = sb;
    const uint32_t WS = sb + 4 * 18432;

    const int t = threadIdx.x, lane = t & 31, w = t >> 5;
    const int warpM = w & 1, warpN = w >> 1;
    const int rowBase = blockIdx.x * 128;
    const int colBase = blockIdx.y * 128;

    float acc[4][4][4];
#pragma unroll
    for (int mt = 0; mt < 4; mt++)
#pragma unroll
        for (int nt = 0; nt < 4; nt++)
#pragma unroll
            for (int c = 0; c < 4; c++) acc[mt][nt][c] = 0.0f;

    const uint32_t a_row  = warpM * 64 + (lane & 15);
    const uint32_t a_col8 = (lane >> 4) * 8;
    const uint32_t b_row  = warpN * 32 + (lane & 7);
    const uint32_t b_col8 = ((lane >> 3) & 1) * 8;

    g1_load(XS, WS, 0, 0, rowBase, colBase, t);
    CP_COMMIT();

    for (int kc = 0; kc < 16; kc++) {
        const int buf = kc & 1;
        if (kc + 1 < 16) { g1_load(XS, WS, (kc + 1) & 1, kc + 1, rowBase, colBase, t); CP_COMMIT(); CP_WAIT(1); }
        else             { CP_WAIT(0); }
        __syncthreads();

#pragma unroll
        for (int ks = 0; ks < 4; ks++) {
            uint32_t bh[4][2], bl[4][2];
#pragma unroll
            for (int nt = 0; nt < 4; nt++) {
                uint32_t baddr = WS + (buf * 2) * 18432 + ((b_row + nt * 8) * 72 + ks * 16 + b_col8) * 2;
                LDSM2(bh[nt][0], bh[nt][1], baddr);
                LDSM2(bl[nt][0], bl[nt][1], baddr + 18432);
            }
#pragma unroll
            for (int mt = 0; mt < 4; mt++) {
                uint32_t ah[4], al[4];
                uint32_t aaddr = XS + (buf * 2) * 18432 + ((a_row + mt * 16) * 72 + ks * 16 + a_col8) * 2;
                LDSM4(ah[0], ah[1], ah[2], ah[3], aaddr);
                LDSM4(al[0], al[1], al[2], al[3], aaddr + 18432);
#pragma unroll
                for (int nt = 0; nt < 4; nt++) {
                    MMA16816(acc[mt][nt], ah, bh[nt]);
                    MMA16816(acc[mt][nt], ah, bl[nt]);
                    MMA16816(acc[mt][nt], al, bh[nt]);
                }
            }
        }
        __syncthreads();
    }

    const int row0 = rowBase + warpM * 64 + (lane >> 2);
    const int col0 = colBase + warpN * 32 + (lane & 3) * 2;
#pragma unroll
    for (int mt = 0; mt < 4; mt++) {
#pragma unroll
        for (int nt = 0; nt < 4; nt++) {
            int r0 = row0 + mt * 16;
            int c  = col0 + nt * 8;
            float b0 = __ldg(&bias[c]), b1 = __ldg(&bias[c + 1]);
            *(float2*)&z[(size_t)r0 * CD + c]       = make_float2(acc[mt][nt][0] + b0, acc[mt][nt][1] + b1);
            *(float2*)&z[(size_t)(r0 + 8) * CD + c] = make_float2(acc[mt][nt][2] + b0, acc[mt][nt][3] + b1);
        }
    }
}

// ---------------------------------------------------------------------------
// Quant kernel: 1-pass hi*hi bf16 scores + top-2 margin certification.
// NO min-blocks clamp (R4 regression: (256,2) forced 128-reg cap -> spills).
// ---------------------------------------------------------------------------
#define Q_ZBYTES  (128 * 264 * 2)
#define Q_CBBYTES (2 * 18432)
#define Q_SMEM    (Q_ZBYTES + Q_CBBYTES)

__device__ __forceinline__ void top2_merge(float& b1, int& i1, float& b2,
                                           float ob1, int oi1, float ob2) {
    if (ob1 > b1)      { b2 = fmaxf(b1, ob2); b1 = ob1; i1 = oi1; }
    else if (ob1 == b1){ if (oi1 != i1) b2 = b1; else b2 = fmaxf(b2, ob2); i1 = min(i1, oi1); }
    else               { b2 = fmaxf(b2, ob1); }
}

__device__ __forceinline__ void q_load_cb(uint32_t CBB, int buf, int tt, int kc, int t) {
#pragma unroll
    for (int q = 0; q < 4; q++) {
        int i = t + 256 * q;
        int r = (i >> 3) & 127, cc = i & 7;
        int code = 1 + tt * 128 + r;
        if (code > NC - 1) code = NC - 1;
        const unsigned short* src = g_cb_hi + (size_t)code * CD + kc * 64 + cc * 8;
        cp16(CBB + buf * 18432 + r * 144 + cc * 16, src);
    }
}

__global__ __launch_bounds__(256, 1)
void quant_mma_kernel(const float* __restrict__ cb,
                      float* __restrict__ out_idx, float* __restrict__ out_hard) {
    extern __shared__ unsigned char smem[];
    const uint32_t sb  = smem_u32(smem);
    const uint32_t ZB  = sb;
    const uint32_t CBB = sb + Q_ZBYTES;

    const int t = threadIdx.x, lane = t & 31, w = t >> 5;
    const int warpM = w & 1, warpN = w >> 1;
    const int rowBase = blockIdx.x * 128;

    // stage z_hi tile, full K=256
#pragma unroll
    for (int q = 0; q < 16; q++) {
        int i = t + 256 * q;
        int r = i >> 5, cc = i & 31;
        const unsigned short* src = g_z_hi + (size_t)(rowBase + r) * CD + cc * 8;
        cp16(ZB + r * 528 + cc * 16, src);
    }
    q_load_cb(CBB, 0, 0, 0, t);
    CP_COMMIT();

    float acc[4][4][4];
#pragma unroll
    for (int mt = 0; mt < 4; mt++)
#pragma unroll
        for (int nt = 0; nt < 4; nt++)
#pragma unroll
            for (int c = 0; c < 4; c++) acc[mt][nt][c] = 0.0f;

    float best[8], sec[8];
    int   bidx[8];
#pragma unroll
    for (int s = 0; s < 8; s++) { best[s] = -3.0e38f; sec[s] = -3.0e38f; bidx[s] = 1; }

    const uint32_t a_row  = warpM * 64 + (lane & 15);
    const uint32_t a_col8 = (lane >> 4) * 8;
    const uint32_t b_row  = warpN * 32 + (lane & 7);
    const uint32_t b_col8 = ((lane >> 3) & 1) * 8;

    for (int it = 0; it < 128; it++) {
        const int tt = it >> 2, kc = it & 3, buf = it & 1;
        if (it + 1 < 128) { q_load_cb(CBB, (it + 1) & 1, (it + 1) >> 2, (it + 1) & 3, t); CP_COMMIT(); CP_WAIT(1); }
        else              { CP_WAIT(0); }
        __syncthreads();

#pragma unroll
        for (int ks = 0; ks < 4; ks++) {
            const int k = kc * 64 + ks * 16;
            uint32_t bh[4][2];
#pragma unroll
            for (int nt = 0; nt < 4; nt++) {
                uint32_t baddr = CBB + buf * 18432 + ((b_row + nt * 8) * 72 + ks * 16 + b_col8) * 2;
                LDSM2(bh[nt][0], bh[nt][1], baddr);
            }
#pragma unroll
            for (int mt = 0; mt < 4; mt++) {
                uint32_t ah[4];
                uint32_t aaddr = ZB + ((a_row + mt * 16) * 264 + k + a_col8) * 2;
                LDSM4(ah[0], ah[1], ah[2], ah[3], aaddr);
#pragma unroll
                for (int nt = 0; nt < 4; nt++)
                    MMA16816(acc[mt][nt], ah, bh[nt]);
            }
        }
        __syncthreads();

        if (kc == 3) {
            const int codeTile = 1 + tt * 128 + warpN * 32;
#pragma unroll
            for (int nt = 0; nt < 4; nt++) {
                int c0 = codeTile + nt * 8 + (lane & 3) * 2;
                float hn0 = (c0 < NC)     ? __ldg(&g_half_norm[c0])     : 0.0f;
                float hn1 = (c0 + 1 < NC) ? __ldg(&g_half_norm[c0 + 1]) : 0.0f;
#pragma unroll
                for (int mt = 0; mt < 4; mt++) {
#pragma unroll
                    for (int h = 0; h < 2; h++) {
                        int s = mt * 2 + h;
                        if (c0 < NC) {
                            float v = acc[mt][nt][h * 2] - hn0;
                            if (v > best[s])      { sec[s] = best[s]; best[s] = v; bidx[s] = c0; }
                            else if (v > sec[s])  { sec[s] = v; }
                        }
                        if (c0 + 1 < NC) {
                            float v = acc[mt][nt][h * 2 + 1] - hn1;
                            if (v > best[s])      { sec[s] = best[s]; best[s] = v; bidx[s] = c0 + 1; }
                            else if (v > sec[s])  { sec[s] = v; }
                        }
                    }
                    acc[mt][nt][0] = 0.0f; acc[mt][nt][1] = 0.0f;
                    acc[mt][nt][2] = 0.0f; acc[mt][nt][3] = 0.0f;
                }
            }
        }
    }

    // reduce across lanes (xor 1, 2) then across warpN via smem
    float* red_val = (float*)(smem + Q_ZBYTES);
    float* red_sec = (float*)(smem + Q_ZBYTES + 2048);
    int*   red_idx = (int*)(smem + Q_ZBYTES + 4096);
    int*   row_idx = (int*)(smem + Q_ZBYTES + 6144);

#pragma unroll
    for (int slot = 0; slot < 8; slot++) {
        float b1 = best[slot], b2 = sec[slot]; int i1 = bidx[slot];
#pragma unroll
        for (int off = 1; off <= 2; off <<= 1) {
            float ob1 = __shfl_xor_sync(0xFFFFFFFFu, b1, off);
            int   oi1 = __shfl_xor_sync(0xFFFFFFFFu, i1, off);
            float ob2 = __shfl_xor_sync(0xFFFFFFFFu, b2, off);
            top2_merge(b1, i1, b2, ob1, oi1, ob2);
        }
        if ((lane & 3) == 0) {
            int mt = slot >> 1, h = slot & 1;
            int row = warpM * 64 + mt * 16 + (lane >> 2) + h * 8;
            red_val[row * 4 + warpN] = b1;
            red_sec[row * 4 + warpN] = b2;
            red_idx[row * 4 + warpN] = i1;
        }
    }
    __syncthreads();

    if (t < 128) {
        float b1 = red_val[t * 4], b2 = red_sec[t * 4];
        int i1 = red_idx[t * 4];
#pragma unroll
        for (int q = 1; q < 4; q++)
            top2_merge(b1, i1, b2, red_val[t * 4 + q], red_idx[t * 4 + q], red_sec[t * 4 + q]);
        row_idx[t] = i1;
        out_idx[rowBase + t] = (float)i1;
        if (b1 - b2 <= FLAG_THRESH) {
            int pos = atomicAdd(&g_flag_count, 1);
            g_flag_list[pos] = rowBase + t;
        }
    }
    __syncthreads();

    for (int r = 0; r < 128; r++) {
        int code = row_idx[r];
        out_hard[(size_t)(rowBase + r) * CD + t] = __ldg(&cb[(size_t)code * CD + t]);
    }
}

// ---------------------------------------------------------------------------
// Fixup: exact fp32 argmin for flagged tokens. 4 independent accumulators
// break the FFMA dependency chain (latency-bound otherwise).
// ---------------------------------------------------------------------------
__global__ __launch_bounds__(256)
void fixup_kernel(const float* __restrict__ z, const float* __restrict__ cb,
                  float* __restrict__ out_idx, float* __restrict__ out_hard) {
    __shared__ float zs[CD];
    __shared__ float rv[8];
    __shared__ int   ri[8];
    __shared__ int   s_best;

    const int t = threadIdx.x, lane = t & 31, warp = t >> 5;
    const int count = g_flag_count;

    for (int i = blockIdx.x; i < count; i += gridDim.x) {
        const int token = g_flag_list[i];
        zs[t] = z[(size_t)token * CD + t];
        __syncthreads();

        float bv = -3.0e38f; int bi = 1;
        for (int j = 0; j < 16; j++) {
            int code = 1 + t + 256 * j;
            if (code >= NC) break;
            const float4* c4 = (const float4*)&cb[(size_t)code * CD];
            float s0 = 0.f, s1 = 0.f, s2 = 0.f, s3 = 0.f;
#pragma unroll
            for (int k = 0; k < 64; k += 4) {
                float4 cv0 = c4[k],     cv1 = c4[k + 1];
                float4 cv2 = c4[k + 2], cv3 = c4[k + 3];
                s0 += zs[k*4+0]*cv0.x + zs[k*4+1]*cv0.y + zs[k*4+2]*cv0.z + zs[k*4+3]*cv0.w;
                s1 += zs[k*4+4]*cv1.x + zs[k*4+5]*cv1.y + zs[k*4+6]*cv1.z + zs[k*4+7]*cv1.w;
                s2 += zs[k*4+8]*cv2.x + zs[k*4+9]*cv2.y + zs[k*4+10]*cv2.z + zs[k*4+11]*cv2.w;
                s3 += zs[k*4+12]*cv3.x + zs[k*4+13]*cv3.y + zs[k*4+14]*cv3.z + zs[k*4+15]*cv3.w;
            }
            float s = (s0 + s1) + (s2 + s3) - __ldg(&g_half_norm[code]);
            if (s > bv || (s == bv && code < bi)) { bv = s; bi = code; }
        }
#pragma unroll
        for (int off = 16; off > 0; off >>= 1) {
            float ov = __shfl_xor_sync(0xFFFFFFFFu, bv, off);
            int   oi = __shfl_xor_sync(0xFFFFFFFFu, bi, off);
            if (ov > bv || (ov == bv && oi < bi)) { bv = ov; bi = oi; }
        }
        if (lane == 0) { rv[warp] = bv; ri[warp] = bi; }
        __syncthreads();
        if (t == 0) {
            float fbv = rv[0]; int fbi = ri[0];
#pragma unroll
            for (int q = 1; q < 8; q++)
                if (rv[q] > fbv || (rv[q] == fbv && ri[q] < fbi)) { fbv = rv[q]; fbi = ri[q]; }
            s_best = fbi;
            out_idx[token] = (float)fbi;
        }
        __syncthreads();
        int code = s_best;
        out_hard[(size_t)token * CD + t] = __ldg(&cb[(size_t)code * CD + t]);
        __syncthreads();
    }
}

// ---------------------------------------------------------------------------
// Launch
// ---------------------------------------------------------------------------
extern "C" void kernel_launch(void* const* d_in, const int* in_sizes, int n_in,
                              void* d_out, int out_size) {
    const float* x  = (const float*)d_in[0];   // [32768, 1024]
    const float* cb = (const float*)d_in[1];   // [4096, 256]
    const float* W  = (const float*)d_in[2];   // [1024, 256]
    const float* b  = (const float*)d_in[3];   // [256]

    float* out   = (float*)d_out;
    float* z     = out;                              // [32768, 256]
    float* oidx  = out + (size_t)M_TOK * CD;         // [32768]
    float* ohard = oidx + M_TOK;                     // [32768, 256]

    cudaFuncSetAttribute(gemm1_mma_kernel, cudaFuncAttributeMaxDynamicSharedMemorySize, G1_SMEM);
    cudaFuncSetAttribute(quant_mma_kernel, cudaFuncAttributeMaxDynamicSharedMemorySize, Q_SMEM);

    reset_kernel<<<1, 1>>>();
    conv_x_kernel<<<(int)((size_t)M_TOK * DMODEL / 4 / 256), 256>>>(x);
    conv_w_kernel<<<(CD * DMODEL) / 256, 256>>>(W);
    halfnorm_kernel<<<NC / 8, 256>>>(cb);
    conv_cb_kernel<<<(NC * CD / 4) / 256, 256>>>(cb);

    gemm1_mma_kernel<<<dim3(M_TOK / 128, CD / 128), 256, G1_SMEM>>>(b, z);
    normalize_kernel<<<M_TOK / 8, 256>>>(z);
    conv_z_kernel<<<(M_TOK * CD / 4) / 256, 256>>>(z);

    quant_mma_kernel<<<M_TOK / 128, 256, Q_SMEM>>>(cb, oidx, ohard);
    fixup_kernel<<<1024, 256>>>(z, cb, oidx, ohard);
}

// round 7
// speedup vs baseline: 4.0839x; 4.0839x over previous
#include <cuda_runtime.h>
#include <cuda_bf16.h>
#include <math.h>
#include <stdint.h>

#define M_TOK 32768
#define DMODEL 1024
#define CD 256
#define NC 4096

#define FLAG_THRESH 1.5e-3f

// ---------------------------------------------------------------------------
// Static device scratch
// ---------------------------------------------------------------------------
__device__ float g_half_norm[NC];
__device__ unsigned short g_x_hi[(size_t)M_TOK * DMODEL];
__device__ unsigned short g_x_lo[(size_t)M_TOK * DMODEL];
__device__ unsigned short g_w_hi[(size_t)CD * DMODEL];   // transposed [n][k]
__device__ unsigned short g_w_lo[(size_t)CD * DMODEL];
__device__ unsigned short g_z_hi[(size_t)M_TOK * CD];
__device__ unsigned short g_z_lo[(size_t)M_TOK * CD];
__device__ unsigned short g_cb_hi[(size_t)NC * CD];
__device__ unsigned short g_cb_lo[(size_t)NC * CD];
__device__ int g_flag_count;
__device__ int g_flag_list[M_TOK];

// ---------------------------------------------------------------------------
// PTX helpers
// ---------------------------------------------------------------------------
__device__ __forceinline__ uint32_t smem_u32(const void* p) {
    uint32_t a;
    asm("{ .reg .u64 t; cvta.to.shared.u64 t, %1; cvt.u32.u64 %0, t; }" : "=r"(a) : "l"(p));
    return a;
}
__device__ __forceinline__ void cp16(uint32_t dst, const void* src) {
    asm volatile("cp.async.cg.shared.global [%0], [%1], 16;" :: "r"(dst), "l"(src));
}
#define CP_COMMIT() asm volatile("cp.async.commit_group;" ::: "memory")
#define CP_WAIT(n)  asm volatile("cp.async.wait_group %0;" :: "n"(n) : "memory")

#define LDSM4(r0, r1, r2, r3, addr) \
    asm volatile("ldmatrix.sync.aligned.m8n8.x4.shared.b16 {%0,%1,%2,%3}, [%4];" \
                 : "=r"(r0), "=r"(r1), "=r"(r2), "=r"(r3) : "r"(addr))
#define LDSM2(r0, r1, addr) \
    asm volatile("ldmatrix.sync.aligned.m8n8.x2.shared.b16 {%0,%1}, [%2];" \
                 : "=r"(r0), "=r"(r1) : "r"(addr))

#define MMA16816(c, a, b) \
    asm volatile("mma.sync.aligned.m16n8k16.row.col.f32.bf16.bf16.f32 " \
                 "{%0,%1,%2,%3}, {%4,%5,%6,%7}, {%8,%9}, {%0,%1,%2,%3};" \
                 : "+f"((c)[0]), "+f"((c)[1]), "+f"((c)[2]), "+f"((c)[3]) \
                 : "r"((a)[0]), "r"((a)[1]), "r"((a)[2]), "r"((a)[3]), \
                   "r"((b)[0]), "r"((b)[1]))

// ---------------------------------------------------------------------------
// hi/lo bf16 split helpers
// ---------------------------------------------------------------------------
__device__ __forceinline__ void split4(float4 v, uint2& hi, uint2& lo) {
    float f[4] = {v.x, v.y, v.z, v.w};
    unsigned short h[4], l[4];
#pragma unroll
    for (int i = 0; i < 4; i++) {
        __nv_bfloat16 hb = __float2bfloat16(f[i]);
        h[i] = __bfloat16_as_ushort(hb);
        l[i] = __bfloat16_as_ushort(__float2bfloat16(f[i] - __bfloat162float(hb)));
    }
    hi.x = (uint32_t)h[0] | ((uint32_t)h[1] << 16);
    hi.y = (uint32_t)h[2] | ((uint32_t)h[3] << 16);
    lo.x = (uint32_t)l[0] | ((uint32_t)l[1] << 16);
    lo.y = (uint32_t)l[2] | ((uint32_t)l[3] << 16);
}

// ---------------------------------------------------------------------------
// Prep kernels
// ---------------------------------------------------------------------------
__global__ __launch_bounds__(256)
void conv_x_kernel(const float* __restrict__ x) {
    size_t gid = (size_t)blockIdx.x * 256 + threadIdx.x;
    float4 v = *(const float4*)&x[gid * 4];
    uint2 hi, lo; split4(v, hi, lo);
    *(uint2*)&g_x_hi[gid * 4] = hi;
    *(uint2*)&g_x_lo[gid * 4] = lo;
}

__global__ __launch_bounds__(256)
void conv_w_kernel(const float* __restrict__ W) {
    size_t gid = (size_t)blockIdx.x * 256 + threadIdx.x;
    int n = (int)(gid >> 10);
    int k = (int)(gid & 1023);
    float v = W[(size_t)k * CD + n];
    __nv_bfloat16 hb = __float2bfloat16(v);
    g_w_hi[gid] = __bfloat16_as_ushort(hb);
    g_w_lo[gid] = __bfloat16_as_ushort(__float2bfloat16(v - __bfloat162float(hb)));
}

__global__ __launch_bounds__(256)
void conv_z_kernel(const float* __restrict__ z) {
    size_t gid = (size_t)blockIdx.x * 256 + threadIdx.x;   // over M*CD/4
    float4 v = *(const float4*)&z[gid * 4];
    uint2 hi, lo; split4(v, hi, lo);
    *(uint2*)&g_z_hi[gid * 4] = hi;
    *(uint2*)&g_z_lo[gid * 4] = lo;
}

__global__ __launch_bounds__(256)
void conv_cb_kernel(const float* __restrict__ cb) {
    size_t gid = (size_t)blockIdx.x * 256 + threadIdx.x;   // over NC*CD/4
    float4 v = *(const float4*)&cb[gid * 4];
    uint2 hi, lo; split4(v, hi, lo);
    *(uint2*)&g_cb_hi[gid * 4] = hi;
    *(uint2*)&g_cb_lo[gid * 4] = lo;
}

__global__ __launch_bounds__(256)
void normalize_kernel(float* __restrict__ z) {
    const int warp = threadIdx.x >> 5;
    const int lane = threadIdx.x & 31;
    const int row  = blockIdx.x * 8 + warp;
    float4* z4 = (float4*)z;
    size_t base = (size_t)row * 64;
    float4 v0 = z4[base + lane];
    float4 v1 = z4[base + 32 + lane];
    float s = v0.x*v0.x + v0.y*v0.y + v0.z*v0.z + v0.w*v0.w
            + v1.x*v1.x + v1.y*v1.y + v1.z*v1.z + v1.w*v1.w;
#pragma unroll
    for (int o = 16; o > 0; o >>= 1) s += __shfl_xor_sync(0xFFFFFFFFu, s, o);
    float inv = 1.0f / (sqrtf(s) + 1e-6f);
    v0.x *= inv; v0.y *= inv; v0.z *= inv; v0.w *= inv;
    v1.x *= inv; v1.y *= inv; v1.z *= inv; v1.w *= inv;
    z4[base + lane]      = v0;
    z4[base + 32 + lane] = v1;
}

__global__ __launch_bounds__(256)
void halfnorm_kernel(const float* __restrict__ cb) {
    const int warp = threadIdx.x >> 5;
    const int lane = threadIdx.x & 31;
    const int code = blockIdx.x * 8 + warp;
    const float4* c4 = (const float4*)cb;
    size_t base = (size_t)code * 64;
    float4 v0 = c4[base + lane];
    float4 v1 = c4[base + 32 + lane];
    float s = v0.x*v0.x + v0.y*v0.y + v0.z*v0.z + v0.w*v0.w
            + v1.x*v1.x + v1.y*v1.y + v1.z*v1.z + v1.w*v1.w;
#pragma unroll
    for (int o = 16; o > 0; o >>= 1) s += __shfl_xor_sync(0xFFFFFFFFu, s, o);
    if (lane == 0) g_half_norm[code] = 0.5f * s;
}

__global__ void reset_kernel() { g_flag_count = 0; }

// ---------------------------------------------------------------------------
// GEMM1 (mma.sync, 3-pass bf16 split) — known good
// ---------------------------------------------------------------------------
#define G1_SMEM (4 * 18432 + 4 * 18432)

__device__ __forceinline__ void g1_load(uint32_t XS, uint32_t WS, int buf, int kc,
                                        int rowBase, int colBase, int t) {
#pragma unroll
    for (int q = 0; q < 8; q++) {
        int i = t + 256 * q;
        int hl = i >> 10, r = (i >> 3) & 127, cc = i & 7;
        const unsigned short* src = (hl ? g_x_lo : g_x_hi)
            + (size_t)(rowBase + r) * DMODEL + kc * 64 + cc * 8;
        cp16(XS + (buf * 2 + hl) * 18432 + r * 144 + cc * 16, src);
    }
#pragma unroll
    for (int q = 0; q < 8; q++) {
        int i = t + 256 * q;
        int hl = i >> 10, r = (i >> 3) & 127, cc = i & 7;
        const unsigned short* src = (hl ? g_w_lo : g_w_hi)
            + (size_t)(colBase + r) * DMODEL + kc * 64 + cc * 8;
        cp16(WS + (buf * 2 + hl) * 18432 + r * 144 + cc * 16, src);
    }
}

__global__ __launch_bounds__(256, 1)
void gemm1_mma_kernel(const float* __restrict__ bias, float* __restrict__ z) {
    extern __shared__ unsigned char smem[];
    const uint32_t sb = smem_u32(smem);
    const uint32_t XS = sb;
    const uint32_t WS = sb + 4 * 18432;

    const int t = threadIdx.x, lane = t & 31, w = t >> 5;
    const int warpM = w & 1, warpN = w >> 1;
    const int rowBase = blockIdx.x * 128;
    const int colBase = blockIdx.y * 128;

    float acc[4][4][4];
#pragma unroll
    for (int mt = 0; mt < 4; mt++)
#pragma unroll
        for (int nt = 0; nt < 4; nt++)
#pragma unroll
            for (int c = 0; c < 4; c++) acc[mt][nt][c] = 0.0f;

    const uint32_t a_row  = warpM * 64 + (lane & 15);
    const uint32_t a_col8 = (lane >> 4) * 8;
    const uint32_t b_row  = warpN * 32 + (lane & 7);
    const uint32_t b_col8 = ((lane >> 3) & 1) * 8;

    g1_load(XS, WS, 0, 0, rowBase, colBase, t);
    CP_COMMIT();

    for (int kc = 0; kc < 16; kc++) {
        const int buf = kc & 1;
        if (kc + 1 < 16) { g1_load(XS, WS, (kc + 1) & 1, kc + 1, rowBase, colBase, t); CP_COMMIT(); CP_WAIT(1); }
        else             { CP_WAIT(0); }
        __syncthreads();

#pragma unroll
        for (int ks = 0; ks < 4; ks++) {
            uint32_t bh[4][2], bl[4][2];
#pragma unroll
            for (int nt = 0; nt < 4; nt++) {
                uint32_t baddr = WS + (buf * 2) * 18432 + ((b_row + nt * 8) * 72 + ks * 16 + b_col8) * 2;
                LDSM2(bh[nt][0], bh[nt][1], baddr);
                LDSM2(bl[nt][0], bl[nt][1], baddr + 18432);
            }
#pragma unroll
            for (int mt = 0; mt < 4; mt++) {
                uint32_t ah[4], al[4];
                uint32_t aaddr = XS + (buf * 2) * 18432 + ((a_row + mt * 16) * 72 + ks * 16 + a_col8) * 2;
                LDSM4(ah[0], ah[1], ah[2], ah[3], aaddr);
                LDSM4(al[0], al[1], al[2], al[3], aaddr + 18432);
#pragma unroll
                for (int nt = 0; nt < 4; nt++) {
                    MMA16816(acc[mt][nt], ah, bh[nt]);
                    MMA16816(acc[mt][nt], ah, bl[nt]);
                    MMA16816(acc[mt][nt], al, bh[nt]);
                }
            }
        }
        __syncthreads();
    }

    const int row0 = rowBase + warpM * 64 + (lane >> 2);
    const int col0 = colBase + warpN * 32 + (lane & 3) * 2;
#pragma unroll
    for (int mt = 0; mt < 4; mt++) {
#pragma unroll
        for (int nt = 0; nt < 4; nt++) {
            int r0 = row0 + mt * 16;
            int c  = col0 + nt * 8;
            float b0 = __ldg(&bias[c]), b1 = __ldg(&bias[c + 1]);
            *(float2*)&z[(size_t)r0 * CD + c]       = make_float2(acc[mt][nt][0] + b0, acc[mt][nt][1] + b1);
            *(float2*)&z[(size_t)(r0 + 8) * CD + c] = make_float2(acc[mt][nt][2] + b0, acc[mt][nt][3] + b1);
        }
    }
}

// ---------------------------------------------------------------------------
// Quant kernel: 1-pass hi*hi bf16 scores + top-2 margin certification.
// ---------------------------------------------------------------------------
#define Q_ZBYTES  (128 * 264 * 2)
#define Q_CBBYTES (2 * 18432)
#define Q_SMEM    (Q_ZBYTES + Q_CBBYTES)

__device__ __forceinline__ void top2_merge(float& b1, int& i1, float& b2,
                                           float ob1, int oi1, float ob2) {
    if (ob1 > b1)      { b2 = fmaxf(b1, ob2); b1 = ob1; i1 = oi1; }
    else if (ob1 == b1){ if (oi1 != i1) b2 = b1; else b2 = fmaxf(b2, ob2); i1 = min(i1, oi1); }
    else               { b2 = fmaxf(b2, ob1); }
}

__device__ __forceinline__ void q_load_cb_hi(uint32_t CBB, int buf, int tt, int kc, int t) {
#pragma unroll
    for (int q = 0; q < 4; q++) {
        int i = t + 256 * q;
        int r = (i >> 3) & 127, cc = i & 7;
        int code = 1 + tt * 128 + r;
        if (code > NC - 1) code = NC - 1;
        const unsigned short* src = g_cb_hi + (size_t)code * CD + kc * 64 + cc * 8;
        cp16(CBB + buf * 18432 + r * 144 + cc * 16, src);
    }
}

__global__ __launch_bounds__(256, 1)
void quant_mma_kernel(const float* __restrict__ cb,
                      float* __restrict__ out_idx, float* __restrict__ out_hard) {
    extern __shared__ unsigned char smem[];
    const uint32_t sb  = smem_u32(smem);
    const uint32_t ZB  = sb;
    const uint32_t CBB = sb + Q_ZBYTES;

    const int t = threadIdx.x, lane = t & 31, w = t >> 5;
    const int warpM = w & 1, warpN = w >> 1;
    const int rowBase = blockIdx.x * 128;

    // stage z_hi tile, full K=256
#pragma unroll
    for (int q = 0; q < 16; q++) {
        int i = t + 256 * q;
        int r = i >> 5, cc = i & 31;
        const unsigned short* src = g_z_hi + (size_t)(rowBase + r) * CD + cc * 8;
        cp16(ZB + r * 528 + cc * 16, src);
    }
    q_load_cb_hi(CBB, 0, 0, 0, t);
    CP_COMMIT();

    float acc[4][4][4];
#pragma unroll
    for (int mt = 0; mt < 4; mt++)
#pragma unroll
        for (int nt = 0; nt < 4; nt++)
#pragma unroll
            for (int c = 0; c < 4; c++) acc[mt][nt][c] = 0.0f;

    float best[8], sec[8];
    int   bidx[8];
#pragma unroll
    for (int s = 0; s < 8; s++) { best[s] = -3.0e38f; sec[s] = -3.0e38f; bidx[s] = 1; }

    const uint32_t a_row  = warpM * 64 + (lane & 15);
    const uint32_t a_col8 = (lane >> 4) * 8;
    const uint32_t b_row  = warpN * 32 + (lane & 7);
    const uint32_t b_col8 = ((lane >> 3) & 1) * 8;

    for (int it = 0; it < 128; it++) {
        const int tt = it >> 2, kc = it & 3, buf = it & 1;
        if (it + 1 < 128) { q_load_cb_hi(CBB, (it + 1) & 1, (it + 1) >> 2, (it + 1) & 3, t); CP_COMMIT(); CP_WAIT(1); }
        else              { CP_WAIT(0); }
        __syncthreads();

#pragma unroll
        for (int ks = 0; ks < 4; ks++) {
            const int k = kc * 64 + ks * 16;
            uint32_t bh[4][2];
#pragma unroll
            for (int nt = 0; nt < 4; nt++) {
                uint32_t baddr = CBB + buf * 18432 + ((b_row + nt * 8) * 72 + ks * 16 + b_col8) * 2;
                LDSM2(bh[nt][0], bh[nt][1], baddr);
            }
#pragma unroll
            for (int mt = 0; mt < 4; mt++) {
                uint32_t ah[4];
                uint32_t aaddr = ZB + ((a_row + mt * 16) * 264 + k + a_col8) * 2;
                LDSM4(ah[0], ah[1], ah[2], ah[3], aaddr);
#pragma unroll
                for (int nt = 0; nt < 4; nt++)
                    MMA16816(acc[mt][nt], ah, bh[nt]);
            }
        }
        __syncthreads();

        if (kc == 3) {
            const int codeTile = 1 + tt * 128 + warpN * 32;
#pragma unroll
            for (int nt = 0; nt < 4; nt++) {
                int c0 = codeTile + nt * 8 + (lane & 3) * 2;
                float hn0 = (c0 < NC)     ? __ldg(&g_half_norm[c0])     : 0.0f;
                float hn1 = (c0 + 1 < NC) ? __ldg(&g_half_norm[c0 + 1]) : 0.0f;
#pragma unroll
                for (int mt = 0; mt < 4; mt++) {
#pragma unroll
                    for (int h = 0; h < 2; h++) {
                        int s = mt * 2 + h;
                        if (c0 < NC) {
                            float v = acc[mt][nt][h * 2] - hn0;
                            if (v > best[s])      { sec[s] = best[s]; best[s] = v; bidx[s] = c0; }
                            else if (v > sec[s])  { sec[s] = v; }
                        }
                        if (c0 + 1 < NC) {
                            float v = acc[mt][nt][h * 2 + 1] - hn1;
                            if (v > best[s])      { sec[s] = best[s]; best[s] = v; bidx[s] = c0 + 1; }
                            else if (v > sec[s])  { sec[s] = v; }
                        }
                    }
                    acc[mt][nt][0] = 0.0f; acc[mt][nt][1] = 0.0f;
                    acc[mt][nt][2] = 0.0f; acc[mt][nt][3] = 0.0f;
                }
            }
        }
    }

    float* red_val = (float*)(smem + Q_ZBYTES);
    float* red_sec = (float*)(smem + Q_ZBYTES + 2048);
    int*   red_idx = (int*)(smem + Q_ZBYTES + 4096);
    int*   row_idx = (int*)(smem + Q_ZBYTES + 6144);

#pragma unroll
    for (int slot = 0; slot < 8; slot++) {
        float b1 = best[slot], b2 = sec[slot]; int i1 = bidx[slot];
#pragma unroll
        for (int off = 1; off <= 2; off <<= 1) {
            float ob1 = __shfl_xor_sync(0xFFFFFFFFu, b1, off);
            int   oi1 = __shfl_xor_sync(0xFFFFFFFFu, i1, off);
            float ob2 = __shfl_xor_sync(0xFFFFFFFFu, b2, off);
            top2_merge(b1, i1, b2, ob1, oi1, ob2);
        }
        if ((lane & 3) == 0) {
            int mt = slot >> 1, h = slot & 1;
            int row = warpM * 64 + mt * 16 + (lane >> 2) + h * 8;
            red_val[row * 4 + warpN] = b1;
            red_sec[row * 4 + warpN] = b2;
            red_idx[row * 4 + warpN] = i1;
        }
    }
    __syncthreads();

    if (t < 128) {
        float b1 = red_val[t * 4], b2 = red_sec[t * 4];
        int i1 = red_idx[t * 4];
#pragma unroll
        for (int q = 1; q < 4; q++)
            top2_merge(b1, i1, b2, red_val[t * 4 + q], red_idx[t * 4 + q], red_sec[t * 4 + q]);
        row_idx[t] = i1;
        out_idx[rowBase + t] = (float)i1;
        if (b1 - b2 <= FLAG_THRESH) {
            int pos = atomicAdd(&g_flag_count, 1);
            g_flag_list[pos] = rowBase + t;
        }
    }
    __syncthreads();

    for (int r = 0; r < 128; r++) {
        int code = row_idx[r];
        out_hard[(size_t)(rowBase + r) * CD + t] = __ldg(&cb[(size_t)code * CD + t]);
    }
}

// ---------------------------------------------------------------------------
// Fixup (mma, 3-pass exact-split): rerun flagged tokens, batched.
// ---------------------------------------------------------------------------
#define F_ZBYTES  (2 * 128 * 264 * 2)
#define F_CBBYTES (4 * 18432)
#define F_SMEM    (F_ZBYTES + F_CBBYTES)

__device__ __forceinline__ void f_load_cb(uint32_t CBB, int buf, int tt, int kc, int t) {
#pragma unroll
    for (int q = 0; q < 8; q++) {
        int i = t + 256 * q;
        int hl = i >> 10, r = (i >> 3) & 127, cc = i & 7;
        int code = 1 + tt * 128 + r;
        if (code > NC - 1) code = NC - 1;
        const unsigned short* src = (hl ? g_cb_lo : g_cb_hi)
            + (size_t)code * CD + kc * 64 + cc * 8;
        cp16(CBB + (buf * 2 + hl) * 18432 + r * 144 + cc * 16, src);
    }
}

__global__ __launch_bounds__(256, 1)
void fixup_mma_kernel(const float* __restrict__ cb,
                      float* __restrict__ out_idx, float* __restrict__ out_hard) {
    __shared__ int s_tok[128];
    extern __shared__ unsigned char smem[];
    const uint32_t sb  = smem_u32(smem);
    const uint32_t ZB  = sb;
    const uint32_t CBB = sb + F_ZBYTES;

    const int t = threadIdx.x, lane = t & 31, w = t >> 5;
    const int warpM = w & 1, warpN = w >> 1;
    const int count = g_flag_count;
    const int base  = blockIdx.x * 128;
    if (base >= count) return;

    if (t < 128) {
        int idx = base + t;
        if (idx > count - 1) idx = count - 1;
        s_tok[t] = g_flag_list[idx];
    }
    __syncthreads();

    // stage z tile (hi|lo), full K, with token indirection
#pragma unroll
    for (int q = 0; q < 32; q++) {
        int i = t + 256 * q;
        int hl = i >> 12, r = (i >> 5) & 127, cc = i & 31;
        const unsigned short* src = (hl ? g_z_lo : g_z_hi)
            + (size_t)s_tok[r] * CD + cc * 8;
        cp16(ZB + hl * 67584 + r * 528 + cc * 16, src);
    }
    f_load_cb(CBB, 0, 0, 0, t);
    CP_COMMIT();

    float acc[4][4][4];
#pragma unroll
    for (int mt = 0; mt < 4; mt++)
#pragma unroll
        for (int nt = 0; nt < 4; nt++)
#pragma unroll
            for (int c = 0; c < 4; c++) acc[mt][nt][c] = 0.0f;

    float best[8];
    int   bidx[8];
#pragma unroll
    for (int s = 0; s < 8; s++) { best[s] = -3.0e38f; bidx[s] = 1; }

    const uint32_t a_row  = warpM * 64 + (lane & 15);
    const uint32_t a_col8 = (lane >> 4) * 8;
    const uint32_t b_row  = warpN * 32 + (lane & 7);
    const uint32_t b_col8 = ((lane >> 3) & 1) * 8;

    for (int it = 0; it < 128; it++) {
        const int tt = it >> 2, kc = it & 3, buf = it & 1;
        if (it + 1 < 128) { f_load_cb(CBB, (it + 1) & 1, (it + 1) >> 2, (it + 1) & 3, t); CP_COMMIT(); CP_WAIT(1); }
        else              { CP_WAIT(0); }
        __syncthreads();

#pragma unroll
        for (int ks = 0; ks < 4; ks++) {
            const int k = kc * 64 + ks * 16;
            uint32_t bh[4][2], bl[4][2];
#pragma unroll
            for (int nt = 0; nt < 4; nt++) {
                uint32_t baddr = CBB + (buf * 2) * 18432 + ((b_row + nt * 8) * 72 + ks * 16 + b_col8) * 2;
                LDSM2(bh[nt][0], bh[nt][1], baddr);
                LDSM2(bl[nt][0], bl[nt][1], baddr + 18432);
            }
#pragma unroll
            for (int mt = 0; mt < 4; mt++) {
                uint32_t ah[4], al[4];
                uint32_t aaddr = ZB + ((a_row + mt * 16) * 264 + k + a_col8) * 2;
                LDSM4(ah[0], ah[1], ah[2], ah[3], aaddr);
                LDSM4(al[0], al[1], al[2], al[3], aaddr + 67584);
#pragma unroll
                for (int nt = 0; nt < 4; nt++) {
                    MMA16816(acc[mt][nt], ah, bh[nt]);
                    MMA16816(acc[mt][nt], ah, bl[nt]);
                    MMA16816(acc[mt][nt], al, bh[nt]);
                }
            }
        }
        __syncthreads();

        if (kc == 3) {
            const int codeTile = 1 + tt * 128 + warpN * 32;
#pragma unroll
            for (int nt = 0; nt < 4; nt++) {
                int c0 = codeTile + nt * 8 + (lane & 3) * 2;
                float hn0 = (c0 < NC)     ? __ldg(&g_half_norm[c0])     : 0.0f;
                float hn1 = (c0 + 1 < NC) ? __ldg(&g_half_norm[c0 + 1]) : 0.0f;
#pragma unroll
                for (int mt = 0; mt < 4; mt++) {
                    if (c0 < NC) {
                        float s0 = acc[mt][nt][0] - hn0;
                        if (s0 > best[mt * 2])     { best[mt * 2] = s0;     bidx[mt * 2] = c0; }
                        float s2 = acc[mt][nt][2] - hn0;
                        if (s2 > best[mt * 2 + 1]) { best[mt * 2 + 1] = s2; bidx[mt * 2 + 1] = c0; }
                    }
                    if (c0 + 1 < NC) {
                        float s1 = acc[mt][nt][1] - hn1;
                        if (s1 > best[mt * 2])     { best[mt * 2] = s1;     bidx[mt * 2] = c0 + 1; }
                        float s3 = acc[mt][nt][3] - hn1;
                        if (s3 > best[mt * 2 + 1]) { best[mt * 2 + 1] = s3; bidx[mt * 2 + 1] = c0 + 1; }
                    }
                    acc[mt][nt][0] = 0.0f; acc[mt][nt][1] = 0.0f;
                    acc[mt][nt][2] = 0.0f; acc[mt][nt][3] = 0.0f;
                }
            }
        }
    }

    float* red_val = (float*)(smem + F_ZBYTES);
    int*   red_idx = (int*)(smem + F_ZBYTES + 2048);
    int*   row_idx = (int*)(smem + F_ZBYTES + 4096);

#pragma unroll
    for (int slot = 0; slot < 8; slot++) {
        float v = best[slot]; int ix = bidx[slot];
#pragma unroll
        for (int off = 1; off <= 2; off <<= 1) {
            float ov = __shfl_xor_sync(0xFFFFFFFFu, v, off);
            int   oi = __shfl_xor_sync(0xFFFFFFFFu, ix, off);
            if (ov > v || (ov == v && oi < ix)) { v = ov; ix = oi; }
        }
        if ((lane & 3) == 0) {
            int mt = slot >> 1, h = slot & 1;
            int row = warpM * 64 + mt * 16 + (lane >> 2) + h * 8;
            red_val[row * 4 + warpN] = v;
            red_idx[row * 4 + warpN] = ix;
        }
    }
    __syncthreads();

    if (t < 128) {
        float bv = red_val[t * 4]; int bi = red_idx[t * 4];
#pragma unroll
        for (int q = 1; q < 4; q++) {
            float v = red_val[t * 4 + q]; int ix = red_idx[t * 4 + q];
            if (v > bv || (v == bv && ix < bi)) { bv = v; bi = ix; }
        }
        row_idx[t] = bi;
        out_idx[s_tok[t]] = (float)bi;
    }
    __syncthreads();

    for (int r = 0; r < 128; r++) {
        int code  = row_idx[r];
        int token = s_tok[r];
        out_hard[(size_t)token * CD + t] = __ldg(&cb[(size_t)code * CD + t]);
    }
}

// ---------------------------------------------------------------------------
// Launch
// ---------------------------------------------------------------------------
extern "C" void kernel_launch(void* const* d_in, const int* in_sizes, int n_in,
                              void* d_out, int out_size) {
    const float* x  = (const float*)d_in[0];   // [32768, 1024]
    const float* cb = (const float*)d_in[1];   // [4096, 256]
    const float* W  = (const float*)d_in[2];   // [1024, 256]
    const float* b  = (const float*)d_in[3];   // [256]

    float* out   = (float*)d_out;
    float* z     = out;                              // [32768, 256]
    float* oidx  = out + (size_t)M_TOK * CD;         // [32768]
    float* ohard = oidx + M_TOK;                     // [32768, 256]

    cudaFuncSetAttribute(gemm1_mma_kernel, cudaFuncAttributeMaxDynamicSharedMemorySize, G1_SMEM);
    cudaFuncSetAttribute(quant_mma_kernel, cudaFuncAttributeMaxDynamicSharedMemorySize, Q_SMEM);
    cudaFuncSetAttribute(fixup_mma_kernel, cudaFuncAttributeMaxDynamicSharedMemorySize, F_SMEM);

    reset_kernel<<<1, 1>>>();
    conv_x_kernel<<<(int)((size_t)M_TOK * DMODEL / 4 / 256), 256>>>(x);
    conv_w_kernel<<<(CD * DMODEL) / 256, 256>>>(W);
    halfnorm_kernel<<<NC / 8, 256>>>(cb);
    conv_cb_kernel<<<(NC * CD / 4) / 256, 256>>>(cb);

    gemm1_mma_kernel<<<dim3(M_TOK / 128, CD / 128), 256, G1_SMEM>>>(b, z);
    normalize_kernel<<<M_TOK / 8, 256>>>(z);
    conv_z_kernel<<<(M_TOK * CD / 4) / 256, 256>>>(z);

    quant_mma_kernel<<<M_TOK / 128, 256, Q_SMEM>>>(cb, oidx, ohard);
    fixup_mma_kernel<<<M_TOK / 128, 256, F_SMEM>>>(cb, oidx, ohard);
}

// round 10
// speedup vs baseline: 5.5072x; 1.3485x over previous
#include <cuda_runtime.h>
#include <cuda_bf16.h>
#include <math.h>
#include <stdint.h>

#define M_TOK 32768
#define DMODEL 1024
#define CD 256
#define NC 4096

#define FLAG_THRESH 1.5e-3f

// ---------------------------------------------------------------------------
// Static device scratch
// ---------------------------------------------------------------------------
__device__ float g_half_norm[NC];
__device__ unsigned short g_x_hi[(size_t)M_TOK * DMODEL];
__device__ unsigned short g_x_lo[(size_t)M_TOK * DMODEL];
__device__ unsigned short g_w_hi[(size_t)CD * DMODEL];   // transposed [n][k]
__device__ unsigned short g_w_lo[(size_t)CD * DMODEL];
__device__ unsigned short g_z_hi[(size_t)M_TOK * CD];
__device__ unsigned short g_z_lo[(size_t)M_TOK * CD];
__device__ unsigned short g_cb_hi[(size_t)NC * CD];
__device__ unsigned short g_cb_lo[(size_t)NC * CD];
__device__ int g_flag_count;
__device__ int g_flag_list[M_TOK];
__device__ unsigned long long g_merge[M_TOK];   // packed (score_key, ~code)

// ---------------------------------------------------------------------------
// PTX helpers
// ---------------------------------------------------------------------------
__device__ __forceinline__ uint32_t smem_u32(const void* p) {
    uint32_t a;
    asm("{ .reg .u64 t; cvta.to.shared.u64 t, %1; cvt.u32.u64 %0, t; }" : "=r"(a) : "l"(p));
    return a;
}
__device__ __forceinline__ void cp16(uint32_t dst, const void* src) {
    asm volatile("cp.async.cg.shared.global [%0], [%1], 16;" :: "r"(dst), "l"(src));
}
#define CP_COMMIT() asm volatile("cp.async.commit_group;" ::: "memory")
#define CP_WAIT(n)  asm volatile("cp.async.wait_group %0;" :: "n"(n) : "memory")

#define LDSM4(r0, r1, r2, r3, addr) \
    asm volatile("ldmatrix.sync.aligned.m8n8.x4.shared.b16 {%0,%1,%2,%3}, [%4];" \
                 : "=r"(r0), "=r"(r1), "=r"(r2), "=r"(r3) : "r"(addr))
#define LDSM2(r0, r1, addr) \
    asm volatile("ldmatrix.sync.aligned.m8n8.x2.shared.b16 {%0,%1}, [%2];" \
                 : "=r"(r0), "=r"(r1) : "r"(addr))

#define MMA16816(c, a, b) \
    asm volatile("mma.sync.aligned.m16n8k16.row.col.f32.bf16.bf16.f32 " \
                 "{%0,%1,%2,%3}, {%4,%5,%6,%7}, {%8,%9}, {%0,%1,%2,%3};" \
                 : "+f"((c)[0]), "+f"((c)[1]), "+f"((c)[2]), "+f"((c)[3]) \
                 : "r"((a)[0]), "r"((a)[1]), "r"((a)[2]), "r"((a)[3]), \
                   "r"((b)[0]), "r"((b)[1]))

// monotone float -> u32 key (order-preserving)
__device__ __forceinline__ uint32_t fkey(float f) {
    uint32_t u = __float_as_uint(f);
    return (u & 0x80000000u) ? ~u : (u | 0x80000000u);
}

// ---------------------------------------------------------------------------
// hi/lo bf16 split helpers
// ---------------------------------------------------------------------------
__device__ __forceinline__ void split4(float4 v, uint2& hi, uint2& lo) {
    float f[4] = {v.x, v.y, v.z, v.w};
    unsigned short h[4], l[4];
#pragma unroll
    for (int i = 0; i < 4; i++) {
        __nv_bfloat16 hb = __float2bfloat16(f[i]);
        h[i] = __bfloat16_as_ushort(hb);
        l[i] = __bfloat16_as_ushort(__float2bfloat16(f[i] - __bfloat162float(hb)));
    }
    hi.x = (uint32_t)h[0] | ((uint32_t)h[1] << 16);
    hi.y = (uint32_t)h[2] | ((uint32_t)h[3] << 16);
    lo.x = (uint32_t)l[0] | ((uint32_t)l[1] << 16);
    lo.y = (uint32_t)l[2] | ((uint32_t)l[3] << 16);
}

// ---------------------------------------------------------------------------
// Prep kernels
// ---------------------------------------------------------------------------
__global__ __launch_bounds__(256)
void conv_x_kernel(const float* __restrict__ x) {
    size_t gid = (size_t)blockIdx.x * 256 + threadIdx.x;
    float4 v = *(const float4*)&x[gid * 4];
    uint2 hi, lo; split4(v, hi, lo);
    *(uint2*)&g_x_hi[gid * 4] = hi;
    *(uint2*)&g_x_lo[gid * 4] = lo;
}

__global__ __launch_bounds__(256)
void conv_w_kernel(const float* __restrict__ W) {
    size_t gid = (size_t)blockIdx.x * 256 + threadIdx.x;
    int n = (int)(gid >> 10);
    int k = (int)(gid & 1023);
    float v = W[(size_t)k * CD + n];
    __nv_bfloat16 hb = __float2bfloat16(v);
    g_w_hi[gid] = __bfloat16_as_ushort(hb);
    g_w_lo[gid] = __bfloat16_as_ushort(__float2bfloat16(v - __bfloat162float(hb)));
}

__global__ __launch_bounds__(256)
void conv_z_kernel(const float* __restrict__ z) {
    size_t gid = (size_t)blockIdx.x * 256 + threadIdx.x;   // over M*CD/4
    float4 v = *(const float4*)&z[gid * 4];
    uint2 hi, lo; split4(v, hi, lo);
    *(uint2*)&g_z_hi[gid * 4] = hi;
    *(uint2*)&g_z_lo[gid * 4] = lo;
}

__global__ __launch_bounds__(256)
void conv_cb_kernel(const float* __restrict__ cb) {
    size_t gid = (size_t)blockIdx.x * 256 + threadIdx.x;   // over NC*CD/4
    float4 v = *(const float4*)&cb[gid * 4];
    uint2 hi, lo; split4(v, hi, lo);
    *(uint2*)&g_cb_hi[gid * 4] = hi;
    *(uint2*)&g_cb_lo[gid * 4] = lo;
}

__global__ __launch_bounds__(256)
void normalize_kernel(float* __restrict__ z) {
    const int warp = threadIdx.x >> 5;
    const int lane = threadIdx.x & 31;
    const int row  = blockIdx.x * 8 + warp;
    float4* z4 = (float4*)z;
    size_t base = (size_t)row * 64;
    float4 v0 = z4[base + lane];
    float4 v1 = z4[base + 32 + lane];
    float s = v0.x*v0.x + v0.y*v0.y + v0.z*v0.z + v0.w*v0.w
            + v1.x*v1.x + v1.y*v1.y + v1.z*v1.z + v1.w*v1.w;
#pragma unroll
    for (int o = 16; o > 0; o >>= 1) s += __shfl_xor_sync(0xFFFFFFFFu, s, o);
    float inv = 1.0f / (sqrtf(s) + 1e-6f);
    v0.x *= inv; v0.y *= inv; v0.z *= inv; v0.w *= inv;
    v1.x *= inv; v1.y *= inv; v1.z *= inv; v1.w *= inv;
    z4[base + lane]      = v0;
    z4[base + 32 + lane] = v1;
}

__global__ __launch_bounds__(256)
void halfnorm_kernel(const float* __restrict__ cb) {
    const int warp = threadIdx.x >> 5;
    const int lane = threadIdx.x & 31;
    const int code = blockIdx.x * 8 + warp;
    const float4* c4 = (const float4*)cb;
    size_t base = (size_t)code * 64;
    float4 v0 = c4[base + lane];
    float4 v1 = c4[base + 32 + lane];
    float s = v0.x*v0.x + v0.y*v0.y + v0.z*v0.z + v0.w*v0.w
            + v1.x*v1.x + v1.y*v1.y + v1.z*v1.z + v1.w*v1.w;
#pragma unroll
    for (int o = 16; o > 0; o >>= 1) s += __shfl_xor_sync(0xFFFFFFFFu, s, o);
    if (lane == 0) g_half_norm[code] = 0.5f * s;
}

__global__ void reset_kernel() { g_flag_count = 0; }

// ---------------------------------------------------------------------------
// GEMM1 (mma.sync, 3-pass bf16 split) — known good
// ---------------------------------------------------------------------------
#define G1_SMEM (4 * 18432 + 4 * 18432)

__device__ __forceinline__ void g1_load(uint32_t XS, uint32_t WS, int buf, int kc,
                                        int rowBase, int colBase, int t) {
#pragma unroll
    for (int q = 0; q < 8; q++) {
        int i = t + 256 * q;
        int hl = i >> 10, r = (i >> 3) & 127, cc = i & 7;
        const unsigned short* src = (hl ? g_x_lo : g_x_hi)
            + (size_t)(rowBase + r) * DMODEL + kc * 64 + cc * 8;
        cp16(XS + (buf * 2 + hl) * 18432 + r * 144 + cc * 16, src);
    }
#pragma unroll
    for (int q = 0; q < 8; q++) {
        int i = t + 256 * q;
        int hl = i >> 10, r = (i >> 3) & 127, cc = i & 7;
        const unsigned short* src = (hl ? g_w_lo : g_w_hi)
            + (size_t)(colBase + r) * DMODEL + kc * 64 + cc * 8;
        cp16(WS + (buf * 2 + hl) * 18432 + r * 144 + cc * 16, src);
    }
}

__global__ __launch_bounds__(256, 1)
void gemm1_mma_kernel(const float* __restrict__ bias, float* __restrict__ z) {
    extern __shared__ unsigned char smem[];
    const uint32_t sb = smem_u32(smem);
    const uint32_t XS = sb;
    const uint32_t WS = sb + 4 * 18432;

    const int t = threadIdx.x, lane = t & 31, w = t >> 5;
    const int warpM = w & 1, warpN = w >> 1;
    const int rowBase = blockIdx.x * 128;
    const int colBase = blockIdx.y * 128;

    float acc[4][4][4];
#pragma unroll
    for (int mt = 0; mt < 4; mt++)
#pragma unroll
        for (int nt = 0; nt < 4; nt++)
#pragma unroll
            for (int c = 0; c < 4; c++) acc[mt][nt][c] = 0.0f;

    const uint32_t a_row  = warpM * 64 + (lane & 15);
    const uint32_t a_col8 = (lane >> 4) * 8;
    const uint32_t b_row  = warpN * 32 + (lane & 7);
    const uint32_t b_col8 = ((lane >> 3) & 1) * 8;

    g1_load(XS, WS, 0, 0, rowBase, colBase, t);
    CP_COMMIT();

    for (int kc = 0; kc < 16; kc++) {
        const int buf = kc & 1;
        if (kc + 1 < 16) { g1_load(XS, WS, (kc + 1) & 1, kc + 1, rowBase, colBase, t); CP_COMMIT(); CP_WAIT(1); }
        else             { CP_WAIT(0); }
        __syncthreads();

#pragma unroll
        for (int ks = 0; ks < 4; ks++) {
            uint32_t bh[4][2], bl[4][2];
#pragma unroll
            for (int nt = 0; nt < 4; nt++) {
                uint32_t baddr = WS + (buf * 2) * 18432 + ((b_row + nt * 8) * 72 + ks * 16 + b_col8) * 2;
                LDSM2(bh[nt][0], bh[nt][1], baddr);
                LDSM2(bl[nt][0], bl[nt][1], baddr + 18432);
            }
#pragma unroll
            for (int mt = 0; mt < 4; mt++) {
                uint32_t ah[4], al[4];
                uint32_t aaddr = XS + (buf * 2) * 18432 + ((a_row + mt * 16) * 72 + ks * 16 + a_col8) * 2;
                LDSM4(ah[0], ah[1], ah[2], ah[3], aaddr);
                LDSM4(al[0], al[1], al[2], al[3], aaddr + 18432);
#pragma unroll
                for (int nt = 0; nt < 4; nt++) {
                    MMA16816(acc[mt][nt], ah, bh[nt]);
                    MMA16816(acc[mt][nt], ah, bl[nt]);
                    MMA16816(acc[mt][nt], al, bh[nt]);
                }
            }
        }
        __syncthreads();
    }

    const int row0 = rowBase + warpM * 64 + (lane >> 2);
    const int col0 = colBase + warpN * 32 + (lane & 3) * 2;
#pragma unroll
    for (int mt = 0; mt < 4; mt++) {
#pragma unroll
        for (int nt = 0; nt < 4; nt++) {
            int r0 = row0 + mt * 16;
            int c  = col0 + nt * 8;
            float b0 = __ldg(&bias[c]), b1 = __ldg(&bias[c + 1]);
            *(float2*)&z[(size_t)r0 * CD + c]       = make_float2(acc[mt][nt][0] + b0, acc[mt][nt][1] + b1);
            *(float2*)&z[(size_t)(r0 + 8) * CD + c] = make_float2(acc[mt][nt][2] + b0, acc[mt][nt][3] + b1);
        }
    }
}

// ---------------------------------------------------------------------------
// Quant kernel: 1-pass hi*hi scores + top-2 certification.
// Full-K cb tiles (128 codes x 256 cols per buffer) -> 32 iterations, 64 syncs.
// smem: z_hi[128][264] (67584) + cb[2][128][264] (135168) = 202752
// ---------------------------------------------------------------------------
#define Q_ZBYTES  (128 * 264 * 2)        // 67584
#define Q_CBSTRIDE 67584                 // one cb buffer
#define Q_SMEM    (Q_ZBYTES + 2 * Q_CBSTRIDE)

__device__ __forceinline__ void top2_merge(float& b1, int& i1, float& b2,
                                           float ob1, int oi1, float ob2) {
    if (ob1 > b1)      { b2 = fmaxf(b1, ob2); b1 = ob1; i1 = oi1; }
    else if (ob1 == b1){ if (oi1 != i1) b2 = b1; else b2 = fmaxf(b2, ob2); i1 = min(i1, oi1); }
    else               { b2 = fmaxf(b2, ob1); }
}

__device__ __forceinline__ void q_load_cb_hi(uint32_t CBB, int buf, int tile, int t) {
#pragma unroll
    for (int q = 0; q < 16; q++) {
        int i = t + 256 * q;           // 0..4095
        int r = i >> 5, cc = i & 31;
        int code = 1 + tile * 128 + r;
        if (code > NC - 1) code = NC - 1;
        cp16(CBB + buf * Q_CBSTRIDE + r * 528 + cc * 16,
             g_cb_hi + (size_t)code * CD + cc * 8);
    }
}

__global__ __launch_bounds__(256, 1)
void quant_mma_kernel(const float* __restrict__ cb,
                      float* __restrict__ out_idx, float* __restrict__ out_hard) {
    extern __shared__ unsigned char smem[];
    const uint32_t sb  = smem_u32(smem);
    const uint32_t ZB  = sb;
    const uint32_t CBB = sb + Q_ZBYTES;

    const int t = threadIdx.x, lane = t & 31, w = t >> 5;
    const int warpM = w & 1, warpN = w >> 1;
    const int rowBase = blockIdx.x * 128;

    // stage z_hi tile, full K=256
#pragma unroll
    for (int q = 0; q < 16; q++) {
        int i = t + 256 * q;
        int r = i >> 5, cc = i & 31;
        const unsigned short* src = g_z_hi + (size_t)(rowBase + r) * CD + cc * 8;
        cp16(ZB + r * 528 + cc * 16, src);
    }
    q_load_cb_hi(CBB, 0, 0, t);
    CP_COMMIT();

    float acc[4][4][4];
#pragma unroll
    for (int mt = 0; mt < 4; mt++)
#pragma unroll
        for (int nt = 0; nt < 4; nt++)
#pragma unroll
            for (int c = 0; c < 4; c++) acc[mt][nt][c] = 0.0f;

    float best[8], sec[8];
    int   bidx[8];
#pragma unroll
    for (int s = 0; s < 8; s++) { best[s] = -3.0e38f; sec[s] = -3.0e38f; bidx[s] = 1; }

    const uint32_t a_row  = warpM * 64 + (lane & 15);
    const uint32_t a_col8 = (lane >> 4) * 8;
    const uint32_t b_row  = warpN * 32 + (lane & 7);
    const uint32_t b_col8 = ((lane >> 3) & 1) * 8;

    for (int tile = 0; tile < 32; tile++) {
        const int buf = tile & 1;
        if (tile + 1 < 32) { q_load_cb_hi(CBB, buf ^ 1, tile + 1, t); CP_COMMIT(); CP_WAIT(1); }
        else               { CP_WAIT(0); }
        __syncthreads();

#pragma unroll
        for (int ks = 0; ks < 16; ks++) {
            uint32_t bh[4][2];
#pragma unroll
            for (int nt = 0; nt < 4; nt++) {
                uint32_t baddr = CBB + buf * Q_CBSTRIDE + ((b_row + nt * 8) * 264 + ks * 16 + b_col8) * 2;
                LDSM2(bh[nt][0], bh[nt][1], baddr);
            }
#pragma unroll
            for (int mt = 0; mt < 4; mt++) {
                uint32_t ah[4];
                uint32_t aaddr = ZB + ((a_row + mt * 16) * 264 + ks * 16 + a_col8) * 2;
                LDSM4(ah[0], ah[1], ah[2], ah[3], aaddr);
#pragma unroll
                for (int nt = 0; nt < 4; nt++)
                    MMA16816(acc[mt][nt], ah, bh[nt]);
            }
        }
        __syncthreads();

        // epilogue every tile (128 codes)
        {
            const int codeTile = 1 + tile * 128 + warpN * 32;
#pragma unroll
            for (int nt = 0; nt < 4; nt++) {
                int c0 = codeTile + nt * 8 + (lane & 3) * 2;
                float hn0 = (c0 < NC)     ? __ldg(&g_half_norm[c0])     : 0.0f;
                float hn1 = (c0 + 1 < NC) ? __ldg(&g_half_norm[c0 + 1]) : 0.0f;
#pragma unroll
                for (int mt = 0; mt < 4; mt++) {
#pragma unroll
                    for (int h = 0; h < 2; h++) {
                        int s = mt * 2 + h;
                        if (c0 < NC) {
                            float v = acc[mt][nt][h * 2] - hn0;
                            if (v > best[s])      { sec[s] = best[s]; best[s] = v; bidx[s] = c0; }
                            else if (v > sec[s])  { sec[s] = v; }
                        }
                        if (c0 + 1 < NC) {
                            float v = acc[mt][nt][h * 2 + 1] - hn1;
                            if (v > best[s])      { sec[s] = best[s]; best[s] = v; bidx[s] = c0 + 1; }
                            else if (v > sec[s])  { sec[s] = v; }
                        }
                    }
                    acc[mt][nt][0] = 0.0f; acc[mt][nt][1] = 0.0f;
                    acc[mt][nt][2] = 0.0f; acc[mt][nt][3] = 0.0f;
                }
            }
        }
    }

    float* red_val = (float*)(smem + Q_ZBYTES);
    float* red_sec = (float*)(smem + Q_ZBYTES + 2048);
    int*   red_idx = (int*)(smem + Q_ZBYTES + 4096);
    int*   row_idx = (int*)(smem + Q_ZBYTES + 6144);

#pragma unroll
    for (int slot = 0; slot < 8; slot++) {
        float b1 = best[slot], b2 = sec[slot]; int i1 = bidx[slot];
#pragma unroll
        for (int off = 1; off <= 2; off <<= 1) {
            float ob1 = __shfl_xor_sync(0xFFFFFFFFu, b1, off);
            int   oi1 = __shfl_xor_sync(0xFFFFFFFFu, i1, off);
            float ob2 = __shfl_xor_sync(0xFFFFFFFFu, b2, off);
            top2_merge(b1, i1, b2, ob1, oi1, ob2);
        }
        if ((lane & 3) == 0) {
            int mt = slot >> 1, h = slot & 1;
            int row = warpM * 64 + mt * 16 + (lane >> 2) + h * 8;
            red_val[row * 4 + warpN] = b1;
            red_sec[row * 4 + warpN] = b2;
            red_idx[row * 4 + warpN] = i1;
        }
    }
    __syncthreads();

    if (t < 128) {
        float b1 = red_val[t * 4], b2 = red_sec[t * 4];
        int i1 = red_idx[t * 4];
#pragma unroll
        for (int q = 1; q < 4; q++)
            top2_merge(b1, i1, b2, red_val[t * 4 + q], red_idx[t * 4 + q], red_sec[t * 4 + q]);
        row_idx[t] = i1;
        out_idx[rowBase + t] = (float)i1;
        if (b1 - b2 <= FLAG_THRESH) {
            int pos = atomicAdd(&g_flag_count, 1);
            g_flag_list[pos] = rowBase + t;
        }
    }
    __syncthreads();

    for (int r = 0; r < 128; r++) {
        int code = row_idx[r];
        out_hard[(size_t)(rowBase + r) * CD + t] = __ldg(&cb[(size_t)code * CD + t]);
    }
}

// ---------------------------------------------------------------------------
// Fixup (mma, 3-pass): SPLIT over codes. Block = (token_tile, code_split).
// Each block scans 512 codes, merges per-token best into g_merge via atomicMax.
// ---------------------------------------------------------------------------
#define F_ZBYTES  (2 * 128 * 264 * 2)
#define F_CBBYTES (4 * 18432)
#define F_SMEM    (F_ZBYTES + F_CBBYTES)

__device__ __forceinline__ void f_load_cb(uint32_t CBB, int buf, int tt, int kc, int t) {
#pragma unroll
    for (int q = 0; q < 8; q++) {
        int i = t + 256 * q;
        int hl = i >> 10, r = (i >> 3) & 127, cc = i & 7;
        int code = 1 + tt * 128 + r;
        if (code > NC - 1) code = NC - 1;
        const unsigned short* src = (hl ? g_cb_lo : g_cb_hi)
            + (size_t)code * CD + kc * 64 + cc * 8;
        cp16(CBB + (buf * 2 + hl) * 18432 + r * 144 + cc * 16, src);
    }
}

__global__ __launch_bounds__(256, 1)
void fixup_mma_kernel(float* __restrict__ out_idx) {
    __shared__ int s_tok[128];
    extern __shared__ unsigned char smem[];
    const uint32_t sb  = smem_u32(smem);
    const uint32_t ZB  = sb;
    const uint32_t CBB = sb + F_ZBYTES;

    const int t = threadIdx.x, lane = t & 31, w = t >> 5;
    const int warpM = w & 1, warpN = w >> 1;
    const int count = g_flag_count;
    const int tileTok = blockIdx.x >> 3;       // token tile
    const int split   = blockIdx.x & 7;        // code split (512 codes each)
    const int base    = tileTok * 128;
    if (base >= count) return;

    if (t < 128) {
        int idx = base + t;
        if (idx > count - 1) idx = count - 1;
        s_tok[t] = g_flag_list[idx];
    }
    __syncthreads();

    // stage z tile (hi|lo), full K, with token indirection
#pragma unroll
    for (int q = 0; q < 32; q++) {
        int i = t + 256 * q;
        int hl = i >> 12, r = (i >> 5) & 127, cc = i & 31;
        const unsigned short* src = (hl ? g_z_lo : g_z_hi)
            + (size_t)s_tok[r] * CD + cc * 8;
        cp16(ZB + hl * 67584 + r * 528 + cc * 16, src);
    }
    f_load_cb(CBB, 0, split * 4, 0, t);
    CP_COMMIT();

    float acc[4][4][4];
#pragma unroll
    for (int mt = 0; mt < 4; mt++)
#pragma unroll
        for (int nt = 0; nt < 4; nt++)
#pragma unroll
            for (int c = 0; c < 4; c++) acc[mt][nt][c] = 0.0f;

    float best[8];
    int   bidx[8];
#pragma unroll
    for (int s = 0; s < 8; s++) { best[s] = -3.0e38f; bidx[s] = 1; }

    const uint32_t a_row  = warpM * 64 + (lane & 15);
    const uint32_t a_col8 = (lane >> 4) * 8;
    const uint32_t b_row  = warpN * 32 + (lane & 7);
    const uint32_t b_col8 = ((lane >> 3) & 1) * 8;

    for (int it = 0; it < 16; it++) {
        const int tt = split * 4 + (it >> 2), kc = it & 3, buf = it & 1;
        if (it + 1 < 16) { f_load_cb(CBB, (it + 1) & 1, split * 4 + ((it + 1) >> 2), (it + 1) & 3, t); CP_COMMIT(); CP_WAIT(1); }
        else             { CP_WAIT(0); }
        __syncthreads();

#pragma unroll
        for (int ks = 0; ks < 4; ks++) {
            const int k = kc * 64 + ks * 16;
            uint32_t bh[4][2], bl[4][2];
#pragma unroll
            for (int nt = 0; nt < 4; nt++) {
                uint32_t baddr = CBB + (buf * 2) * 18432 + ((b_row + nt * 8) * 72 + ks * 16 + b_col8) * 2;
                LDSM2(bh[nt][0], bh[nt][1], baddr);
                LDSM2(bl[nt][0], bl[nt][1], baddr + 18432);
            }
#pragma unroll
            for (int mt = 0; mt < 4; mt++) {
                uint32_t ah[4], al[4];
                uint32_t aaddr = ZB + ((a_row + mt * 16) * 264 + k + a_col8) * 2;
                LDSM4(ah[0], ah[1], ah[2], ah[3], aaddr);
                LDSM4(al[0], al[1], al[2], al[3], aaddr + 67584);
#pragma unroll
                for (int nt = 0; nt < 4; nt++) {
                    MMA16816(acc[mt][nt], ah, bh[nt]);
                    MMA16816(acc[mt][nt], ah, bl[nt]);
                    MMA16816(acc[mt][nt], al, bh[nt]);
                }
            }
        }
        __syncthreads();

        if (kc == 3) {
            const int codeTile = 1 + tt * 128 + warpN * 32;
#pragma unroll
            for (int nt = 0; nt < 4; nt++) {
                int c0 = codeTile + nt * 8 + (lane & 3) * 2;
                float hn0 = (c0 < NC)     ? __ldg(&g_half_norm[c0])     : 0.0f;
                float hn1 = (c0 + 1 < NC) ? __ldg(&g_half_norm[c0 + 1]) : 0.0f;
#pragma unroll
                for (int mt = 0; mt < 4; mt++) {
                    if (c0 < NC) {
                        float s0 = acc[mt][nt][0] - hn0;
                        if (s0 > best[mt * 2])     { best[mt * 2] = s0;     bidx[mt * 2] = c0; }
                        float s2 = acc[mt][nt][2] - hn0;
                        if (s2 > best[mt * 2 + 1]) { best[mt * 2 + 1] = s2; bidx[mt * 2 + 1] = c0; }
                    }
                    if (c0 + 1 < NC) {
                        float s1 = acc[mt][nt][1] - hn1;
                        if (s1 > best[mt * 2])     { best[mt * 2] = s1;     bidx[mt * 2] = c0 + 1; }
                        float s3 = acc[mt][nt][3] - hn1;
                        if (s3 > best[mt * 2 + 1]) { best[mt * 2 + 1] = s3; bidx[mt * 2 + 1] = c0 + 1; }
                    }
                    acc[mt][nt][0] = 0.0f; acc[mt][nt][1] = 0.0f;
                    acc[mt][nt][2] = 0.0f; acc[mt][nt][3] = 0.0f;
                }
            }
        }
    }

    float* red_val = (float*)(smem + F_ZBYTES);
    int*   red_idx = (int*)(smem + F_ZBYTES + 2048);

#pragma unroll
    for (int slot = 0; slot < 8; slot++) {
        float v = best[slot]; int ix = bidx[slot];
#pragma unroll
        for (int off = 1; off <= 2; off <<= 1) {
            float ov = __shfl_xor_sync(0xFFFFFFFFu, v, off);
            int   oi = __shfl_xor_sync(0xFFFFFFFFu, ix, off);
            if (ov > v || (ov == v && oi < ix)) { v = ov; ix = oi; }
        }
        if ((lane & 3) == 0) {
            int mt = slot >> 1, h = slot & 1;
            int row = warpM * 64 + mt * 16 + (lane >> 2) + h * 8;
            red_val[row * 4 + warpN] = v;
            red_idx[row * 4 + warpN] = ix;
        }
    }
    __syncthreads();

    if (t < 128) {
        float bv = red_val[t * 4]; int bi = red_idx[t * 4];
#pragma unroll
        for (int q = 1; q < 4; q++) {
            float v = red_val[t * 4 + q]; int ix = red_idx[t * 4 + q];
            if (v > bv || (v == bv && ix < bi)) { bv = v; bi = ix; }
        }
        unsigned long long pack =
            ((unsigned long long)fkey(bv) << 32) | (unsigned long long)(0xFFFFFFFFu - (uint32_t)bi);
        atomicMax(&g_merge[s_tok[t]], pack);
    }
}

// ---------------------------------------------------------------------------
// Apply: write out_idx / out_hard for flagged tokens from g_merge.
// ---------------------------------------------------------------------------
__global__ __launch_bounds__(256)
void apply_kernel(const float* __restrict__ cb,
                  float* __restrict__ out_idx, float* __restrict__ out_hard) {
    __shared__ int s_tok[128];
    __shared__ int s_code[128];
    const int t = threadIdx.x;
    const int count = g_flag_count;
    const int base = blockIdx.x * 128;
    if (base >= count) return;

    if (t < 128) {
        int idx = base + t;
        if (idx > count - 1) idx = count - 1;
        int token = g_flag_list[idx];
        unsigned long long m = g_merge[token];
        int code = (int)(0xFFFFFFFFu - (uint32_t)(m & 0xFFFFFFFFull));
        s_tok[t] = token;
        s_code[t] = code;
        out_idx[token] = (float)code;
    }
    __syncthreads();

    for (int r = 0; r < 128; r++) {
        int code  = s_code[r];
        int token = s_tok[r];
        out_hard[(size_t)token * CD + t] = __ldg(&cb[(size_t)code * CD + t]);
    }
}

// ---------------------------------------------------------------------------
// Launch
// ---------------------------------------------------------------------------
extern "C" void kernel_launch(void* const* d_in, const int* in_sizes, int n_in,
                              void* d_out, int out_size) {
    const float* x  = (const float*)d_in[0];   // [32768, 1024]
    const float* cb = (const float*)d_in[1];   // [4096, 256]
    const float* W  = (const float*)d_in[2];   // [1024, 256]
    const float* b  = (const float*)d_in[3];   // [256]

    float* out   = (float*)d_out;
    float* z     = out;                              // [32768, 256]
    float* oidx  = out + (size_t)M_TOK * CD;         // [32768]
    float* ohard = oidx + M_TOK;                     // [32768, 256]

    cudaFuncSetAttribute(gemm1_mma_kernel, cudaFuncAttributeMaxDynamicSharedMemorySize, G1_SMEM);
    cudaFuncSetAttribute(quant_mma_kernel, cudaFuncAttributeMaxDynamicSharedMemorySize, Q_SMEM);
    cudaFuncSetAttribute(fixup_mma_kernel, cudaFuncAttributeMaxDynamicSharedMemorySize, F_SMEM);

    reset_kernel<<<1, 1>>>();
    conv_x_kernel<<<(int)((size_t)M_TOK * DMODEL / 4 / 256), 256>>>(x);
    conv_w_kernel<<<(CD * DMODEL) / 256, 256>>>(W);
    halfnorm_kernel<<<NC / 8, 256>>>(cb);
    conv_cb_kernel<<<(NC * CD / 4) / 256, 256>>>(cb);

    gemm1_mma_kernel<<<dim3(M_TOK / 128, CD / 128), 256, G1_SMEM>>>(b, z);
    normalize_kernel<<<M_TOK / 8, 256>>>(z);
    conv_z_kernel<<<(M_TOK * CD / 4) / 256, 256>>>(z);

    quant_mma_kernel<<<M_TOK / 128, 256, Q_SMEM>>>(cb, oidx, ohard);
    fixup_mma_kernel<<<(M_TOK / 128) * 8, 256, F_SMEM>>>(oidx);
    apply_kernel<<<M_TOK / 128, 256>>>(cb, oidx, ohard);
}

// round 12
// speedup vs baseline: 6.0104x; 1.0914x over previous
#include <cuda_runtime.h>
#include <cuda_bf16.h>
#include <math.h>
#include <stdint.h>

#define M_TOK 32768
#define DMODEL 1024
#define CD 256
#define NC 4096

#define FLAG_THRESH 1.5e-3f

// ---------------------------------------------------------------------------
// Static device scratch
// ---------------------------------------------------------------------------
__device__ float g_half_norm[NC];
__device__ unsigned short g_x_hi[(size_t)M_TOK * DMODEL];
__device__ unsigned short g_x_lo[(size_t)M_TOK * DMODEL];
__device__ unsigned short g_w_hi[(size_t)CD * DMODEL];   // transposed [n][k]
__device__ unsigned short g_w_lo[(size_t)CD * DMODEL];
__device__ unsigned short g_z_hi[(size_t)M_TOK * CD];
__device__ unsigned short g_z_lo[(size_t)M_TOK * CD];
__device__ unsigned short g_cb_hi[(size_t)NC * CD];
__device__ unsigned short g_cb_lo[(size_t)NC * CD];
__device__ int g_flag_count;
__device__ int g_flag_list[M_TOK];
__device__ unsigned long long g_merge[M_TOK];   // packed (score_key, ~code)

// ---------------------------------------------------------------------------
// PTX helpers
// ---------------------------------------------------------------------------
__device__ __forceinline__ uint32_t smem_u32(const void* p) {
    uint32_t a;
    asm("{ .reg .u64 t; cvta.to.shared.u64 t, %1; cvt.u32.u64 %0, t; }" : "=r"(a) : "l"(p));
    return a;
}
__device__ __forceinline__ void cp16(uint32_t dst, const void* src) {
    asm volatile("cp.async.cg.shared.global [%0], [%1], 16;" :: "r"(dst), "l"(src));
}
#define CP_COMMIT() asm volatile("cp.async.commit_group;" ::: "memory")
#define CP_WAIT(n)  asm volatile("cp.async.wait_group %0;" :: "n"(n) : "memory")

#define LDSM4(r0, r1, r2, r3, addr) \
    asm volatile("ldmatrix.sync.aligned.m8n8.x4.shared.b16 {%0,%1,%2,%3}, [%4];" \
                 : "=r"(r0), "=r"(r1), "=r"(r2), "=r"(r3) : "r"(addr))
#define LDSM2(r0, r1, addr) \
    asm volatile("ldmatrix.sync.aligned.m8n8.x2.shared.b16 {%0,%1}, [%2];" \
                 : "=r"(r0), "=r"(r1) : "r"(addr))

#define MMA16816(c, a, b) \
    asm volatile("mma.sync.aligned.m16n8k16.row.col.f32.bf16.bf16.f32 " \
                 "{%0,%1,%2,%3}, {%4,%5,%6,%7}, {%8,%9}, {%0,%1,%2,%3};" \
                 : "+f"((c)[0]), "+f"((c)[1]), "+f"((c)[2]), "+f"((c)[3]) \
                 : "r"((a)[0]), "r"((a)[1]), "r"((a)[2]), "r"((a)[3]), \
                   "r"((b)[0]), "r"((b)[1]))

// monotone float -> u32 key (order-preserving)
__device__ __forceinline__ uint32_t fkey(float f) {
    uint32_t u = __float_as_uint(f);
    return (u & 0x80000000u) ? ~u : (u | 0x80000000u);
}

// ---------------------------------------------------------------------------
// hi/lo bf16 split helpers
// ---------------------------------------------------------------------------
__device__ __forceinline__ void split4(float4 v, uint2& hi, uint2& lo) {
    float f[4] = {v.x, v.y, v.z, v.w};
    unsigned short h[4], l[4];
#pragma unroll
    for (int i = 0; i < 4; i++) {
        __nv_bfloat16 hb = __float2bfloat16(f[i]);
        h[i] = __bfloat16_as_ushort(hb);
        l[i] = __bfloat16_as_ushort(__float2bfloat16(f[i] - __bfloat162float(hb)));
    }
    hi.x = (uint32_t)h[0] | ((uint32_t)h[1] << 16);
    hi.y = (uint32_t)h[2] | ((uint32_t)h[3] << 16);
    lo.x = (uint32_t)l[0] | ((uint32_t)l[1] << 16);
    lo.y = (uint32_t)l[2] | ((uint32_t)l[3] << 16);
}

// ---------------------------------------------------------------------------
// Prep kernels
// ---------------------------------------------------------------------------
__global__ __launch_bounds__(256)
void conv_x_kernel(const float* __restrict__ x) {
    size_t gid = (size_t)blockIdx.x * 256 + threadIdx.x;
    float4 v = *(const float4*)&x[gid * 4];
    uint2 hi, lo; split4(v, hi, lo);
    *(uint2*)&g_x_hi[gid * 4] = hi;
    *(uint2*)&g_x_lo[gid * 4] = lo;
}

__global__ __launch_bounds__(256)
void conv_w_kernel(const float* __restrict__ W) {
    size_t gid = (size_t)blockIdx.x * 256 + threadIdx.x;
    int n = (int)(gid >> 10);
    int k = (int)(gid & 1023);
    float v = W[(size_t)k * CD + n];
    __nv_bfloat16 hb = __float2bfloat16(v);
    g_w_hi[gid] = __bfloat16_as_ushort(hb);
    g_w_lo[gid] = __bfloat16_as_ushort(__float2bfloat16(v - __bfloat162float(hb)));
}

__global__ __launch_bounds__(256)
void conv_cb_kernel(const float* __restrict__ cb) {
    size_t gid = (size_t)blockIdx.x * 256 + threadIdx.x;   // over NC*CD/4
    float4 v = *(const float4*)&cb[gid * 4];
    uint2 hi, lo; split4(v, hi, lo);
    *(uint2*)&g_cb_hi[gid * 4] = hi;
    *(uint2*)&g_cb_lo[gid * 4] = lo;
}

// normalize + hi/lo conversion fused (was separate conv_z kernel)
__global__ __launch_bounds__(256)
void normalize_kernel(float* __restrict__ z) {
    const int warp = threadIdx.x >> 5;
    const int lane = threadIdx.x & 31;
    const int row  = blockIdx.x * 8 + warp;
    float4* z4 = (float4*)z;
    size_t base = (size_t)row * 64;
    float4 v0 = z4[base + lane];
    float4 v1 = z4[base + 32 + lane];
    float s = v0.x*v0.x + v0.y*v0.y + v0.z*v0.z + v0.w*v0.w
            + v1.x*v1.x + v1.y*v1.y + v1.z*v1.z + v1.w*v1.w;
#pragma unroll
    for (int o = 16; o > 0; o >>= 1) s += __shfl_xor_sync(0xFFFFFFFFu, s, o);
    float inv = 1.0f / (sqrtf(s) + 1e-6f);
    v0.x *= inv; v0.y *= inv; v0.z *= inv; v0.w *= inv;
    v1.x *= inv; v1.y *= inv; v1.z *= inv; v1.w *= inv;
    z4[base + lane]      = v0;
    z4[base + 32 + lane] = v1;

    uint2 h0, l0, h1, l1;
    split4(v0, h0, l0);
    split4(v1, h1, l1);
    size_t kb = (size_t)row * CD + lane * 4;
    *(uint2*)&g_z_hi[kb]       = h0;
    *(uint2*)&g_z_lo[kb]       = l0;
    *(uint2*)&g_z_hi[kb + 128] = h1;
    *(uint2*)&g_z_lo[kb + 128] = l1;
}

__global__ __launch_bounds__(256)
void halfnorm_kernel(const float* __restrict__ cb) {
    const int warp = threadIdx.x >> 5;
    const int lane = threadIdx.x & 31;
    const int code = blockIdx.x * 8 + warp;
    const float4* c4 = (const float4*)cb;
    size_t base = (size_t)code * 64;
    float4 v0 = c4[base + lane];
    float4 v1 = c4[base + 32 + lane];
    float s = v0.x*v0.x + v0.y*v0.y + v0.z*v0.z + v0.w*v0.w
            + v1.x*v1.x + v1.y*v1.y + v1.z*v1.z + v1.w*v1.w;
#pragma unroll
    for (int o = 16; o > 0; o >>= 1) s += __shfl_xor_sync(0xFFFFFFFFu, s, o);
    if (lane == 0) g_half_norm[code] = 0.5f * s;
}

__global__ void reset_kernel() { g_flag_count = 0; }

// ---------------------------------------------------------------------------
// GEMM1 v2 (mma.sync, 3-pass): BM=64, BN=128 -> 2 CTAs/SM.
// 8 warps as 2(M) x 4(N); warp tile 32x32; acc[2][4][4].
// smem: XS 2buf*2hl*64*144 = 36864 ; WS 2buf*2hl*128*144 = 73728 ; tot 110592
// ---------------------------------------------------------------------------
#define G1_XSTRIDE 9216          // one (buf,hl) x-plane: 64*144
#define G1_WSTRIDE 18432         // one (buf,hl) w-plane: 128*144
#define G1_SMEM (4 * G1_XSTRIDE + 4 * G1_WSTRIDE)   // 110592

__device__ __forceinline__ void g1_load(uint32_t XS, uint32_t WS, int buf, int kc,
                                        int rowBase, int colBase, int t) {
#pragma unroll
    for (int q = 0; q < 4; q++) {
        int i = t + 256 * q;               // 0..1023
        int hl = i >> 9, rem = i & 511;
        int r = rem >> 3, cc = rem & 7;
        const unsigned short* src = (hl ? g_x_lo : g_x_hi)
            + (size_t)(rowBase + r) * DMODEL + kc * 64 + cc * 8;
        cp16(XS + (buf * 2 + hl) * G1_XSTRIDE + r * 144 + cc * 16, src);
    }
#pragma unroll
    for (int q = 0; q < 8; q++) {
        int i = t + 256 * q;               // 0..2047
        int hl = i >> 10, rem = i & 1023;
        int r = rem >> 3, cc = rem & 7;
        const unsigned short* src = (hl ? g_w_lo : g_w_hi)
            + (size_t)(colBase + r) * DMODEL + kc * 64 + cc * 8;
        cp16(WS + (buf * 2 + hl) * G1_WSTRIDE + r * 144 + cc * 16, src);
    }
}

__global__ __launch_bounds__(256, 2)
void gemm1_mma_kernel(const float* __restrict__ bias, float* __restrict__ z) {
    extern __shared__ unsigned char smem[];
    const uint32_t sb = smem_u32(smem);
    const uint32_t XS = sb;
    const uint32_t WS = sb + 4 * G1_XSTRIDE;

    const int t = threadIdx.x, lane = t & 31, w = t >> 5;
    const int warpM = w & 1, warpN = w >> 1;
    const int rowBase = blockIdx.x * 64;
    const int colBase = blockIdx.y * 128;

    float acc[2][4][4];
#pragma unroll
    for (int mt = 0; mt < 2; mt++)
#pragma unroll
        for (int nt = 0; nt < 4; nt++)
#pragma unroll
            for (int c = 0; c < 4; c++) acc[mt][nt][c] = 0.0f;

    const uint32_t a_row  = warpM * 32 + (lane & 15);
    const uint32_t a_col8 = (lane >> 4) * 8;
    const uint32_t b_row  = warpN * 32 + (lane & 7);
    const uint32_t b_col8 = ((lane >> 3) & 1) * 8;

    g1_load(XS, WS, 0, 0, rowBase, colBase, t);
    CP_COMMIT();

    for (int kc = 0; kc < 16; kc++) {
        const int buf = kc & 1;
        if (kc + 1 < 16) { g1_load(XS, WS, (kc + 1) & 1, kc + 1, rowBase, colBase, t); CP_COMMIT(); CP_WAIT(1); }
        else             { CP_WAIT(0); }
        __syncthreads();

#pragma unroll
        for (int ks = 0; ks < 4; ks++) {
            uint32_t bh[4][2], bl[4][2];
#pragma unroll
            for (int nt = 0; nt < 4; nt++) {
                uint32_t baddr = WS + (buf * 2) * G1_WSTRIDE + ((b_row + nt * 8) * 72 + ks * 16 + b_col8) * 2;
                LDSM2(bh[nt][0], bh[nt][1], baddr);
                LDSM2(bl[nt][0], bl[nt][1], baddr + G1_WSTRIDE);
            }
#pragma unroll
            for (int mt = 0; mt < 2; mt++) {
                uint32_t ah[4], al[4];
                uint32_t aaddr = XS + (buf * 2) * G1_XSTRIDE + ((a_row + mt * 16) * 72 + ks * 16 + a_col8) * 2;
                LDSM4(ah[0], ah[1], ah[2], ah[3], aaddr);
                LDSM4(al[0], al[1], al[2], al[3], aaddr + G1_XSTRIDE);
#pragma unroll
                for (int nt = 0; nt < 4; nt++) {
                    MMA16816(acc[mt][nt], ah, bh[nt]);
                    MMA16816(acc[mt][nt], ah, bl[nt]);
                    MMA16816(acc[mt][nt], al, bh[nt]);
                }
            }
        }
        __syncthreads();
    }

    const int row0 = rowBase + warpM * 32 + (lane >> 2);
    const int col0 = colBase + warpN * 32 + (lane & 3) * 2;
#pragma unroll
    for (int mt = 0; mt < 2; mt++) {
#pragma unroll
        for (int nt = 0; nt < 4; nt++) {
            int r0 = row0 + mt * 16;
            int c  = col0 + nt * 8;
            float b0 = __ldg(&bias[c]), b1 = __ldg(&bias[c + 1]);
            *(float2*)&z[(size_t)r0 * CD + c]       = make_float2(acc[mt][nt][0] + b0, acc[mt][nt][1] + b1);
            *(float2*)&z[(size_t)(r0 + 8) * CD + c] = make_float2(acc[mt][nt][2] + b0, acc[mt][nt][3] + b1);
        }
    }
}

// ---------------------------------------------------------------------------
// Quant v2: 64-token CTA, 1-pass hi*hi + top-2 certification, 2 CTAs/SM.
// cb tiles: 128 codes x 64-col K-chunk (double buffered).
// smem: z 64*528 = 33792 ; cb 2*18432 = 36864 ; total 70656.
// ---------------------------------------------------------------------------
#define Q_ZBYTES  (64 * 528)             // 33792
#define Q_CBSTRIDE 18432
#define Q_SMEM    (Q_ZBYTES + 2 * Q_CBSTRIDE)

__device__ __forceinline__ void top2_merge(float& b1, int& i1, float& b2,
                                           float ob1, int oi1, float ob2) {
    if (ob1 > b1)      { b2 = fmaxf(b1, ob2); b1 = ob1; i1 = oi1; }
    else if (ob1 == b1){ if (oi1 != i1) b2 = b1; else b2 = fmaxf(b2, ob2); i1 = min(i1, oi1); }
    else               { b2 = fmaxf(b2, ob1); }
}

__device__ __forceinline__ void q_load_cb_hi(uint32_t CBB, int buf, int tt, int kc, int t) {
#pragma unroll
    for (int q = 0; q < 4; q++) {
        int i = t + 256 * q;               // 0..1023
        int r = i >> 3, cc = i & 7;
        int code = 1 + tt * 128 + r;
        if (code > NC - 1) code = NC - 1;
        cp16(CBB + buf * Q_CBSTRIDE + r * 144 + cc * 16,
             g_cb_hi + (size_t)code * CD + kc * 64 + cc * 8);
    }
}

__global__ __launch_bounds__(256, 2)
void quant_mma_kernel(const float* __restrict__ cb,
                      float* __restrict__ out_idx, float* __restrict__ out_hard) {
    extern __shared__ unsigned char smem[];
    const uint32_t sb  = smem_u32(smem);
    const uint32_t ZB  = sb;
    const uint32_t CBB = sb + Q_ZBYTES;

    const int t = threadIdx.x, lane = t & 31, w = t >> 5;
    const int warpM = w & 1, warpN = w >> 1;
    const int rowBase = blockIdx.x * 64;

    // stage z_hi tile (64 rows, full K=256)
#pragma unroll
    for (int q = 0; q < 8; q++) {
        int i = t + 256 * q;               // 0..2047
        int r = i >> 5, cc = i & 31;
        cp16(ZB + r * 528 + cc * 16, g_z_hi + (size_t)(rowBase + r) * CD + cc * 8);
    }
    q_load_cb_hi(CBB, 0, 0, 0, t);
    CP_COMMIT();

    float acc[2][4][4];
#pragma unroll
    for (int mt = 0; mt < 2; mt++)
#pragma unroll
        for (int nt = 0; nt < 4; nt++)
#pragma unroll
            for (int c = 0; c < 4; c++) acc[mt][nt][c] = 0.0f;

    float best[4], sec[4];
    int   bidx[4];
#pragma unroll
    for (int s = 0; s < 4; s++) { best[s] = -3.0e38f; sec[s] = -3.0e38f; bidx[s] = 1; }

    const uint32_t a_row  = warpM * 32 + (lane & 15);
    const uint32_t a_col8 = (lane >> 4) * 8;
    const uint32_t b_row  = warpN * 32 + (lane & 7);
    const uint32_t b_col8 = ((lane >> 3) & 1) * 8;

    for (int it = 0; it < 128; it++) {
        const int tt = it >> 2, kc = it & 3, buf = it & 1;
        if (it + 1 < 128) { q_load_cb_hi(CBB, (it + 1) & 1, (it + 1) >> 2, (it + 1) & 3, t); CP_COMMIT(); CP_WAIT(1); }
        else              { CP_WAIT(0); }
        __syncthreads();

#pragma unroll
        for (int ks = 0; ks < 4; ks++) {
            const int k = kc * 64 + ks * 16;
            uint32_t bh[4][2];
#pragma unroll
            for (int nt = 0; nt < 4; nt++) {
                uint32_t baddr = CBB + buf * Q_CBSTRIDE + ((b_row + nt * 8) * 72 + ks * 16 + b_col8) * 2;
                LDSM2(bh[nt][0], bh[nt][1], baddr);
            }
#pragma unroll
            for (int mt = 0; mt < 2; mt++) {
                uint32_t ah[4];
                uint32_t aaddr = ZB + ((a_row + mt * 16) * 264 + k + a_col8) * 2;
                LDSM4(ah[0], ah[1], ah[2], ah[3], aaddr);
#pragma unroll
                for (int nt = 0; nt < 4; nt++)
                    MMA16816(acc[mt][nt], ah, bh[nt]);
            }
        }
        __syncthreads();

        if (kc == 3) {
            const int codeTile = 1 + tt * 128 + warpN * 32;
#pragma unroll
            for (int nt = 0; nt < 4; nt++) {
                int c0 = codeTile + nt * 8 + (lane & 3) * 2;
                float hn0 = (c0 < NC)     ? __ldg(&g_half_norm[c0])     : 0.0f;
                float hn1 = (c0 + 1 < NC) ? __ldg(&g_half_norm[c0 + 1]) : 0.0f;
#pragma unroll
                for (int mt = 0; mt < 2; mt++) {
#pragma unroll
                    for (int h = 0; h < 2; h++) {
                        int s = mt * 2 + h;
                        if (c0 < NC) {
                            float v = acc[mt][nt][h * 2] - hn0;
                            if (v > best[s])      { sec[s] = best[s]; best[s] = v; bidx[s] = c0; }
                            else if (v > sec[s])  { sec[s] = v; }
                        }
                        if (c0 + 1 < NC) {
                            float v = acc[mt][nt][h * 2 + 1] - hn1;
                            if (v > best[s])      { sec[s] = best[s]; best[s] = v; bidx[s] = c0 + 1; }
                            else if (v > sec[s])  { sec[s] = v; }
                        }
                    }
                    acc[mt][nt][0] = 0.0f; acc[mt][nt][1] = 0.0f;
                    acc[mt][nt][2] = 0.0f; acc[mt][nt][3] = 0.0f;
                }
            }
        }
    }

    // reduce: 4 lanes (lane&3) share each row-slot, then 4 warpN columns
    float* red_val = (float*)(smem + Q_ZBYTES);            // 64*4 floats
    float* red_sec = (float*)(smem + Q_ZBYTES + 1024);
    int*   red_idx = (int*)(smem + Q_ZBYTES + 2048);
    int*   row_idx = (int*)(smem + Q_ZBYTES + 3072);

#pragma unroll
    for (int slot = 0; slot < 4; slot++) {
        float b1 = best[slot], b2 = sec[slot]; int i1 = bidx[slot];
#pragma unroll
        for (int off = 1; off <= 2; off <<= 1) {
            float ob1 = __shfl_xor_sync(0xFFFFFFFFu, b1, off);
            int   oi1 = __shfl_xor_sync(0xFFFFFFFFu, i1, off);
            float ob2 = __shfl_xor_sync(0xFFFFFFFFu, b2, off);
            top2_merge(b1, i1, b2, ob1, oi1, ob2);
        }
        if ((lane & 3) == 0) {
            int mt = slot >> 1, h = slot & 1;
            int row = warpM * 32 + mt * 16 + (lane >> 2) + h * 8;
            red_val[row * 4 + warpN] = b1;
            red_sec[row * 4 + warpN] = b2;
            red_idx[row * 4 + warpN] = i1;
        }
    }
    __syncthreads();

    if (t < 64) {
        float b1 = red_val[t * 4], b2 = red_sec[t * 4];
        int i1 = red_idx[t * 4];
#pragma unroll
        for (int q = 1; q < 4; q++)
            top2_merge(b1, i1, b2, red_val[t * 4 + q], red_idx[t * 4 + q], red_sec[t * 4 + q]);
        row_idx[t] = i1;
        out_idx[rowBase + t] = (float)i1;
        if (b1 - b2 <= FLAG_THRESH) {
            int pos = atomicAdd(&g_flag_count, 1);
            g_flag_list[pos] = rowBase + t;
        }
    }
    __syncthreads();

    for (int r = 0; r < 64; r++) {
        int code = row_idx[r];
        out_hard[(size_t)(rowBase + r) * CD + t] = __ldg(&cb[(size_t)code * CD + t]);
    }
}

// ---------------------------------------------------------------------------
// Fixup (mma, 3-pass): code-split, merged via atomicMax — unchanged (proven).
// ---------------------------------------------------------------------------
#define F_ZBYTES  (2 * 128 * 264 * 2)
#define F_CBBYTES (4 * 18432)
#define F_SMEM    (F_ZBYTES + F_CBBYTES)

__device__ __forceinline__ void f_load_cb(uint32_t CBB, int buf, int tt, int kc, int t) {
#pragma unroll
    for (int q = 0; q < 8; q++) {
        int i = t + 256 * q;
        int hl = i >> 10, r = (i >> 3) & 127, cc = i & 7;
        int code = 1 + tt * 128 + r;
        if (code > NC - 1) code = NC - 1;
        const unsigned short* src = (hl ? g_cb_lo : g_cb_hi)
            + (size_t)code * CD + kc * 64 + cc * 8;
        cp16(CBB + (buf * 2 + hl) * 18432 + r * 144 + cc * 16, src);
    }
}

__global__ __launch_bounds__(256, 1)
void fixup_mma_kernel(float* __restrict__ out_idx) {
    __shared__ int s_tok[128];
    extern __shared__ unsigned char smem[];
    const uint32_t sb  = smem_u32(smem);
    const uint32_t ZB  = sb;
    const uint32_t CBB = sb + F_ZBYTES;

    const int t = threadIdx.x, lane = t & 31, w = t >> 5;
    const int warpM = w & 1, warpN = w >> 1;
    const int count = g_flag_count;
    const int tileTok = blockIdx.x >> 3;
    const int split   = blockIdx.x & 7;
    const int base    = tileTok * 128;
    if (base >= count) return;

    if (t < 128) {
        int idx = base + t;
        if (idx > count - 1) idx = count - 1;
        s_tok[t] = g_flag_list[idx];
    }
    __syncthreads();

#pragma unroll
    for (int q = 0; q < 32; q++) {
        int i = t + 256 * q;
        int hl = i >> 12, r = (i >> 5) & 127, cc = i & 31;
        const unsigned short* src = (hl ? g_z_lo : g_z_hi)
            + (size_t)s_tok[r] * CD + cc * 8;
        cp16(ZB + hl * 67584 + r * 528 + cc * 16, src);
    }
    f_load_cb(CBB, 0, split * 4, 0, t);
    CP_COMMIT();

    float acc[4][4][4];
#pragma unroll
    for (int mt = 0; mt < 4; mt++)
#pragma unroll
        for (int nt = 0; nt < 4; nt++)
#pragma unroll
            for (int c = 0; c < 4; c++) acc[mt][nt][c] = 0.0f;

    float best[8];
    int   bidx[8];
#pragma unroll
    for (int s = 0; s < 8; s++) { best[s] = -3.0e38f; bidx[s] = 1; }

    const uint32_t a_row  = warpM * 64 + (lane & 15);
    const uint32_t a_col8 = (lane >> 4) * 8;
    const uint32_t b_row  = warpN * 32 + (lane & 7);
    const uint32_t b_col8 = ((lane >> 3) & 1) * 8;

    for (int it = 0; it < 16; it++) {
        const int tt = split * 4 + (it >> 2), kc = it & 3, buf = it & 1;
        if (it + 1 < 16) { f_load_cb(CBB, (it + 1) & 1, split * 4 + ((it + 1) >> 2), (it + 1) & 3, t); CP_COMMIT(); CP_WAIT(1); }
        else             { CP_WAIT(0); }
        __syncthreads();

#pragma unroll
        for (int ks = 0; ks < 4; ks++) {
            const int k = kc * 64 + ks * 16;
            uint32_t bh[4][2], bl[4][2];
#pragma unroll
            for (int nt = 0; nt < 4; nt++) {
                uint32_t baddr = CBB + (buf * 2) * 18432 + ((b_row + nt * 8) * 72 + ks * 16 + b_col8) * 2;
                LDSM2(bh[nt][0], bh[nt][1], baddr);
                LDSM2(bl[nt][0], bl[nt][1], baddr + 18432);
            }
#pragma unroll
            for (int mt = 0; mt < 4; mt++) {
                uint32_t ah[4], al[4];
                uint32_t aaddr = ZB + ((a_row + mt * 16) * 264 + k + a_col8) * 2;
                LDSM4(ah[0], ah[1], ah[2], ah[3], aaddr);
                LDSM4(al[0], al[1], al[2], al[3], aaddr + 67584);
#pragma unroll
                for (int nt = 0; nt < 4; nt++) {
                    MMA16816(acc[mt][nt], ah, bh[nt]);
                    MMA16816(acc[mt][nt], ah, bl[nt]);
                    MMA16816(acc[mt][nt], al, bh[nt]);
                }
            }
        }
        __syncthreads();

        if (kc == 3) {
            const int codeTile = 1 + tt * 128 + warpN * 32;
#pragma unroll
            for (int nt = 0; nt < 4; nt++) {
                int c0 = codeTile + nt * 8 + (lane & 3) * 2;
                float hn0 = (c0 < NC)     ? __ldg(&g_half_norm[c0])     : 0.0f;
                float hn1 = (c0 + 1 < NC) ? __ldg(&g_half_norm[c0 + 1]) : 0.0f;
#pragma unroll
                for (int mt = 0; mt < 4; mt++) {
                    if (c0 < NC) {
                        float s0 = acc[mt][nt][0] - hn0;
                        if (s0 > best[mt * 2])     { best[mt * 2] = s0;     bidx[mt * 2] = c0; }
                        float s2 = acc[mt][nt][2] - hn0;
                        if (s2 > best[mt * 2 + 1]) { best[mt * 2 + 1] = s2; bidx[mt * 2 + 1] = c0; }
                    }
                    if (c0 + 1 < NC) {
                        float s1 = acc[mt][nt][1] - hn1;
                        if (s1 > best[mt * 2])     { best[mt * 2] = s1;     bidx[mt * 2] = c0 + 1; }
                        float s3 = acc[mt][nt][3] - hn1;
                        if (s3 > best[mt * 2 + 1]) { best[mt * 2 + 1] = s3; bidx[mt * 2 + 1] = c0 + 1; }
                    }
                    acc[mt][nt][0] = 0.0f; acc[mt][nt][1] = 0.0f;
                    acc[mt][nt][2] = 0.0f; acc[mt][nt][3] = 0.0f;
                }
            }
        }
    }

    float* red_val = (float*)(smem + F_ZBYTES);
    int*   red_idx = (int*)(smem + F_ZBYTES + 2048);

#pragma unroll
    for (int slot = 0; slot < 8; slot++) {
        float v = best[slot]; int ix = bidx[slot];
#pragma unroll
        for (int off = 1; off <= 2; off <<= 1) {
            float ov = __shfl_xor_sync(0xFFFFFFFFu, v, off);
            int   oi = __shfl_xor_sync(0xFFFFFFFFu, ix, off);
            if (ov > v || (ov == v && oi < ix)) { v = ov; ix = oi; }
        }
        if ((lane & 3) == 0) {
            int mt = slot >> 1, h = slot & 1;
            int row = warpM * 64 + mt * 16 + (lane >> 2) + h * 8;
            red_val[row * 4 + warpN] = v;
            red_idx[row * 4 + warpN] = ix;
        }
    }
    __syncthreads();

    if (t < 128) {
        float bv = red_val[t * 4]; int bi = red_idx[t * 4];
#pragma unroll
        for (int q = 1; q < 4; q++) {
            float v = red_val[t * 4 + q]; int ix = red_idx[t * 4 + q];
            if (v > bv || (v == bv && ix < bi)) { bv = v; bi = ix; }
        }
        unsigned long long pack =
            ((unsigned long long)fkey(bv) << 32) | (unsigned long long)(0xFFFFFFFFu - (uint32_t)bi);
        atomicMax(&g_merge[s_tok[t]], pack);
    }
}

// ---------------------------------------------------------------------------
// Apply: write out_idx / out_hard for flagged tokens from g_merge.
// ---------------------------------------------------------------------------
__global__ __launch_bounds__(256)
void apply_kernel(const float* __restrict__ cb,
                  float* __restrict__ out_idx, float* __restrict__ out_hard) {
    __shared__ int s_tok[128];
    __shared__ int s_code[128];
    const int t = threadIdx.x;
    const int count = g_flag_count;
    const int base = blockIdx.x * 128;
    if (base >= count) return;

    if (t < 128) {
        int idx = base + t;
        if (idx > count - 1) idx = count - 1;
        int token = g_flag_list[idx];
        unsigned long long m = g_merge[token];
        int code = (int)(0xFFFFFFFFu - (uint32_t)(m & 0xFFFFFFFFull));
        s_tok[t] = token;
        s_code[t] = code;
        out_idx[token] = (float)code;
    }
    __syncthreads();

    for (int r = 0; r < 128; r++) {
        int code  = s_code[r];
        int token = s_tok[r];
        out_hard[(size_t)token * CD + t] = __ldg(&cb[(size_t)code * CD + t]);
    }
}

// ---------------------------------------------------------------------------
// Launch
// ---------------------------------------------------------------------------
extern "C" void kernel_launch(void* const* d_in, const int* in_sizes, int n_in,
                              void* d_out, int out_size) {
    const float* x  = (const float*)d_in[0];   // [32768, 1024]
    const float* cb = (const float*)d_in[1];   // [4096, 256]
    const float* W  = (const float*)d_in[2];   // [1024, 256]
    const float* b  = (const float*)d_in[3];   // [256]

    float* out   = (float*)d_out;
    float* z     = out;                              // [32768, 256]
    float* oidx  = out + (size_t)M_TOK * CD;         // [32768]
    float* ohard = oidx + M_TOK;                     // [32768, 256]

    cudaFuncSetAttribute(gemm1_mma_kernel, cudaFuncAttributeMaxDynamicSharedMemorySize, G1_SMEM);
    cudaFuncSetAttribute(quant_mma_kernel, cudaFuncAttributeMaxDynamicSharedMemorySize, Q_SMEM);
    cudaFuncSetAttribute(fixup_mma_kernel, cudaFuncAttributeMaxDynamicSharedMemorySize, F_SMEM);

    reset_kernel<<<1, 1>>>();
    conv_x_kernel<<<(int)((size_t)M_TOK * DMODEL / 4 / 256), 256>>>(x);
    conv_w_kernel<<<(CD * DMODEL) / 256, 256>>>(W);
    halfnorm_kernel<<<NC / 8, 256>>>(cb);
    conv_cb_kernel<<<(NC * CD / 4) / 256, 256>>>(cb);

    gemm1_mma_kernel<<<dim3(M_TOK / 64, CD / 128), 256, G1_SMEM>>>(b, z);
    normalize_kernel<<<M_TOK / 8, 256>>>(z);

    quant_mma_kernel<<<M_TOK / 64, 256, Q_SMEM>>>(cb, oidx, ohard);
    fixup_mma_kernel<<<(M_TOK / 128) * 8, 256, F_SMEM>>>(oidx);
    apply_kernel<<<M_TOK / 128, 256>>>(cb, oidx, ohard);
}

// round 14
// speedup vs baseline: 6.2447x; 1.0390x over previous
#include <cuda_runtime.h>
#include <cuda_bf16.h>
#include <math.h>
#include <stdint.h>

#define M_TOK 32768
#define DMODEL 1024
#define CD 256
#define NC 4096

#define FLAG_THRESH 1.5e-3f

// ---------------------------------------------------------------------------
// Static device scratch
// ---------------------------------------------------------------------------
__device__ float g_half_norm[NC];
__device__ unsigned short g_x_hi[(size_t)M_TOK * DMODEL];
__device__ unsigned short g_x_lo[(size_t)M_TOK * DMODEL];
__device__ unsigned short g_w_hi[(size_t)CD * DMODEL];   // transposed [n][k]
__device__ unsigned short g_w_lo[(size_t)CD * DMODEL];
__device__ unsigned short g_z_hi[(size_t)M_TOK * CD];
__device__ unsigned short g_z_lo[(size_t)M_TOK * CD];
__device__ unsigned short g_cb_hi[(size_t)NC * CD];
__device__ unsigned short g_cb_lo[(size_t)NC * CD];
__device__ int g_flag_count;
__device__ int g_flag_list[M_TOK];
__device__ unsigned long long g_merge[M_TOK];   // packed (score_key, ~code)

// ---------------------------------------------------------------------------
// PTX helpers
// ---------------------------------------------------------------------------
__device__ __forceinline__ uint32_t smem_u32(const void* p) {
    uint32_t a;
    asm("{ .reg .u64 t; cvta.to.shared.u64 t, %1; cvt.u32.u64 %0, t; }" : "=r"(a) : "l"(p));
    return a;
}
__device__ __forceinline__ void cp16(uint32_t dst, const void* src) {
    asm volatile("cp.async.cg.shared.global [%0], [%1], 16;" :: "r"(dst), "l"(src));
}
#define CP_COMMIT() asm volatile("cp.async.commit_group;" ::: "memory")
#define CP_WAIT(n)  asm volatile("cp.async.wait_group %0;" :: "n"(n) : "memory")

#define LDSM4(r0, r1, r2, r3, addr) \
    asm volatile("ldmatrix.sync.aligned.m8n8.x4.shared.b16 {%0,%1,%2,%3}, [%4];" \
                 : "=r"(r0), "=r"(r1), "=r"(r2), "=r"(r3) : "r"(addr))
#define LDSM2(r0, r1, addr) \
    asm volatile("ldmatrix.sync.aligned.m8n8.x2.shared.b16 {%0,%1}, [%2];" \
                 : "=r"(r0), "=r"(r1) : "r"(addr))

#define MMA16816(c, a, b) \
    asm volatile("mma.sync.aligned.m16n8k16.row.col.f32.bf16.bf16.f32 " \
                 "{%0,%1,%2,%3}, {%4,%5,%6,%7}, {%8,%9}, {%0,%1,%2,%3};" \
                 : "+f"((c)[0]), "+f"((c)[1]), "+f"((c)[2]), "+f"((c)[3]) \
                 : "r"((a)[0]), "r"((a)[1]), "r"((a)[2]), "r"((a)[3]), \
                   "r"((b)[0]), "r"((b)[1]))

// monotone float -> u32 key (order-preserving)
__device__ __forceinline__ uint32_t fkey(float f) {
    uint32_t u = __float_as_uint(f);
    return (u & 0x80000000u) ? ~u : (u | 0x80000000u);
}

// ---------------------------------------------------------------------------
// hi/lo bf16 split helpers
// ---------------------------------------------------------------------------
__device__ __forceinline__ void split4(float4 v, uint2& hi, uint2& lo) {
    float f[4] = {v.x, v.y, v.z, v.w};
    unsigned short h[4], l[4];
#pragma unroll
    for (int i = 0; i < 4; i++) {
        __nv_bfloat16 hb = __float2bfloat16(f[i]);
        h[i] = __bfloat16_as_ushort(hb);
        l[i] = __bfloat16_as_ushort(__float2bfloat16(f[i] - __bfloat162float(hb)));
    }
    hi.x = (uint32_t)h[0] | ((uint32_t)h[1] << 16);
    hi.y = (uint32_t)h[2] | ((uint32_t)h[3] << 16);
    lo.x = (uint32_t)l[0] | ((uint32_t)l[1] << 16);
    lo.y = (uint32_t)l[2] | ((uint32_t)l[3] << 16);
}

// ---------------------------------------------------------------------------
// Prep kernels
// ---------------------------------------------------------------------------
__global__ __launch_bounds__(256)
void conv_x_kernel(const float* __restrict__ x) {
    if (blockIdx.x == 0 && threadIdx.x == 0) g_flag_count = 0;   // fused reset
    size_t gid = (size_t)blockIdx.x * 256 + threadIdx.x;
    float4 v = *(const float4*)&x[gid * 4];
    uint2 hi, lo; split4(v, hi, lo);
    *(uint2*)&g_x_hi[gid * 4] = hi;
    *(uint2*)&g_x_lo[gid * 4] = lo;
}

__global__ __launch_bounds__(256)
void conv_w_kernel(const float* __restrict__ W) {
    size_t gid = (size_t)blockIdx.x * 256 + threadIdx.x;
    int n = (int)(gid >> 10);
    int k = (int)(gid & 1023);
    float v = W[(size_t)k * CD + n];
    __nv_bfloat16 hb = __float2bfloat16(v);
    g_w_hi[gid] = __bfloat16_as_ushort(hb);
    g_w_lo[gid] = __bfloat16_as_ushort(__float2bfloat16(v - __bfloat162float(hb)));
}

// conv_cb + halfnorm fused: one warp per code, single cb read.
__global__ __launch_bounds__(256)
void cb_prep_kernel(const float* __restrict__ cb) {
    const int warp = threadIdx.x >> 5;
    const int lane = threadIdx.x & 31;
    const int code = blockIdx.x * 8 + warp;
    const float4* c4 = (const float4*)cb;
    size_t base = (size_t)code * 64;
    float4 v0 = c4[base + lane];
    float4 v1 = c4[base + 32 + lane];

    // halfnorm
    float s = v0.x*v0.x + v0.y*v0.y + v0.z*v0.z + v0.w*v0.w
            + v1.x*v1.x + v1.y*v1.y + v1.z*v1.z + v1.w*v1.w;
#pragma unroll
    for (int o = 16; o > 0; o >>= 1) s += __shfl_xor_sync(0xFFFFFFFFu, s, o);
    if (lane == 0) g_half_norm[code] = 0.5f * s;

    // hi/lo split
    uint2 h0, l0, h1, l1;
    split4(v0, h0, l0);
    split4(v1, h1, l1);
    size_t kb = (size_t)code * CD + lane * 4;
    *(uint2*)&g_cb_hi[kb]       = h0;
    *(uint2*)&g_cb_lo[kb]       = l0;
    *(uint2*)&g_cb_hi[kb + 128] = h1;
    *(uint2*)&g_cb_lo[kb + 128] = l1;
}

// normalize + hi/lo conversion fused
__global__ __launch_bounds__(256)
void normalize_kernel(float* __restrict__ z) {
    const int warp = threadIdx.x >> 5;
    const int lane = threadIdx.x & 31;
    const int row  = blockIdx.x * 8 + warp;
    float4* z4 = (float4*)z;
    size_t base = (size_t)row * 64;
    float4 v0 = z4[base + lane];
    float4 v1 = z4[base + 32 + lane];
    float s = v0.x*v0.x + v0.y*v0.y + v0.z*v0.z + v0.w*v0.w
            + v1.x*v1.x + v1.y*v1.y + v1.z*v1.z + v1.w*v1.w;
#pragma unroll
    for (int o = 16; o > 0; o >>= 1) s += __shfl_xor_sync(0xFFFFFFFFu, s, o);
    float inv = 1.0f / (sqrtf(s) + 1e-6f);
    v0.x *= inv; v0.y *= inv; v0.z *= inv; v0.w *= inv;
    v1.x *= inv; v1.y *= inv; v1.z *= inv; v1.w *= inv;
    z4[base + lane]      = v0;
    z4[base + 32 + lane] = v1;

    uint2 h0, l0, h1, l1;
    split4(v0, h0, l0);
    split4(v1, h1, l1);
    size_t kb = (size_t)row * CD + lane * 4;
    *(uint2*)&g_z_hi[kb]       = h0;
    *(uint2*)&g_z_lo[kb]       = l0;
    *(uint2*)&g_z_hi[kb + 128] = h1;
    *(uint2*)&g_z_lo[kb + 128] = l1;
}

// ---------------------------------------------------------------------------
// GEMM1 v2 (mma.sync, 3-pass): BM=64, BN=128, 2 CTAs/SM — unchanged (proven)
// ---------------------------------------------------------------------------
#define G1_XSTRIDE 9216
#define G1_WSTRIDE 18432
#define G1_SMEM (4 * G1_XSTRIDE + 4 * G1_WSTRIDE)   // 110592

__device__ __forceinline__ void g1_load(uint32_t XS, uint32_t WS, int buf, int kc,
                                        int rowBase, int colBase, int t) {
#pragma unroll
    for (int q = 0; q < 4; q++) {
        int i = t + 256 * q;
        int hl = i >> 9, rem = i & 511;
        int r = rem >> 3, cc = rem & 7;
        const unsigned short* src = (hl ? g_x_lo : g_x_hi)
            + (size_t)(rowBase + r) * DMODEL + kc * 64 + cc * 8;
        cp16(XS + (buf * 2 + hl) * G1_XSTRIDE + r * 144 + cc * 16, src);
    }
#pragma unroll
    for (int q = 0; q < 8; q++) {
        int i = t + 256 * q;
        int hl = i >> 10, rem = i & 1023;
        int r = rem >> 3, cc = rem & 7;
        const unsigned short* src = (hl ? g_w_lo : g_w_hi)
            + (size_t)(colBase + r) * DMODEL + kc * 64 + cc * 8;
        cp16(WS + (buf * 2 + hl) * G1_WSTRIDE + r * 144 + cc * 16, src);
    }
}

__global__ __launch_bounds__(256, 2)
void gemm1_mma_kernel(const float* __restrict__ bias, float* __restrict__ z) {
    extern __shared__ unsigned char smem[];
    const uint32_t sb = smem_u32(smem);
    const uint32_t XS = sb;
    const uint32_t WS = sb + 4 * G1_XSTRIDE;

    const int t = threadIdx.x, lane = t & 31, w = t >> 5;
    const int warpM = w & 1, warpN = w >> 1;
    const int rowBase = blockIdx.x * 64;
    const int colBase = blockIdx.y * 128;

    float acc[2][4][4];
#pragma unroll
    for (int mt = 0; mt < 2; mt++)
#pragma unroll
        for (int nt = 0; nt < 4; nt++)
#pragma unroll
            for (int c = 0; c < 4; c++) acc[mt][nt][c] = 0.0f;

    const uint32_t a_row  = warpM * 32 + (lane & 15);
    const uint32_t a_col8 = (lane >> 4) * 8;
    const uint32_t b_row  = warpN * 32 + (lane & 7);
    const uint32_t b_col8 = ((lane >> 3) & 1) * 8;

    g1_load(XS, WS, 0, 0, rowBase, colBase, t);
    CP_COMMIT();

    for (int kc = 0; kc < 16; kc++) {
        const int buf = kc & 1;
        if (kc + 1 < 16) { g1_load(XS, WS, (kc + 1) & 1, kc + 1, rowBase, colBase, t); CP_COMMIT(); CP_WAIT(1); }
        else             { CP_WAIT(0); }
        __syncthreads();

#pragma unroll
        for (int ks = 0; ks < 4; ks++) {
            uint32_t bh[4][2], bl[4][2];
#pragma unroll
            for (int nt = 0; nt < 4; nt++) {
                uint32_t baddr = WS + (buf * 2) * G1_WSTRIDE + ((b_row + nt * 8) * 72 + ks * 16 + b_col8) * 2;
                LDSM2(bh[nt][0], bh[nt][1], baddr);
                LDSM2(bl[nt][0], bl[nt][1], baddr + G1_WSTRIDE);
            }
#pragma unroll
            for (int mt = 0; mt < 2; mt++) {
                uint32_t ah[4], al[4];
                uint32_t aaddr = XS + (buf * 2) * G1_XSTRIDE + ((a_row + mt * 16) * 72 + ks * 16 + a_col8) * 2;
                LDSM4(ah[0], ah[1], ah[2], ah[3], aaddr);
                LDSM4(al[0], al[1], al[2], al[3], aaddr + G1_XSTRIDE);
#pragma unroll
                for (int nt = 0; nt < 4; nt++) {
                    MMA16816(acc[mt][nt], ah, bh[nt]);
                    MMA16816(acc[mt][nt], ah, bl[nt]);
                    MMA16816(acc[mt][nt], al, bh[nt]);
                }
            }
        }
        __syncthreads();
    }

    const int row0 = rowBase + warpM * 32 + (lane >> 2);
    const int col0 = colBase + warpN * 32 + (lane & 3) * 2;
#pragma unroll
    for (int mt = 0; mt < 2; mt++) {
#pragma unroll
        for (int nt = 0; nt < 4; nt++) {
            int r0 = row0 + mt * 16;
            int c  = col0 + nt * 8;
            float b0 = __ldg(&bias[c]), b1 = __ldg(&bias[c + 1]);
            *(float2*)&z[(size_t)r0 * CD + c]       = make_float2(acc[mt][nt][0] + b0, acc[mt][nt][1] + b1);
            *(float2*)&z[(size_t)(r0 + 8) * CD + c] = make_float2(acc[mt][nt][2] + b0, acc[mt][nt][3] + b1);
        }
    }
}

// ---------------------------------------------------------------------------
// Quant v3: 64-token CTA, warp N-tile 64 (nt=8), 2 CTAs/SM.
// cb tiles: 256 codes x 64-col K-chunk (double buffered) -> 64 its, half syncs.
// smem: z 64*528 = 33792 ; cb 2*36864 = 73728 ; total 107520.
// ---------------------------------------------------------------------------
#define Q_ZBYTES   (64 * 528)            // 33792
#define Q_CBSTRIDE 36864                 // 256 codes * 144B
#define Q_SMEM     (Q_ZBYTES + 2 * Q_CBSTRIDE)   // 107520

__device__ __forceinline__ void top2_merge(float& b1, int& i1, float& b2,
                                           float ob1, int oi1, float ob2) {
    if (ob1 > b1)      { b2 = fmaxf(b1, ob2); b1 = ob1; i1 = oi1; }
    else if (ob1 == b1){ if (oi1 != i1) b2 = b1; else b2 = fmaxf(b2, ob2); i1 = min(i1, oi1); }
    else               { b2 = fmaxf(b2, ob1); }
}

__device__ __forceinline__ void q_load_cb_hi(uint32_t CBB, int buf, int tile, int kc, int t) {
#pragma unroll
    for (int q = 0; q < 8; q++) {
        int i = t + 256 * q;               // 0..2047
        int r = i >> 3, cc = i & 7;        // r: 0..255
        int code = 1 + tile * 256 + r;
        if (code > NC - 1) code = NC - 1;
        cp16(CBB + buf * Q_CBSTRIDE + r * 144 + cc * 16,
             g_cb_hi + (size_t)code * CD + kc * 64 + cc * 8);
    }
}

__global__ __launch_bounds__(256, 2)
void quant_mma_kernel(const float* __restrict__ cb,
                      float* __restrict__ out_idx, float* __restrict__ out_hard) {
    extern __shared__ unsigned char smem[];
    const uint32_t sb  = smem_u32(smem);
    const uint32_t ZB  = sb;
    const uint32_t CBB = sb + Q_ZBYTES;

    const int t = threadIdx.x, lane = t & 31, w = t >> 5;
    const int warpM = w & 1, warpN = w >> 1;
    const int rowBase = blockIdx.x * 64;

    // stage z_hi tile (64 rows, full K=256)
#pragma unroll
    for (int q = 0; q < 8; q++) {
        int i = t + 256 * q;
        int r = i >> 5, cc = i & 31;
        cp16(ZB + r * 528 + cc * 16, g_z_hi + (size_t)(rowBase + r) * CD + cc * 8);
    }
    q_load_cb_hi(CBB, 0, 0, 0, t);
    CP_COMMIT();

    float acc[2][8][4];
#pragma unroll
    for (int mt = 0; mt < 2; mt++)
#pragma unroll
        for (int nt = 0; nt < 8; nt++)
#pragma unroll
            for (int c = 0; c < 4; c++) acc[mt][nt][c] = 0.0f;

    float best[4], sec[4];
    int   bidx[4];
#pragma unroll
    for (int s = 0; s < 4; s++) { best[s] = -3.0e38f; sec[s] = -3.0e38f; bidx[s] = 1; }

    const uint32_t a_row  = warpM * 32 + (lane & 15);
    const uint32_t a_col8 = (lane >> 4) * 8;
    const uint32_t b_row  = warpN * 64 + (lane & 7);
    const uint32_t b_col8 = ((lane >> 3) & 1) * 8;

    for (int it = 0; it < 64; it++) {
        const int tile = it >> 2, kc = it & 3, buf = it & 1;
        if (it + 1 < 64) { q_load_cb_hi(CBB, (it + 1) & 1, (it + 1) >> 2, (it + 1) & 3, t); CP_COMMIT(); CP_WAIT(1); }
        else             { CP_WAIT(0); }
        __syncthreads();

#pragma unroll
        for (int ks = 0; ks < 4; ks++) {
            const int k = kc * 64 + ks * 16;
            uint32_t bh[8][2];
#pragma unroll
            for (int nt = 0; nt < 8; nt++) {
                uint32_t baddr = CBB + buf * Q_CBSTRIDE + ((b_row + nt * 8) * 72 + ks * 16 + b_col8) * 2;
                LDSM2(bh[nt][0], bh[nt][1], baddr);
            }
#pragma unroll
            for (int mt = 0; mt < 2; mt++) {
                uint32_t ah[4];
                uint32_t aaddr = ZB + ((a_row + mt * 16) * 264 + k + a_col8) * 2;
                LDSM4(ah[0], ah[1], ah[2], ah[3], aaddr);
#pragma unroll
                for (int nt = 0; nt < 8; nt++)
                    MMA16816(acc[mt][nt], ah, bh[nt]);
            }
        }
        __syncthreads();

        if (kc == 3) {
            const int codeTile = 1 + tile * 256 + warpN * 64;
#pragma unroll
            for (int nt = 0; nt < 8; nt++) {
                int c0 = codeTile + nt * 8 + (lane & 3) * 2;
                float hn0 = (c0 < NC)     ? __ldg(&g_half_norm[c0])     : 0.0f;
                float hn1 = (c0 + 1 < NC) ? __ldg(&g_half_norm[c0 + 1]) : 0.0f;
#pragma unroll
                for (int mt = 0; mt < 2; mt++) {
#pragma unroll
                    for (int h = 0; h < 2; h++) {
                        int s = mt * 2 + h;
                        if (c0 < NC) {
                            float v = acc[mt][nt][h * 2] - hn0;
                            if (v > best[s])      { sec[s] = best[s]; best[s] = v; bidx[s] = c0; }
                            else if (v > sec[s])  { sec[s] = v; }
                        }
                        if (c0 + 1 < NC) {
                            float v = acc[mt][nt][h * 2 + 1] - hn1;
                            if (v > best[s])      { sec[s] = best[s]; best[s] = v; bidx[s] = c0 + 1; }
                            else if (v > sec[s])  { sec[s] = v; }
                        }
                    }
                    acc[mt][nt][0] = 0.0f; acc[mt][nt][1] = 0.0f;
                    acc[mt][nt][2] = 0.0f; acc[mt][nt][3] = 0.0f;
                }
            }
        }
    }

    float* red_val = (float*)(smem + Q_ZBYTES);
    float* red_sec = (float*)(smem + Q_ZBYTES + 1024);
    int*   red_idx = (int*)(smem + Q_ZBYTES + 2048);
    int*   row_idx = (int*)(smem + Q_ZBYTES + 3072);

#pragma unroll
    for (int slot = 0; slot < 4; slot++) {
        float b1 = best[slot], b2 = sec[slot]; int i1 = bidx[slot];
#pragma unroll
        for (int off = 1; off <= 2; off <<= 1) {
            float ob1 = __shfl_xor_sync(0xFFFFFFFFu, b1, off);
            int   oi1 = __shfl_xor_sync(0xFFFFFFFFu, i1, off);
            float ob2 = __shfl_xor_sync(0xFFFFFFFFu, b2, off);
            top2_merge(b1, i1, b2, ob1, oi1, ob2);
        }
        if ((lane & 3) == 0) {
            int mt = slot >> 1, h = slot & 1;
            int row = warpM * 32 + mt * 16 + (lane >> 2) + h * 8;
            red_val[row * 4 + warpN] = b1;
            red_sec[row * 4 + warpN] = b2;
            red_idx[row * 4 + warpN] = i1;
        }
    }
    __syncthreads();

    if (t < 64) {
        float b1 = red_val[t * 4], b2 = red_sec[t * 4];
        int i1 = red_idx[t * 4];
#pragma unroll
        for (int q = 1; q < 4; q++)
            top2_merge(b1, i1, b2, red_val[t * 4 + q], red_idx[t * 4 + q], red_sec[t * 4 + q]);
        row_idx[t] = i1;
        out_idx[rowBase + t] = (float)i1;
        if (b1 - b2 <= FLAG_THRESH) {
            int pos = atomicAdd(&g_flag_count, 1);
            g_flag_list[pos] = rowBase + t;
        }
    }
    __syncthreads();

    for (int r = 0; r < 64; r++) {
        int code = row_idx[r];
        out_hard[(size_t)(rowBase + r) * CD + t] = __ldg(&cb[(size_t)code * CD + t]);
    }
}

// ---------------------------------------------------------------------------
// Fixup (mma, 3-pass): code-split, merged via atomicMax — unchanged (proven).
// ---------------------------------------------------------------------------
#define F_ZBYTES  (2 * 128 * 264 * 2)
#define F_CBBYTES (4 * 18432)
#define F_SMEM    (F_ZBYTES + F_CBBYTES)

__device__ __forceinline__ void f_load_cb(uint32_t CBB, int buf, int tt, int kc, int t) {
#pragma unroll
    for (int q = 0; q < 8; q++) {
        int i = t + 256 * q;
        int hl = i >> 10, r = (i >> 3) & 127, cc = i & 7;
        int code = 1 + tt * 128 + r;
        if (code > NC - 1) code = NC - 1;
        const unsigned short* src = (hl ? g_cb_lo : g_cb_hi)
            + (size_t)code * CD + kc * 64 + cc * 8;
        cp16(CBB + (buf * 2 + hl) * 18432 + r * 144 + cc * 16, src);
    }
}

__global__ __launch_bounds__(256, 1)
void fixup_mma_kernel(float* __restrict__ out_idx) {
    __shared__ int s_tok[128];
    extern __shared__ unsigned char smem[];
    const uint32_t sb  = smem_u32(smem);
    const uint32_t ZB  = sb;
    const uint32_t CBB = sb + F_ZBYTES;

    const int t = threadIdx.x, lane = t & 31, w = t >> 5;
    const int warpM = w & 1, warpN = w >> 1;
    const int count = g_flag_count;
    const int tileTok = blockIdx.x >> 3;
    const int split   = blockIdx.x & 7;
    const int base    = tileTok * 128;
    if (base >= count) return;

    if (t < 128) {
        int idx = base + t;
        if (idx > count - 1) idx = count - 1;
        s_tok[t] = g_flag_list[idx];
    }
    __syncthreads();

#pragma unroll
    for (int q = 0; q < 32; q++) {
        int i = t + 256 * q;
        int hl = i >> 12, r = (i >> 5) & 127, cc = i & 31;
        const unsigned short* src = (hl ? g_z_lo : g_z_hi)
            + (size_t)s_tok[r] * CD + cc * 8;
        cp16(ZB + hl * 67584 + r * 528 + cc * 16, src);
    }
    f_load_cb(CBB, 0, split * 4, 0, t);
    CP_COMMIT();

    float acc[4][4][4];
#pragma unroll
    for (int mt = 0; mt < 4; mt++)
#pragma unroll
        for (int nt = 0; nt < 4; nt++)
#pragma unroll
            for (int c = 0; c < 4; c++) acc[mt][nt][c] = 0.0f;

    float best[8];
    int   bidx[8];
#pragma unroll
    for (int s = 0; s < 8; s++) { best[s] = -3.0e38f; bidx[s] = 1; }

    const uint32_t a_row  = warpM * 64 + (lane & 15);
    const uint32_t a_col8 = (lane >> 4) * 8;
    const uint32_t b_row  = warpN * 32 + (lane & 7);
    const uint32_t b_col8 = ((lane >> 3) & 1) * 8;

    for (int it = 0; it < 16; it++) {
        const int tt = split * 4 + (it >> 2), kc = it & 3, buf = it & 1;
        if (it + 1 < 16) { f_load_cb(CBB, (it + 1) & 1, split * 4 + ((it + 1) >> 2), (it + 1) & 3, t); CP_COMMIT(); CP_WAIT(1); }
        else             { CP_WAIT(0); }
        __syncthreads();

#pragma unroll
        for (int ks = 0; ks < 4; ks++) {
            const int k = kc * 64 + ks * 16;
            uint32_t bh[4][2], bl[4][2];
#pragma unroll
            for (int nt = 0; nt < 4; nt++) {
                uint32_t baddr = CBB + (buf * 2) * 18432 + ((b_row + nt * 8) * 72 + ks * 16 + b_col8) * 2;
                LDSM2(bh[nt][0], bh[nt][1], baddr);
                LDSM2(bl[nt][0], bl[nt][1], baddr + 18432);
            }
#pragma unroll
            for (int mt = 0; mt < 4; mt++) {
                uint32_t ah[4], al[4];
                uint32_t aaddr = ZB + ((a_row + mt * 16) * 264 + k + a_col8) * 2;
                LDSM4(ah[0], ah[1], ah[2], ah[3], aaddr);
                LDSM4(al[0], al[1], al[2], al[3], aaddr + 67584);
#pragma unroll
                for (int nt = 0; nt < 4; nt++) {
                    MMA16816(acc[mt][nt], ah, bh[nt]);
                    MMA16816(acc[mt][nt], ah, bl[nt]);
                    MMA16816(acc[mt][nt], al, bh[nt]);
                }
            }
        }
        __syncthreads();

        if (kc == 3) {
            const int codeTile = 1 + tt * 128 + warpN * 32;
#pragma unroll
            for (int nt = 0; nt < 4; nt++) {
                int c0 = codeTile + nt * 8 + (lane & 3) * 2;
                float hn0 = (c0 < NC)     ? __ldg(&g_half_norm[c0])     : 0.0f;
                float hn1 = (c0 + 1 < NC) ? __ldg(&g_half_norm[c0 + 1]) : 0.0f;
#pragma unroll
                for (int mt = 0; mt < 4; mt++) {
                    if (c0 < NC) {
                        float s0 = acc[mt][nt][0] - hn0;
                        if (s0 > best[mt * 2])     { best[mt * 2] = s0;     bidx[mt * 2] = c0; }
                        float s2 = acc[mt][nt][2] - hn0;
                        if (s2 > best[mt * 2 + 1]) { best[mt * 2 + 1] = s2; bidx[mt * 2 + 1] = c0; }
                    }
                    if (c0 + 1 < NC) {
                        float s1 = acc[mt][nt][1] - hn1;
                        if (s1 > best[mt * 2])     { best[mt * 2] = s1;     bidx[mt * 2] = c0 + 1; }
                        float s3 = acc[mt][nt][3] - hn1;
                        if (s3 > best[mt * 2 + 1]) { best[mt * 2 + 1] = s3; bidx[mt * 2 + 1] = c0 + 1; }
                    }
                    acc[mt][nt][0] = 0.0f; acc[mt][nt][1] = 0.0f;
                    acc[mt][nt][2] = 0.0f; acc[mt][nt][3] = 0.0f;
                }
            }
        }
    }

    float* red_val = (float*)(smem + F_ZBYTES);
    int*   red_idx = (int*)(smem + F_ZBYTES + 2048);

#pragma unroll
    for (int slot = 0; slot < 8; slot++) {
        float v = best[slot]; int ix = bidx[slot];
#pragma unroll
        for (int off = 1; off <= 2; off <<= 1) {
            float ov = __shfl_xor_sync(0xFFFFFFFFu, v, off);
            int   oi = __shfl_xor_sync(0xFFFFFFFFu, ix, off);
            if (ov > v || (ov == v && oi < ix)) { v = ov; ix = oi; }
        }
        if ((lane & 3) == 0) {
            int mt = slot >> 1, h = slot & 1;
            int row = warpM * 64 + mt * 16 + (lane >> 2) + h * 8;
            red_val[row * 4 + warpN] = v;
            red_idx[row * 4 + warpN] = ix;
        }
    }
    __syncthreads();

    if (t < 128) {
        float bv = red_val[t * 4]; int bi = red_idx[t * 4];
#pragma unroll
        for (int q = 1; q < 4; q++) {
            float v = red_val[t * 4 + q]; int ix = red_idx[t * 4 + q];
            if (v > bv || (v == bv && ix < bi)) { bv = v; bi = ix; }
        }
        unsigned long long pack =
            ((unsigned long long)fkey(bv) << 32) | (unsigned long long)(0xFFFFFFFFu - (uint32_t)bi);
        atomicMax(&g_merge[s_tok[t]], pack);
    }
}

// ---------------------------------------------------------------------------
// Apply: write out_idx / out_hard for flagged tokens from g_merge.
// ---------------------------------------------------------------------------
__global__ __launch_bounds__(256)
void apply_kernel(const float* __restrict__ cb,
                  float* __restrict__ out_idx, float* __restrict__ out_hard) {
    __shared__ int s_tok[128];
    __shared__ int s_code[128];
    const int t = threadIdx.x;
    const int count = g_flag_count;
    const int base = blockIdx.x * 128;
    if (base >= count) return;

    if (t < 128) {
        int idx = base + t;
        if (idx > count - 1) idx = count - 1;
        int token = g_flag_list[idx];
        unsigned long long m = g_merge[token];
        int code = (int)(0xFFFFFFFFu - (uint32_t)(m & 0xFFFFFFFFull));
        s_tok[t] = token;
        s_code[t] = code;
        out_idx[token] = (float)code;
    }
    __syncthreads();

    for (int r = 0; r < 128; r++) {
        int code  = s_code[r];
        int token = s_tok[r];
        out_hard[(size_t)token * CD + t] = __ldg(&cb[(size_t)code * CD + t]);
    }
}

// ---------------------------------------------------------------------------
// Launch
// ---------------------------------------------------------------------------
extern "C" void kernel_launch(void* const* d_in, const int* in_sizes, int n_in,
                              void* d_out, int out_size) {
    const float* x  = (const float*)d_in[0];   // [32768, 1024]
    const float* cb = (const float*)d_in[1];   // [4096, 256]
    const float* W  = (const float*)d_in[2];   // [1024, 256]
    const float* b  = (const float*)d_in[3];   // [256]

    float* out   = (float*)d_out;
    float* z     = out;                              // [32768, 256]
    float* oidx  = out + (size_t)M_TOK * CD;         // [32768]
    float* ohard = oidx + M_TOK;                     // [32768, 256]

    cudaFuncSetAttribute(gemm1_mma_kernel, cudaFuncAttributeMaxDynamicSharedMemorySize, G1_SMEM);
    cudaFuncSetAttribute(quant_mma_kernel, cudaFuncAttributeMaxDynamicSharedMemorySize, Q_SMEM);
    cudaFuncSetAttribute(fixup_mma_kernel, cudaFuncAttributeMaxDynamicSharedMemorySize, F_SMEM);

    conv_x_kernel<<<(int)((size_t)M_TOK * DMODEL / 4 / 256), 256>>>(x);
    conv_w_kernel<<<(CD * DMODEL) / 256, 256>>>(W);
    cb_prep_kernel<<<NC / 8, 256>>>(cb);

    gemm1_mma_kernel<<<dim3(M_TOK / 64, CD / 128), 256, G1_SMEM>>>(b, z);
    normalize_kernel<<<M_TOK / 8, 256>>>(z);

    quant_mma_kernel<<<M_TOK / 64, 256, Q_SMEM>>>(cb, oidx, ohard);
    fixup_mma_kernel<<<(M_TOK / 128) * 8, 256, F_SMEM>>>(oidx);
    apply_kernel<<<M_TOK / 128, 256>>>(cb, oidx, ohard);
}

// round 15
// speedup vs baseline: 6.6758x; 1.0690x over previous
#include <cuda_runtime.h>
#include <cuda_bf16.h>
#include <math.h>
#include <stdint.h>

#define M_TOK 32768
#define DMODEL 1024
#define CD 256
#define NC 4096

#define FLAG_THRESH 1.5e-3f

// ---------------------------------------------------------------------------
// Static device scratch
// ---------------------------------------------------------------------------
__device__ float g_half_norm[NC];
__device__ unsigned short g_x_hi[(size_t)M_TOK * DMODEL];
__device__ unsigned short g_x_lo[(size_t)M_TOK * DMODEL];
__device__ unsigned short g_w_hi[(size_t)CD * DMODEL];   // transposed [n][k]
__device__ unsigned short g_w_lo[(size_t)CD * DMODEL];
__device__ unsigned short g_z_hi[(size_t)M_TOK * CD];
__device__ unsigned short g_z_lo[(size_t)M_TOK * CD];
__device__ unsigned short g_cb_hi[(size_t)NC * CD];
__device__ unsigned short g_cb_lo[(size_t)NC * CD];
__device__ int g_flag_count;
__device__ int g_flag_list[M_TOK];
__device__ unsigned long long g_merge[M_TOK];   // packed (score_key, ~code)

// ---------------------------------------------------------------------------
// PTX helpers
// ---------------------------------------------------------------------------
__device__ __forceinline__ uint32_t smem_u32(const void* p) {
    uint32_t a;
    asm("{ .reg .u64 t; cvta.to.shared.u64 t, %1; cvt.u32.u64 %0, t; }" : "=r"(a) : "l"(p));
    return a;
}
__device__ __forceinline__ void cp16(uint32_t dst, const void* src) {
    asm volatile("cp.async.cg.shared.global [%0], [%1], 16;" :: "r"(dst), "l"(src));
}
#define CP_COMMIT() asm volatile("cp.async.commit_group;" ::: "memory")
#define CP_WAIT(n)  asm volatile("cp.async.wait_group %0;" :: "n"(n) : "memory")

#define LDSM4(r0, r1, r2, r3, addr) \
    asm volatile("ldmatrix.sync.aligned.m8n8.x4.shared.b16 {%0,%1,%2,%3}, [%4];" \
                 : "=r"(r0), "=r"(r1), "=r"(r2), "=r"(r3) : "r"(addr))
#define LDSM2(r0, r1, addr) \
    asm volatile("ldmatrix.sync.aligned.m8n8.x2.shared.b16 {%0,%1}, [%2];" \
                 : "=r"(r0), "=r"(r1) : "r"(addr))

#define MMA16816(c, a, b) \
    asm volatile("mma.sync.aligned.m16n8k16.row.col.f32.bf16.bf16.f32 " \
                 "{%0,%1,%2,%3}, {%4,%5,%6,%7}, {%8,%9}, {%0,%1,%2,%3};" \
                 : "+f"((c)[0]), "+f"((c)[1]), "+f"((c)[2]), "+f"((c)[3]) \
                 : "r"((a)[0]), "r"((a)[1]), "r"((a)[2]), "r"((a)[3]), \
                   "r"((b)[0]), "r"((b)[1]))

// monotone float -> u32 key (order-preserving)
__device__ __forceinline__ uint32_t fkey(float f) {
    uint32_t u = __float_as_uint(f);
    return (u & 0x80000000u) ? ~u : (u | 0x80000000u);
}

// ---------------------------------------------------------------------------
// hi/lo bf16 split helpers
// ---------------------------------------------------------------------------
__device__ __forceinline__ void split4(float4 v, uint2& hi, uint2& lo) {
    float f[4] = {v.x, v.y, v.z, v.w};
    unsigned short h[4], l[4];
#pragma unroll
    for (int i = 0; i < 4; i++) {
        __nv_bfloat16 hb = __float2bfloat16(f[i]);
        h[i] = __bfloat16_as_ushort(hb);
        l[i] = __bfloat16_as_ushort(__float2bfloat16(f[i] - __bfloat162float(hb)));
    }
    hi.x = (uint32_t)h[0] | ((uint32_t)h[1] << 16);
    hi.y = (uint32_t)h[2] | ((uint32_t)h[3] << 16);
    lo.x = (uint32_t)l[0] | ((uint32_t)l[1] << 16);
    lo.y = (uint32_t)l[2] | ((uint32_t)l[3] << 16);
}

// ---------------------------------------------------------------------------
// Prep kernels
// ---------------------------------------------------------------------------
__global__ __launch_bounds__(256)
void conv_x_kernel(const float* __restrict__ x) {
    if (blockIdx.x == 0 && threadIdx.x == 0) g_flag_count = 0;   // fused reset
    size_t gid = (size_t)blockIdx.x * 256 + threadIdx.x;
    float4 v = *(const float4*)&x[gid * 4];
    uint2 hi, lo; split4(v, hi, lo);
    *(uint2*)&g_x_hi[gid * 4] = hi;
    *(uint2*)&g_x_lo[gid * 4] = lo;
}

__global__ __launch_bounds__(256)
void conv_w_kernel(const float* __restrict__ W) {
    size_t gid = (size_t)blockIdx.x * 256 + threadIdx.x;
    int n = (int)(gid >> 10);
    int k = (int)(gid & 1023);
    float v = W[(size_t)k * CD + n];
    __nv_bfloat16 hb = __float2bfloat16(v);
    g_w_hi[gid] = __bfloat16_as_ushort(hb);
    g_w_lo[gid] = __bfloat16_as_ushort(__float2bfloat16(v - __bfloat162float(hb)));
}

// conv_cb + halfnorm fused: one warp per code, single cb read.
__global__ __launch_bounds__(256)
void cb_prep_kernel(const float* __restrict__ cb) {
    const int warp = threadIdx.x >> 5;
    const int lane = threadIdx.x & 31;
    const int code = blockIdx.x * 8 + warp;
    const float4* c4 = (const float4*)cb;
    size_t base = (size_t)code * 64;
    float4 v0 = c4[base + lane];
    float4 v1 = c4[base + 32 + lane];

    float s = v0.x*v0.x + v0.y*v0.y + v0.z*v0.z + v0.w*v0.w
            + v1.x*v1.x + v1.y*v1.y + v1.z*v1.z + v1.w*v1.w;
#pragma unroll
    for (int o = 16; o > 0; o >>= 1) s += __shfl_xor_sync(0xFFFFFFFFu, s, o);
    if (lane == 0) g_half_norm[code] = 0.5f * s;

    uint2 h0, l0, h1, l1;
    split4(v0, h0, l0);
    split4(v1, h1, l1);
    size_t kb = (size_t)code * CD + lane * 4;
    *(uint2*)&g_cb_hi[kb]       = h0;
    *(uint2*)&g_cb_lo[kb]       = l0;
    *(uint2*)&g_cb_hi[kb + 128] = h1;
    *(uint2*)&g_cb_lo[kb + 128] = l1;
}

// normalize + hi/lo conversion fused
__global__ __launch_bounds__(256)
void normalize_kernel(float* __restrict__ z) {
    const int warp = threadIdx.x >> 5;
    const int lane = threadIdx.x & 31;
    const int row  = blockIdx.x * 8 + warp;
    float4* z4 = (float4*)z;
    size_t base = (size_t)row * 64;
    float4 v0 = z4[base + lane];
    float4 v1 = z4[base + 32 + lane];
    float s = v0.x*v0.x + v0.y*v0.y + v0.z*v0.z + v0.w*v0.w
            + v1.x*v1.x + v1.y*v1.y + v1.z*v1.z + v1.w*v1.w;
#pragma unroll
    for (int o = 16; o > 0; o >>= 1) s += __shfl_xor_sync(0xFFFFFFFFu, s, o);
    float inv = 1.0f / (sqrtf(s) + 1e-6f);
    v0.x *= inv; v0.y *= inv; v0.z *= inv; v0.w *= inv;
    v1.x *= inv; v1.y *= inv; v1.z *= inv; v1.w *= inv;
    z4[base + lane]      = v0;
    z4[base + 32 + lane] = v1;

    uint2 h0, l0, h1, l1;
    split4(v0, h0, l0);
    split4(v1, h1, l1);
    size_t kb = (size_t)row * CD + lane * 4;
    *(uint2*)&g_z_hi[kb]       = h0;
    *(uint2*)&g_z_lo[kb]       = l0;
    *(uint2*)&g_z_hi[kb + 128] = h1;
    *(uint2*)&g_z_lo[kb + 128] = l1;
}

// ---------------------------------------------------------------------------
// GEMM1 v2 (mma.sync, 3-pass): BM=64, BN=128, 2 CTAs/SM — unchanged (proven)
// ---------------------------------------------------------------------------
#define G1_XSTRIDE 9216
#define G1_WSTRIDE 18432
#define G1_SMEM (4 * G1_XSTRIDE + 4 * G1_WSTRIDE)   // 110592

__device__ __forceinline__ void g1_load(uint32_t XS, uint32_t WS, int buf, int kc,
                                        int rowBase, int colBase, int t) {
#pragma unroll
    for (int q = 0; q < 4; q++) {
        int i = t + 256 * q;
        int hl = i >> 9, rem = i & 511;
        int r = rem >> 3, cc = rem & 7;
        const unsigned short* src = (hl ? g_x_lo : g_x_hi)
            + (size_t)(rowBase + r) * DMODEL + kc * 64 + cc * 8;
        cp16(XS + (buf * 2 + hl) * G1_XSTRIDE + r * 144 + cc * 16, src);
    }
#pragma unroll
    for (int q = 0; q < 8; q++) {
        int i = t + 256 * q;
        int hl = i >> 10, rem = i & 1023;
        int r = rem >> 3, cc = rem & 7;
        const unsigned short* src = (hl ? g_w_lo : g_w_hi)
            + (size_t)(colBase + r) * DMODEL + kc * 64 + cc * 8;
        cp16(WS + (buf * 2 + hl) * G1_WSTRIDE + r * 144 + cc * 16, src);
    }
}

__global__ __launch_bounds__(256, 2)
void gemm1_mma_kernel(const float* __restrict__ bias, float* __restrict__ z) {
    extern __shared__ unsigned char smem[];
    const uint32_t sb = smem_u32(smem);
    const uint32_t XS = sb;
    const uint32_t WS = sb + 4 * G1_XSTRIDE;

    const int t = threadIdx.x, lane = t & 31, w = t >> 5;
    const int warpM = w & 1, warpN = w >> 1;
    const int rowBase = blockIdx.x * 64;
    const int colBase = blockIdx.y * 128;

    float acc[2][4][4];
#pragma unroll
    for (int mt = 0; mt < 2; mt++)
#pragma unroll
        for (int nt = 0; nt < 4; nt++)
#pragma unroll
            for (int c = 0; c < 4; c++) acc[mt][nt][c] = 0.0f;

    const uint32_t a_row  = warpM * 32 + (lane & 15);
    const uint32_t a_col8 = (lane >> 4) * 8;
    const uint32_t b_row  = warpN * 32 + (lane & 7);
    const uint32_t b_col8 = ((lane >> 3) & 1) * 8;

    g1_load(XS, WS, 0, 0, rowBase, colBase, t);
    CP_COMMIT();

    for (int kc = 0; kc < 16; kc++) {
        const int buf = kc & 1;
        if (kc + 1 < 16) { g1_load(XS, WS, (kc + 1) & 1, kc + 1, rowBase, colBase, t); CP_COMMIT(); CP_WAIT(1); }
        else             { CP_WAIT(0); }
        __syncthreads();

#pragma unroll
        for (int ks = 0; ks < 4; ks++) {
            uint32_t bh[4][2], bl[4][2];
#pragma unroll
            for (int nt = 0; nt < 4; nt++) {
                uint32_t baddr = WS + (buf * 2) * G1_WSTRIDE + ((b_row + nt * 8) * 72 + ks * 16 + b_col8) * 2;
                LDSM2(bh[nt][0], bh[nt][1], baddr);
                LDSM2(bl[nt][0], bl[nt][1], baddr + G1_WSTRIDE);
            }
#pragma unroll
            for (int mt = 0; mt < 2; mt++) {
                uint32_t ah[4], al[4];
                uint32_t aaddr = XS + (buf * 2) * G1_XSTRIDE + ((a_row + mt * 16) * 72 + ks * 16 + a_col8) * 2;
                LDSM4(ah[0], ah[1], ah[2], ah[3], aaddr);
                LDSM4(al[0], al[1], al[2], al[3], aaddr + G1_XSTRIDE);
#pragma unroll
                for (int nt = 0; nt < 4; nt++) {
                    MMA16816(acc[mt][nt], ah, bh[nt]);
                    MMA16816(acc[mt][nt], ah, bl[nt]);
                    MMA16816(acc[mt][nt], al, bh[nt]);
                }
            }
        }
        __syncthreads();
    }

    const int row0 = rowBase + warpM * 32 + (lane >> 2);
    const int col0 = colBase + warpN * 32 + (lane & 3) * 2;
#pragma unroll
    for (int mt = 0; mt < 2; mt++) {
#pragma unroll
        for (int nt = 0; nt < 4; nt++) {
            int r0 = row0 + mt * 16;
            int c  = col0 + nt * 8;
            float b0 = __ldg(&bias[c]), b1 = __ldg(&bias[c + 1]);
            *(float2*)&z[(size_t)r0 * CD + c]       = make_float2(acc[mt][nt][0] + b0, acc[mt][nt][1] + b1);
            *(float2*)&z[(size_t)(r0 + 8) * CD + c] = make_float2(acc[mt][nt][2] + b0, acc[mt][nt][3] + b1);
        }
    }
}

// ---------------------------------------------------------------------------
// Quant v4: 128 tokens per CTA (two 64-row z sub-tiles), 8 warps =
// 2 z-groups x (2M x 2N); warp tile 32x64 (nt=8). cb tile read ONCE per
// 128 tokens -> half the L2 traffic of v3. Grid 256 = one wave @ 2 CTAs/SM.
// smem: z 128*528 = 67584 ; cb 2*18432 = 36864 ; total 104448.
// ---------------------------------------------------------------------------
#define Q_ZBYTES   (128 * 528)           // 67584
#define Q_CBSTRIDE 18432                 // 128 codes * 144B
#define Q_SMEM     (Q_ZBYTES + 2 * Q_CBSTRIDE)   // 104448

__device__ __forceinline__ void top2_merge(float& b1, int& i1, float& b2,
                                           float ob1, int oi1, float ob2) {
    if (ob1 > b1)      { b2 = fmaxf(b1, ob2); b1 = ob1; i1 = oi1; }
    else if (ob1 == b1){ if (oi1 != i1) b2 = b1; else b2 = fmaxf(b2, ob2); i1 = min(i1, oi1); }
    else               { b2 = fmaxf(b2, ob1); }
}

__device__ __forceinline__ void q_load_cb_hi(uint32_t CBB, int buf, int tile, int kc, int t) {
#pragma unroll
    for (int q = 0; q < 4; q++) {
        int i = t + 256 * q;               // 0..1023
        int r = i >> 3, cc = i & 7;        // r: 0..127
        int code = 1 + tile * 128 + r;
        if (code > NC - 1) code = NC - 1;
        cp16(CBB + buf * Q_CBSTRIDE + r * 144 + cc * 16,
             g_cb_hi + (size_t)code * CD + kc * 64 + cc * 8);
    }
}

__global__ __launch_bounds__(256, 2)
void quant_mma_kernel(const float* __restrict__ cb,
                      float* __restrict__ out_idx, float* __restrict__ out_hard) {
    extern __shared__ unsigned char smem[];
    const uint32_t sb  = smem_u32(smem);
    const uint32_t ZB  = sb;
    const uint32_t CBB = sb + Q_ZBYTES;

    const int t = threadIdx.x, lane = t & 31, w = t >> 5;
    const int zt    = w >> 2;          // z sub-tile 0/1 (tokens 0-63 / 64-127)
    const int wsub  = w & 3;
    const int warpM = wsub & 1;        // 2 M-tiles of 32 within 64 tokens
    const int warpN = wsub >> 1;       // 2 N-tiles of 64 within 128 codes
    const int rowBase = blockIdx.x * 128;

    // stage z_hi tile (128 rows, full K=256): 4096 cp16 / 256 threads
#pragma unroll
    for (int q = 0; q < 16; q++) {
        int i = t + 256 * q;
        int r = i >> 5, cc = i & 31;
        cp16(ZB + r * 528 + cc * 16, g_z_hi + (size_t)(rowBase + r) * CD + cc * 8);
    }
    q_load_cb_hi(CBB, 0, 0, 0, t);
    CP_COMMIT();

    float acc[2][8][4];
#pragma unroll
    for (int mt = 0; mt < 2; mt++)
#pragma unroll
        for (int nt = 0; nt < 8; nt++)
#pragma unroll
            for (int c = 0; c < 4; c++) acc[mt][nt][c] = 0.0f;

    float best[4], sec[4];
    int   bidx[4];
#pragma unroll
    for (int s = 0; s < 4; s++) { best[s] = -3.0e38f; sec[s] = -3.0e38f; bidx[s] = 1; }

    const uint32_t a_row  = (uint32_t)(zt * 64 + warpM * 32 + (lane & 15));
    const uint32_t a_col8 = (lane >> 4) * 8;
    const uint32_t b_row  = (uint32_t)(warpN * 64 + (lane & 7));
    const uint32_t b_col8 = ((lane >> 3) & 1) * 8;

    for (int it = 0; it < 128; it++) {
        const int tile = it >> 2, kc = it & 3, buf = it & 1;
        if (it + 1 < 128) { q_load_cb_hi(CBB, (it + 1) & 1, (it + 1) >> 2, (it + 1) & 3, t); CP_COMMIT(); CP_WAIT(1); }
        else              { CP_WAIT(0); }
        __syncthreads();

#pragma unroll
        for (int ks = 0; ks < 4; ks++) {
            const int k = kc * 64 + ks * 16;
            uint32_t bh[8][2];
#pragma unroll
            for (int nt = 0; nt < 8; nt++) {
                uint32_t baddr = CBB + buf * Q_CBSTRIDE + ((b_row + nt * 8) * 72 + ks * 16 + b_col8) * 2;
                LDSM2(bh[nt][0], bh[nt][1], baddr);
            }
#pragma unroll
            for (int mt = 0; mt < 2; mt++) {
                uint32_t ah[4];
                uint32_t aaddr = ZB + ((a_row + mt * 16) * 264 + k + a_col8) * 2;
                LDSM4(ah[0], ah[1], ah[2], ah[3], aaddr);
#pragma unroll
                for (int nt = 0; nt < 8; nt++)
                    MMA16816(acc[mt][nt], ah, bh[nt]);
            }
        }
        __syncthreads();

        if (kc == 3) {
            const int codeTile = 1 + tile * 128 + warpN * 64;
#pragma unroll
            for (int nt = 0; nt < 8; nt++) {
                int c0 = codeTile + nt * 8 + (lane & 3) * 2;
                float hn0 = (c0 < NC)     ? __ldg(&g_half_norm[c0])     : 0.0f;
                float hn1 = (c0 + 1 < NC) ? __ldg(&g_half_norm[c0 + 1]) : 0.0f;
#pragma unroll
                for (int mt = 0; mt < 2; mt++) {
#pragma unroll
                    for (int h = 0; h < 2; h++) {
                        int s = mt * 2 + h;
                        if (c0 < NC) {
                            float v = acc[mt][nt][h * 2] - hn0;
                            if (v > best[s])      { sec[s] = best[s]; best[s] = v; bidx[s] = c0; }
                            else if (v > sec[s])  { sec[s] = v; }
                        }
                        if (c0 + 1 < NC) {
                            float v = acc[mt][nt][h * 2 + 1] - hn1;
                            if (v > best[s])      { sec[s] = best[s]; best[s] = v; bidx[s] = c0 + 1; }
                            else if (v > sec[s])  { sec[s] = v; }
                        }
                    }
                    acc[mt][nt][0] = 0.0f; acc[mt][nt][1] = 0.0f;
                    acc[mt][nt][2] = 0.0f; acc[mt][nt][3] = 0.0f;
                }
            }
        }
    }

    // reduce: 4 lanes (lane&3) share each row-slot, then 2 warpN columns
    float* red_val = (float*)(smem + Q_ZBYTES);            // [128][2]
    float* red_sec = (float*)(smem + Q_ZBYTES + 1024);
    int*   red_idx = (int*)(smem + Q_ZBYTES + 2048);
    int*   row_idx = (int*)(smem + Q_ZBYTES + 3072);

#pragma unroll
    for (int slot = 0; slot < 4; slot++) {
        float b1 = best[slot], b2 = sec[slot]; int i1 = bidx[slot];
#pragma unroll
        for (int off = 1; off <= 2; off <<= 1) {
            float ob1 = __shfl_xor_sync(0xFFFFFFFFu, b1, off);
            int   oi1 = __shfl_xor_sync(0xFFFFFFFFu, i1, off);
            float ob2 = __shfl_xor_sync(0xFFFFFFFFu, b2, off);
            top2_merge(b1, i1, b2, ob1, oi1, ob2);
        }
        if ((lane & 3) == 0) {
            int mt = slot >> 1, h = slot & 1;
            int row = zt * 64 + warpM * 32 + mt * 16 + (lane >> 2) + h * 8;
            red_val[row * 2 + warpN] = b1;
            red_sec[row * 2 + warpN] = b2;
            red_idx[row * 2 + warpN] = i1;
        }
    }
    __syncthreads();

    if (t < 128) {
        float b1 = red_val[t * 2], b2 = red_sec[t * 2];
        int i1 = red_idx[t * 2];
        top2_merge(b1, i1, b2, red_val[t * 2 + 1], red_idx[t * 2 + 1], red_sec[t * 2 + 1]);
        row_idx[t] = i1;
        out_idx[rowBase + t] = (float)i1;
        if (b1 - b2 <= FLAG_THRESH) {
            int pos = atomicAdd(&g_flag_count, 1);
            g_flag_list[pos] = rowBase + t;
        }
    }
    __syncthreads();

    for (int r = 0; r < 128; r++) {
        int code = row_idx[r];
        out_hard[(size_t)(rowBase + r) * CD + t] = __ldg(&cb[(size_t)code * CD + t]);
    }
}

// ---------------------------------------------------------------------------
// Fixup (mma, 3-pass): code-split, merged via atomicMax — unchanged (proven).
// ---------------------------------------------------------------------------
#define F_ZBYTES  (2 * 128 * 264 * 2)
#define F_CBBYTES (4 * 18432)
#define F_SMEM    (F_ZBYTES + F_CBBYTES)

__device__ __forceinline__ void f_load_cb(uint32_t CBB, int buf, int tt, int kc, int t) {
#pragma unroll
    for (int q = 0; q < 8; q++) {
        int i = t + 256 * q;
        int hl = i >> 10, r = (i >> 3) & 127, cc = i & 7;
        int code = 1 + tt * 128 + r;
        if (code > NC - 1) code = NC - 1;
        const unsigned short* src = (hl ? g_cb_lo : g_cb_hi)
            + (size_t)code * CD + kc * 64 + cc * 8;
        cp16(CBB + (buf * 2 + hl) * 18432 + r * 144 + cc * 16, src);
    }
}

__global__ __launch_bounds__(256, 1)
void fixup_mma_kernel(float* __restrict__ out_idx) {
    __shared__ int s_tok[128];
    extern __shared__ unsigned char smem[];
    const uint32_t sb  = smem_u32(smem);
    const uint32_t ZB  = sb;
    const uint32_t CBB = sb + F_ZBYTES;

    const int t = threadIdx.x, lane = t & 31, w = t >> 5;
    const int warpM = w & 1, warpN = w >> 1;
    const int count = g_flag_count;
    const int tileTok = blockIdx.x >> 3;
    const int split   = blockIdx.x & 7;
    const int base    = tileTok * 128;
    if (base >= count) return;

    if (t < 128) {
        int idx = base + t;
        if (idx > count - 1) idx = count - 1;
        s_tok[t] = g_flag_list[idx];
    }
    __syncthreads();

#pragma unroll
    for (int q = 0; q < 32; q++) {
        int i = t + 256 * q;
        int hl = i >> 12, r = (i >> 5) & 127, cc = i & 31;
        const unsigned short* src = (hl ? g_z_lo : g_z_hi)
            + (size_t)s_tok[r] * CD + cc * 8;
        cp16(ZB + hl * 67584 + r * 528 + cc * 16, src);
    }
    f_load_cb(CBB, 0, split * 4, 0, t);
    CP_COMMIT();

    float acc[4][4][4];
#pragma unroll
    for (int mt = 0; mt < 4; mt++)
#pragma unroll
        for (int nt = 0; nt < 4; nt++)
#pragma unroll
            for (int c = 0; c < 4; c++) acc[mt][nt][c] = 0.0f;

    float best[8];
    int   bidx[8];
#pragma unroll
    for (int s = 0; s < 8; s++) { best[s] = -3.0e38f; bidx[s] = 1; }

    const uint32_t a_row  = warpM * 64 + (lane & 15);
    const uint32_t a_col8 = (lane >> 4) * 8;
    const uint32_t b_row  = warpN * 32 + (lane & 7);
    const uint32_t b_col8 = ((lane >> 3) & 1) * 8;

    for (int it = 0; it < 16; it++) {
        const int tt = split * 4 + (it >> 2), kc = it & 3, buf = it & 1;
        if (it + 1 < 16) { f_load_cb(CBB, (it + 1) & 1, split * 4 + ((it + 1) >> 2), (it + 1) & 3, t); CP_COMMIT(); CP_WAIT(1); }
        else             { CP_WAIT(0); }
        __syncthreads();

#pragma unroll
        for (int ks = 0; ks < 4; ks++) {
            const int k = kc * 64 + ks * 16;
            uint32_t bh[4][2], bl[4][2];
#pragma unroll
            for (int nt = 0; nt < 4; nt++) {
                uint32_t baddr = CBB + (buf * 2) * 18432 + ((b_row + nt * 8) * 72 + ks * 16 + b_col8) * 2;
                LDSM2(bh[nt][0], bh[nt][1], baddr);
                LDSM2(bl[nt][0], bl[nt][1], baddr + 18432);
            }
#pragma unroll
            for (int mt = 0; mt < 4; mt++) {
                uint32_t ah[4], al[4];
                uint32_t aaddr = ZB + ((a_row + mt * 16) * 264 + k + a_col8) * 2;
                LDSM4(ah[0], ah[1], ah[2], ah[3], aaddr);
                LDSM4(al[0], al[1], al[2], al[3], aaddr + 67584);
#pragma unroll
                for (int nt = 0; nt < 4; nt++) {
                    MMA16816(acc[mt][nt], ah, bh[nt]);
                    MMA16816(acc[mt][nt], ah, bl[nt]);
                    MMA16816(acc[mt][nt], al, bh[nt]);
                }
            }
        }
        __syncthreads();

        if (kc == 3) {
            const int codeTile = 1 + tt * 128 + warpN * 32;
#pragma unroll
            for (int nt = 0; nt < 4; nt++) {
                int c0 = codeTile + nt * 8 + (lane & 3) * 2;
                float hn0 = (c0 < NC)     ? __ldg(&g_half_norm[c0])     : 0.0f;
                float hn1 = (c0 + 1 < NC) ? __ldg(&g_half_norm[c0 + 1]) : 0.0f;
#pragma unroll
                for (int mt = 0; mt < 4; mt++) {
                    if (c0 < NC) {
                        float s0 = acc[mt][nt][0] - hn0;
                        if (s0 > best[mt * 2])     { best[mt * 2] = s0;     bidx[mt * 2] = c0; }
                        float s2 = acc[mt][nt][2] - hn0;
                        if (s2 > best[mt * 2 + 1]) { best[mt * 2 + 1] = s2; bidx[mt * 2 + 1] = c0; }
                    }
                    if (c0 + 1 < NC) {
                        float s1 = acc[mt][nt][1] - hn1;
                        if (s1 > best[mt * 2])     { best[mt * 2] = s1;     bidx[mt * 2] = c0 + 1; }
                        float s3 = acc[mt][nt][3] - hn1;
                        if (s3 > best[mt * 2 + 1]) { best[mt * 2 + 1] = s3; bidx[mt * 2 + 1] = c0 + 1; }
                    }
                    acc[mt][nt][0] = 0.0f; acc[mt][nt][1] = 0.0f;
                    acc[mt][nt][2] = 0.0f; acc[mt][nt][3] = 0.0f;
                }
            }
        }
    }

    float* red_val = (float*)(smem + F_ZBYTES);
    int*   red_idx = (int*)(smem + F_ZBYTES + 2048);

#pragma unroll
    for (int slot = 0; slot < 8; slot++) {
        float v = best[slot]; int ix = bidx[slot];
#pragma unroll
        for (int off = 1; off <= 2; off <<= 1) {
            float ov = __shfl_xor_sync(0xFFFFFFFFu, v, off);
            int   oi = __shfl_xor_sync(0xFFFFFFFFu, ix, off);
            if (ov > v || (ov == v && oi < ix)) { v = ov; ix = oi; }
        }
        if ((lane & 3) == 0) {
            int mt = slot >> 1, h = slot & 1;
            int row = warpM * 64 + mt * 16 + (lane >> 2) + h * 8;
            red_val[row * 4 + warpN] = v;
            red_idx[row * 4 + warpN] = ix;
        }
    }
    __syncthreads();

    if (t < 128) {
        float bv = red_val[t * 4]; int bi = red_idx[t * 4];
#pragma unroll
        for (int q = 1; q < 4; q++) {
            float v = red_val[t * 4 + q]; int ix = red_idx[t * 4 + q];
            if (v > bv || (v == bv && ix < bi)) { bv = v; bi = ix; }
        }
        unsigned long long pack =
            ((unsigned long long)fkey(bv) << 32) | (unsigned long long)(0xFFFFFFFFu - (uint32_t)bi);
        atomicMax(&g_merge[s_tok[t]], pack);
    }
}

// ---------------------------------------------------------------------------
// Apply: write out_idx / out_hard for flagged tokens from g_merge.
// ---------------------------------------------------------------------------
__global__ __launch_bounds__(256)
void apply_kernel(const float* __restrict__ cb,
                  float* __restrict__ out_idx, float* __restrict__ out_hard) {
    __shared__ int s_tok[128];
    __shared__ int s_code[128];
    const int t = threadIdx.x;
    const int count = g_flag_count;
    const int base = blockIdx.x * 128;
    if (base >= count) return;

    if (t < 128) {
        int idx = base + t;
        if (idx > count - 1) idx = count - 1;
        int token = g_flag_list[idx];
        unsigned long long m = g_merge[token];
        int code = (int)(0xFFFFFFFFu - (uint32_t)(m & 0xFFFFFFFFull));
        s_tok[t] = token;
        s_code[t] = code;
        out_idx[token] = (float)code;
    }
    __syncthreads();

    for (int r = 0; r < 128; r++) {
        int code  = s_code[r];
        int token = s_tok[r];
        out_hard[(size_t)token * CD + t] = __ldg(&cb[(size_t)code * CD + t]);
    }
}

// ---------------------------------------------------------------------------
// Launch
// ---------------------------------------------------------------------------
extern "C" void kernel_launch(void* const* d_in, const int* in_sizes, int n_in,
                              void* d_out, int out_size) {
    const float* x  = (const float*)d_in[0];   // [32768, 1024]
    const float* cb = (const float*)d_in[1];   // [4096, 256]
    const float* W  = (const float*)d_in[2];   // [1024, 256]
    const float* b  = (const float*)d_in[3];   // [256]

    float* out   = (float*)d_out;
    float* z     = out;                              // [32768, 256]
    float* oidx  = out + (size_t)M_TOK * CD;         // [32768]
    float* ohard = oidx + M_TOK;                     // [32768, 256]

    cudaFuncSetAttribute(gemm1_mma_kernel, cudaFuncAttributeMaxDynamicSharedMemorySize, G1_SMEM);
    cudaFuncSetAttribute(quant_mma_kernel, cudaFuncAttributeMaxDynamicSharedMemorySize, Q_SMEM);
    cudaFuncSetAttribute(fixup_mma_kernel, cudaFuncAttributeMaxDynamicSharedMemorySize, F_SMEM);

    conv_x_kernel<<<(int)((size_t)M_TOK * DMODEL / 4 / 256), 256>>>(x);
    conv_w_kernel<<<(CD * DMODEL) / 256, 256>>>(W);
    cb_prep_kernel<<<NC / 8, 256>>>(cb);

    gemm1_mma_kernel<<<dim3(M_TOK / 64, CD / 128), 256, G1_SMEM>>>(b, z);
    normalize_kernel<<<M_TOK / 8, 256>>>(z);

    quant_mma_kernel<<<M_TOK / 128, 256, Q_SMEM>>>(cb, oidx, ohard);
    fixup_mma_kernel<<<(M_TOK / 128) * 8, 256, F_SMEM>>>(oidx);
    apply_kernel<<<M_TOK / 128, 256>>>(cb, oidx, ohard);
}

// round 16
// speedup vs baseline: 6.8480x; 1.0258x over previous
#include <cuda_runtime.h>
#include <cuda_bf16.h>
#include <math.h>
#include <stdint.h>

#define M_TOK 32768
#define DMODEL 1024
#define CD 256
#define NC 4096

#define FLAG_THRESH 1.5e-3f

// ---------------------------------------------------------------------------
// Static device scratch
// ---------------------------------------------------------------------------
__device__ float g_half_norm[NC];
__device__ unsigned short g_w_hi[(size_t)CD * DMODEL];   // transposed [n][k]
__device__ unsigned short g_w_lo[(size_t)CD * DMODEL];
__device__ unsigned short g_z_hi[(size_t)M_TOK * CD];
__device__ unsigned short g_z_lo[(size_t)M_TOK * CD];
__device__ unsigned short g_cb_hi[(size_t)NC * CD];
__device__ unsigned short g_cb_lo[(size_t)NC * CD];
__device__ int g_flag_count;
__device__ int g_flag_list[M_TOK];
__device__ unsigned long long g_merge[M_TOK];   // packed (score_key, ~code)

// ---------------------------------------------------------------------------
// PTX helpers
// ---------------------------------------------------------------------------
__device__ __forceinline__ uint32_t smem_u32(const void* p) {
    uint32_t a;
    asm("{ .reg .u64 t; cvta.to.shared.u64 t, %1; cvt.u32.u64 %0, t; }" : "=r"(a) : "l"(p));
    return a;
}
__device__ __forceinline__ void cp16(uint32_t dst, const void* src) {
    asm volatile("cp.async.cg.shared.global [%0], [%1], 16;" :: "r"(dst), "l"(src));
}
#define CP_COMMIT() asm volatile("cp.async.commit_group;" ::: "memory")
#define CP_WAIT(n)  asm volatile("cp.async.wait_group %0;" :: "n"(n) : "memory")

#define LDSM4(r0, r1, r2, r3, addr) \
    asm volatile("ldmatrix.sync.aligned.m8n8.x4.shared.b16 {%0,%1,%2,%3}, [%4];" \
                 : "=r"(r0), "=r"(r1), "=r"(r2), "=r"(r3) : "r"(addr))
#define LDSM2(r0, r1, addr) \
    asm volatile("ldmatrix.sync.aligned.m8n8.x2.shared.b16 {%0,%1}, [%2];" \
                 : "=r"(r0), "=r"(r1) : "r"(addr))

#define MMA16816(c, a, b) \
    asm volatile("mma.sync.aligned.m16n8k16.row.col.f32.bf16.bf16.f32 " \
                 "{%0,%1,%2,%3}, {%4,%5,%6,%7}, {%8,%9}, {%0,%1,%2,%3};" \
                 : "+f"((c)[0]), "+f"((c)[1]), "+f"((c)[2]), "+f"((c)[3]) \
                 : "r"((a)[0]), "r"((a)[1]), "r"((a)[2]), "r"((a)[3]), \
                   "r"((b)[0]), "r"((b)[1]))

// monotone float -> u32 key (order-preserving)
__device__ __forceinline__ uint32_t fkey(float f) {
    uint32_t u = __float_as_uint(f);
    return (u & 0x80000000u) ? ~u : (u | 0x80000000u);
}

// ---------------------------------------------------------------------------
// hi/lo bf16 split helpers
// ---------------------------------------------------------------------------
__device__ __forceinline__ void split4(float4 v, uint2& hi, uint2& lo) {
    float f[4] = {v.x, v.y, v.z, v.w};
    unsigned short h[4], l[4];
#pragma unroll
    for (int i = 0; i < 4; i++) {
        __nv_bfloat16 hb = __float2bfloat16(f[i]);
        h[i] = __bfloat16_as_ushort(hb);
        l[i] = __bfloat16_as_ushort(__float2bfloat16(f[i] - __bfloat162float(hb)));
    }
    hi.x = (uint32_t)h[0] | ((uint32_t)h[1] << 16);
    hi.y = (uint32_t)h[2] | ((uint32_t)h[3] << 16);
    lo.x = (uint32_t)l[0] | ((uint32_t)l[1] << 16);
    lo.y = (uint32_t)l[2] | ((uint32_t)l[3] << 16);
}

// ---------------------------------------------------------------------------
// Prep kernels (conv_x eliminated: gemm1 splits x on the fly)
// ---------------------------------------------------------------------------
__global__ __launch_bounds__(256)
void conv_w_kernel(const float* __restrict__ W) {
    if (blockIdx.x == 0 && threadIdx.x == 0) g_flag_count = 0;   // fused reset
    size_t gid = (size_t)blockIdx.x * 256 + threadIdx.x;
    int n = (int)(gid >> 10);
    int k = (int)(gid & 1023);
    float v = W[(size_t)k * CD + n];
    __nv_bfloat16 hb = __float2bfloat16(v);
    g_w_hi[gid] = __bfloat16_as_ushort(hb);
    g_w_lo[gid] = __bfloat16_as_ushort(__float2bfloat16(v - __bfloat162float(hb)));
}

// conv_cb + halfnorm fused: one warp per code, single cb read.
__global__ __launch_bounds__(256)
void cb_prep_kernel(const float* __restrict__ cb) {
    const int warp = threadIdx.x >> 5;
    const int lane = threadIdx.x & 31;
    const int code = blockIdx.x * 8 + warp;
    const float4* c4 = (const float4*)cb;
    size_t base = (size_t)code * 64;
    float4 v0 = c4[base + lane];
    float4 v1 = c4[base + 32 + lane];

    float s = v0.x*v0.x + v0.y*v0.y + v0.z*v0.z + v0.w*v0.w
            + v1.x*v1.x + v1.y*v1.y + v1.z*v1.z + v1.w*v1.w;
#pragma unroll
    for (int o = 16; o > 0; o >>= 1) s += __shfl_xor_sync(0xFFFFFFFFu, s, o);
    if (lane == 0) g_half_norm[code] = 0.5f * s;

    uint2 h0, l0, h1, l1;
    split4(v0, h0, l0);
    split4(v1, h1, l1);
    size_t kb = (size_t)code * CD + lane * 4;
    *(uint2*)&g_cb_hi[kb]       = h0;
    *(uint2*)&g_cb_lo[kb]       = l0;
    *(uint2*)&g_cb_hi[kb + 128] = h1;
    *(uint2*)&g_cb_lo[kb + 128] = l1;
}

// normalize + hi/lo conversion fused
__global__ __launch_bounds__(256)
void normalize_kernel(float* __restrict__ z) {
    const int warp = threadIdx.x >> 5;
    const int lane = threadIdx.x & 31;
    const int row  = blockIdx.x * 8 + warp;
    float4* z4 = (float4*)z;
    size_t base = (size_t)row * 64;
    float4 v0 = z4[base + lane];
    float4 v1 = z4[base + 32 + lane];
    float s = v0.x*v0.x + v0.y*v0.y + v0.z*v0.z + v0.w*v0.w
            + v1.x*v1.x + v1.y*v1.y + v1.z*v1.z + v1.w*v1.w;
#pragma unroll
    for (int o = 16; o > 0; o >>= 1) s += __shfl_xor_sync(0xFFFFFFFFu, s, o);
    float inv = 1.0f / (sqrtf(s) + 1e-6f);
    v0.x *= inv; v0.y *= inv; v0.z *= inv; v0.w *= inv;
    v1.x *= inv; v1.y *= inv; v1.z *= inv; v1.w *= inv;
    z4[base + lane]      = v0;
    z4[base + 32 + lane] = v1;

    uint2 h0, l0, h1, l1;
    split4(v0, h0, l0);
    split4(v1, h1, l1);
    size_t kb = (size_t)row * CD + lane * 4;
    *(uint2*)&g_z_hi[kb]       = h0;
    *(uint2*)&g_z_lo[kb]       = l0;
    *(uint2*)&g_z_hi[kb + 128] = h1;
    *(uint2*)&g_z_lo[kb + 128] = l1;
}

// ---------------------------------------------------------------------------
// GEMM1 v3 (mma.sync, 3-pass): BM=64, BN=128, 2 CTAs/SM.
// x loaded DIRECTLY as fp32 via LDG, split to hi/lo bf16 in registers,
// stored to smem with STS (conv_x kernel eliminated).  W stays cp.async.
// ---------------------------------------------------------------------------
#define G1_XSTRIDE 9216
#define G1_WSTRIDE 18432
#define G1_SMEM (4 * G1_XSTRIDE + 4 * G1_WSTRIDE)   // 110592

__device__ __forceinline__ void g1_load_w(uint32_t WS, int buf, int kc,
                                          int colBase, int t) {
#pragma unroll
    for (int q = 0; q < 8; q++) {
        int i = t + 256 * q;
        int hl = i >> 10, rem = i & 1023;
        int r = rem >> 3, cc = rem & 7;
        const unsigned short* src = (hl ? g_w_lo : g_w_hi)
            + (size_t)(colBase + r) * DMODEL + kc * 64 + cc * 8;
        cp16(WS + (buf * 2 + hl) * G1_WSTRIDE + r * 144 + cc * 16, src);
    }
}

__device__ __forceinline__ void g1_load_x(unsigned char* smem, const float* __restrict__ x,
                                          int buf, int kc, int rowBase, int t) {
    // x tile: 64 rows x 64 floats = 1024 float4 slots; 4 per thread.
#pragma unroll
    for (int q = 0; q < 4; q++) {
        int i = t + 256 * q;           // 0..1023
        int r = i >> 4;                // 0..63
        int c4 = i & 15;               // float4 column
        float4 v = *(const float4*)&x[(size_t)(rowBase + r) * DMODEL + kc * 64 + c4 * 4];
        uint2 hi, lo; split4(v, hi, lo);
        unsigned char* base = smem + (buf * 2) * G1_XSTRIDE + r * 144 + c4 * 8;
        *(uint2*)base                 = hi;
        *(uint2*)(base + G1_XSTRIDE)  = lo;
    }
}

__global__ __launch_bounds__(256, 2)
void gemm1_mma_kernel(const float* __restrict__ x, const float* __restrict__ bias,
                      float* __restrict__ z) {
    extern __shared__ unsigned char smem[];
    const uint32_t sb = smem_u32(smem);
    const uint32_t XS = sb;
    const uint32_t WS = sb + 4 * G1_XSTRIDE;
    unsigned char* xs_ptr = smem;

    const int t = threadIdx.x, lane = t & 31, w = t >> 5;
    const int warpM = w & 1, warpN = w >> 1;
    const int rowBase = blockIdx.x * 64;
    const int colBase = blockIdx.y * 128;

    float acc[2][4][4];
#pragma unroll
    for (int mt = 0; mt < 2; mt++)
#pragma unroll
        for (int nt = 0; nt < 4; nt++)
#pragma unroll
            for (int c = 0; c < 4; c++) acc[mt][nt][c] = 0.0f;

    const uint32_t a_row  = warpM * 32 + (lane & 15);
    const uint32_t a_col8 = (lane >> 4) * 8;
    const uint32_t b_row  = warpN * 32 + (lane & 7);
    const uint32_t b_col8 = ((lane >> 3) & 1) * 8;

    g1_load_w(WS, 0, 0, colBase, t);
    CP_COMMIT();
    g1_load_x(xs_ptr, x, 0, 0, rowBase, t);

    for (int kc = 0; kc < 16; kc++) {
        const int buf = kc & 1;
        if (kc + 1 < 16) {
            g1_load_w(WS, (kc + 1) & 1, kc + 1, colBase, t);
            CP_COMMIT();
            g1_load_x(xs_ptr, x, (kc + 1) & 1, kc + 1, rowBase, t);
            CP_WAIT(1);
        } else {
            CP_WAIT(0);
        }
        __syncthreads();

#pragma unroll
        for (int ks = 0; ks < 4; ks++) {
            uint32_t bh[4][2], bl[4][2];
#pragma unroll
            for (int nt = 0; nt < 4; nt++) {
                uint32_t baddr = WS + (buf * 2) * G1_WSTRIDE + ((b_row + nt * 8) * 72 + ks * 16 + b_col8) * 2;
                LDSM2(bh[nt][0], bh[nt][1], baddr);
                LDSM2(bl[nt][0], bl[nt][1], baddr + G1_WSTRIDE);
            }
#pragma unroll
            for (int mt = 0; mt < 2; mt++) {
                uint32_t ah[4], al[4];
                uint32_t aaddr = XS + (buf * 2) * G1_XSTRIDE + ((a_row + mt * 16) * 72 + ks * 16 + a_col8) * 2;
                LDSM4(ah[0], ah[1], ah[2], ah[3], aaddr);
                LDSM4(al[0], al[1], al[2], al[3], aaddr + G1_XSTRIDE);
#pragma unroll
                for (int nt = 0; nt < 4; nt++) {
                    MMA16816(acc[mt][nt], ah, bh[nt]);
                    MMA16816(acc[mt][nt], ah, bl[nt]);
                    MMA16816(acc[mt][nt], al, bh[nt]);
                }
            }
        }
        __syncthreads();
    }

    const int row0 = rowBase + warpM * 32 + (lane >> 2);
    const int col0 = colBase + warpN * 32 + (lane & 3) * 2;
#pragma unroll
    for (int mt = 0; mt < 2; mt++) {
#pragma unroll
        for (int nt = 0; nt < 4; nt++) {
            int r0 = row0 + mt * 16;
            int c  = col0 + nt * 8;
            float b0 = __ldg(&bias[c]), b1 = __ldg(&bias[c + 1]);
            *(float2*)&z[(size_t)r0 * CD + c]       = make_float2(acc[mt][nt][0] + b0, acc[mt][nt][1] + b1);
            *(float2*)&z[(size_t)(r0 + 8) * CD + c] = make_float2(acc[mt][nt][2] + b0, acc[mt][nt][3] + b1);
        }
    }
}

// ---------------------------------------------------------------------------
// Quant v4: 128 tokens per CTA, 2 z-groups x (2M x 2N), warp tile 32x64.
// Unchanged from R15 (proven).
// ---------------------------------------------------------------------------
#define Q_ZBYTES   (128 * 528)           // 67584
#define Q_CBSTRIDE 18432                 // 128 codes * 144B
#define Q_SMEM     (Q_ZBYTES + 2 * Q_CBSTRIDE)   // 104448

__device__ __forceinline__ void top2_merge(float& b1, int& i1, float& b2,
                                           float ob1, int oi1, float ob2) {
    if (ob1 > b1)      { b2 = fmaxf(b1, ob2); b1 = ob1; i1 = oi1; }
    else if (ob1 == b1){ if (oi1 != i1) b2 = b1; else b2 = fmaxf(b2, ob2); i1 = min(i1, oi1); }
    else               { b2 = fmaxf(b2, ob1); }
}

__device__ __forceinline__ void q_load_cb_hi(uint32_t CBB, int buf, int tile, int kc, int t) {
#pragma unroll
    for (int q = 0; q < 4; q++) {
        int i = t + 256 * q;               // 0..1023
        int r = i >> 3, cc = i & 7;        // r: 0..127
        int code = 1 + tile * 128 + r;
        if (code > NC - 1) code = NC - 1;
        cp16(CBB + buf * Q_CBSTRIDE + r * 144 + cc * 16,
             g_cb_hi + (size_t)code * CD + kc * 64 + cc * 8);
    }
}

__global__ __launch_bounds__(256, 2)
void quant_mma_kernel(const float* __restrict__ cb,
                      float* __restrict__ out_idx, float* __restrict__ out_hard) {
    extern __shared__ unsigned char smem[];
    const uint32_t sb  = smem_u32(smem);
    const uint32_t ZB  = sb;
    const uint32_t CBB = sb + Q_ZBYTES;

    const int t = threadIdx.x, lane = t & 31, w = t >> 5;
    const int zt    = w >> 2;
    const int wsub  = w & 3;
    const int warpM = wsub & 1;
    const int warpN = wsub >> 1;
    const int rowBase = blockIdx.x * 128;

#pragma unroll
    for (int q = 0; q < 16; q++) {
        int i = t + 256 * q;
        int r = i >> 5, cc = i & 31;
        cp16(ZB + r * 528 + cc * 16, g_z_hi + (size_t)(rowBase + r) * CD + cc * 8);
    }
    q_load_cb_hi(CBB, 0, 0, 0, t);
    CP_COMMIT();

    float acc[2][8][4];
#pragma unroll
    for (int mt = 0; mt < 2; mt++)
#pragma unroll
        for (int nt = 0; nt < 8; nt++)
#pragma unroll
            for (int c = 0; c < 4; c++) acc[mt][nt][c] = 0.0f;

    float best[4], sec[4];
    int   bidx[4];
#pragma unroll
    for (int s = 0; s < 4; s++) { best[s] = -3.0e38f; sec[s] = -3.0e38f; bidx[s] = 1; }

    const uint32_t a_row  = (uint32_t)(zt * 64 + warpM * 32 + (lane & 15));
    const uint32_t a_col8 = (lane >> 4) * 8;
    const uint32_t b_row  = (uint32_t)(warpN * 64 + (lane & 7));
    const uint32_t b_col8 = ((lane >> 3) & 1) * 8;

    for (int it = 0; it < 128; it++) {
        const int tile = it >> 2, kc = it & 3, buf = it & 1;
        if (it + 1 < 128) { q_load_cb_hi(CBB, (it + 1) & 1, (it + 1) >> 2, (it + 1) & 3, t); CP_COMMIT(); CP_WAIT(1); }
        else              { CP_WAIT(0); }
        __syncthreads();

#pragma unroll
        for (int ks = 0; ks < 4; ks++) {
            const int k = kc * 64 + ks * 16;
            uint32_t bh[8][2];
#pragma unroll
            for (int nt = 0; nt < 8; nt++) {
                uint32_t baddr = CBB + buf * Q_CBSTRIDE + ((b_row + nt * 8) * 72 + ks * 16 + b_col8) * 2;
                LDSM2(bh[nt][0], bh[nt][1], baddr);
            }
#pragma unroll
            for (int mt = 0; mt < 2; mt++) {
                uint32_t ah[4];
                uint32_t aaddr = ZB + ((a_row + mt * 16) * 264 + k + a_col8) * 2;
                LDSM4(ah[0], ah[1], ah[2], ah[3], aaddr);
#pragma unroll
                for (int nt = 0; nt < 8; nt++)
                    MMA16816(acc[mt][nt], ah, bh[nt]);
            }
        }
        __syncthreads();

        if (kc == 3) {
            const int codeTile = 1 + tile * 128 + warpN * 64;
#pragma unroll
            for (int nt = 0; nt < 8; nt++) {
                int c0 = codeTile + nt * 8 + (lane & 3) * 2;
                float hn0 = (c0 < NC)     ? __ldg(&g_half_norm[c0])     : 0.0f;
                float hn1 = (c0 + 1 < NC) ? __ldg(&g_half_norm[c0 + 1]) : 0.0f;
#pragma unroll
                for (int mt = 0; mt < 2; mt++) {
#pragma unroll
                    for (int h = 0; h < 2; h++) {
                        int s = mt * 2 + h;
                        if (c0 < NC) {
                            float v = acc[mt][nt][h * 2] - hn0;
                            if (v > best[s])      { sec[s] = best[s]; best[s] = v; bidx[s] = c0; }
                            else if (v > sec[s])  { sec[s] = v; }
                        }
                        if (c0 + 1 < NC) {
                            float v = acc[mt][nt][h * 2 + 1] - hn1;
                            if (v > best[s])      { sec[s] = best[s]; best[s] = v; bidx[s] = c0 + 1; }
                            else if (v > sec[s])  { sec[s] = v; }
                        }
                    }
                    acc[mt][nt][0] = 0.0f; acc[mt][nt][1] = 0.0f;
                    acc[mt][nt][2] = 0.0f; acc[mt][nt][3] = 0.0f;
                }
            }
        }
    }

    float* red_val = (float*)(smem + Q_ZBYTES);            // [128][2]
    float* red_sec = (float*)(smem + Q_ZBYTES + 1024);
    int*   red_idx = (int*)(smem + Q_ZBYTES + 2048);
    int*   row_idx = (int*)(smem + Q_ZBYTES + 3072);

#pragma unroll
    for (int slot = 0; slot < 4; slot++) {
        float b1 = best[slot], b2 = sec[slot]; int i1 = bidx[slot];
#pragma unroll
        for (int off = 1; off <= 2; off <<= 1) {
            float ob1 = __shfl_xor_sync(0xFFFFFFFFu, b1, off);
            int   oi1 = __shfl_xor_sync(0xFFFFFFFFu, i1, off);
            float ob2 = __shfl_xor_sync(0xFFFFFFFFu, b2, off);
            top2_merge(b1, i1, b2, ob1, oi1, ob2);
        }
        if ((lane & 3) == 0) {
            int mt = slot >> 1, h = slot & 1;
            int row = zt * 64 + warpM * 32 + mt * 16 + (lane >> 2) + h * 8;
            red_val[row * 2 + warpN] = b1;
            red_sec[row * 2 + warpN] = b2;
            red_idx[row * 2 + warpN] = i1;
        }
    }
    __syncthreads();

    if (t < 128) {
        float b1 = red_val[t * 2], b2 = red_sec[t * 2];
        int i1 = red_idx[t * 2];
        top2_merge(b1, i1, b2, red_val[t * 2 + 1], red_idx[t * 2 + 1], red_sec[t * 2 + 1]);
        row_idx[t] = i1;
        out_idx[rowBase + t] = (float)i1;
        if (b1 - b2 <= FLAG_THRESH) {
            int pos = atomicAdd(&g_flag_count, 1);
            g_flag_list[pos] = rowBase + t;
        }
    }
    __syncthreads();

    for (int r = 0; r < 128; r++) {
        int code = row_idx[r];
        out_hard[(size_t)(rowBase + r) * CD + t] = __ldg(&cb[(size_t)code * CD + t]);
    }
}

// ---------------------------------------------------------------------------
// Fixup (mma, 3-pass): code-split, merged via atomicMax — unchanged (proven).
// ---------------------------------------------------------------------------
#define F_ZBYTES  (2 * 128 * 264 * 2)
#define F_CBBYTES (4 * 18432)
#define F_SMEM    (F_ZBYTES + F_CBBYTES)

__device__ __forceinline__ void f_load_cb(uint32_t CBB, int buf, int tt, int kc, int t) {
#pragma unroll
    for (int q = 0; q < 8; q++) {
        int i = t + 256 * q;
        int hl = i >> 10, r = (i >> 3) & 127, cc = i & 7;
        int code = 1 + tt * 128 + r;
        if (code > NC - 1) code = NC - 1;
        const unsigned short* src = (hl ? g_cb_lo : g_cb_hi)
            + (size_t)code * CD + kc * 64 + cc * 8;
        cp16(CBB + (buf * 2 + hl) * 18432 + r * 144 + cc * 16, src);
    }
}

__global__ __launch_bounds__(256, 1)
void fixup_mma_kernel(float* __restrict__ out_idx) {
    __shared__ int s_tok[128];
    extern __shared__ unsigned char smem[];
    const uint32_t sb  = smem_u32(smem);
    const uint32_t ZB  = sb;
    const uint32_t CBB = sb + F_ZBYTES;

    const int t = threadIdx.x, lane = t & 31, w = t >> 5;
    const int warpM = w & 1, warpN = w >> 1;
    const int count = g_flag_count;
    const int tileTok = blockIdx.x >> 3;
    const int split   = blockIdx.x & 7;
    const int base    = tileTok * 128;
    if (base >= count) return;

    if (t < 128) {
        int idx = base + t;
        if (idx > count - 1) idx = count - 1;
        s_tok[t] = g_flag_list[idx];
    }
    __syncthreads();

#pragma unroll
    for (int q = 0; q < 32; q++) {
        int i = t + 256 * q;
        int hl = i >> 12, r = (i >> 5) & 127, cc = i & 31;
        const unsigned short* src = (hl ? g_z_lo : g_z_hi)
            + (size_t)s_tok[r] * CD + cc * 8;
        cp16(ZB + hl * 67584 + r * 528 + cc * 16, src);
    }
    f_load_cb(CBB, 0, split * 4, 0, t);
    CP_COMMIT();

    float acc[4][4][4];
#pragma unroll
    for (int mt = 0; mt < 4; mt++)
#pragma unroll
        for (int nt = 0; nt < 4; nt++)
#pragma unroll
            for (int c = 0; c < 4; c++) acc[mt][nt][c] = 0.0f;

    float best[8];
    int   bidx[8];
#pragma unroll
    for (int s = 0; s < 8; s++) { best[s] = -3.0e38f; bidx[s] = 1; }

    const uint32_t a_row  = warpM * 64 + (lane & 15);
    const uint32_t a_col8 = (lane >> 4) * 8;
    const uint32_t b_row  = warpN * 32 + (lane & 7);
    const uint32_t b_col8 = ((lane >> 3) & 1) * 8;

    for (int it = 0; it < 16; it++) {
        const int tt = split * 4 + (it >> 2), kc = it & 3, buf = it & 1;
        if (it + 1 < 16) { f_load_cb(CBB, (it + 1) & 1, split * 4 + ((it + 1) >> 2), (it + 1) & 3, t); CP_COMMIT(); CP_WAIT(1); }
        else             { CP_WAIT(0); }
        __syncthreads();

#pragma unroll
        for (int ks = 0; ks < 4; ks++) {
            const int k = kc * 64 + ks * 16;
            uint32_t bh[4][2], bl[4][2];
#pragma unroll
            for (int nt = 0; nt < 4; nt++) {
                uint32_t baddr = CBB + (buf * 2) * 18432 + ((b_row + nt * 8) * 72 + ks * 16 + b_col8) * 2;
                LDSM2(bh[nt][0], bh[nt][1], baddr);
                LDSM2(bl[nt][0], bl[nt][1], baddr + 18432);
            }
#pragma unroll
            for (int mt = 0; mt < 4; mt++) {
                uint32_t ah[4], al[4];
                uint32_t aaddr = ZB + ((a_row + mt * 16) * 264 + k + a_col8) * 2;
                LDSM4(ah[0], ah[1], ah[2], ah[3], aaddr);
                LDSM4(al[0], al[1], al[2], al[3], aaddr + 67584);
#pragma unroll
                for (int nt = 0; nt < 4; nt++) {
                    MMA16816(acc[mt][nt], ah, bh[nt]);
                    MMA16816(acc[mt][nt], ah, bl[nt]);
                    MMA16816(acc[mt][nt], al, bh[nt]);
                }
            }
        }
        __syncthreads();

        if (kc == 3) {
            const int codeTile = 1 + tt * 128 + warpN * 32;
#pragma unroll
            for (int nt = 0; nt < 4; nt++) {
                int c0 = codeTile + nt * 8 + (lane & 3) * 2;
                float hn0 = (c0 < NC)     ? __ldg(&g_half_norm[c0])     : 0.0f;
                float hn1 = (c0 + 1 < NC) ? __ldg(&g_half_norm[c0 + 1]) : 0.0f;
#pragma unroll
                for (int mt = 0; mt < 4; mt++) {
                    if (c0 < NC) {
                        float s0 = acc[mt][nt][0] - hn0;
                        if (s0 > best[mt * 2])     { best[mt * 2] = s0;     bidx[mt * 2] = c0; }
                        float s2 = acc[mt][nt][2] - hn0;
                        if (s2 > best[mt * 2 + 1]) { best[mt * 2 + 1] = s2; bidx[mt * 2 + 1] = c0; }
                    }
                    if (c0 + 1 < NC) {
                        float s1 = acc[mt][nt][1] - hn1;
                        if (s1 > best[mt * 2])     { best[mt * 2] = s1;     bidx[mt * 2] = c0 + 1; }
                        float s3 = acc[mt][nt][3] - hn1;
                        if (s3 > best[mt * 2 + 1]) { best[mt * 2 + 1] = s3; bidx[mt * 2 + 1] = c0 + 1; }
                    }
                    acc[mt][nt][0] = 0.0f; acc[mt][nt][1] = 0.0f;
                    acc[mt][nt][2] = 0.0f; acc[mt][nt][3] = 0.0f;
                }
            }
        }
    }

    float* red_val = (float*)(smem + F_ZBYTES);
    int*   red_idx = (int*)(smem + F_ZBYTES + 2048);

#pragma unroll
    for (int slot = 0; slot < 8; slot++) {
        float v = best[slot]; int ix = bidx[slot];
#pragma unroll
        for (int off = 1; off <= 2; off <<= 1) {
            float ov = __shfl_xor_sync(0xFFFFFFFFu, v, off);
            int   oi = __shfl_xor_sync(0xFFFFFFFFu, ix, off);
            if (ov > v || (ov == v && oi < ix)) { v = ov; ix = oi; }
        }
        if ((lane & 3) == 0) {
            int mt = slot >> 1, h = slot & 1;
            int row = warpM * 64 + mt * 16 + (lane >> 2) + h * 8;
            red_val[row * 4 + warpN] = v;
            red_idx[row * 4 + warpN] = ix;
        }
    }
    __syncthreads();

    if (t < 128) {
        float bv = red_val[t * 4]; int bi = red_idx[t * 4];
#pragma unroll
        for (int q = 1; q < 4; q++) {
            float v = red_val[t * 4 + q]; int ix = red_idx[t * 4 + q];
            if (v > bv || (v == bv && ix < bi)) { bv = v; bi = ix; }
        }
        unsigned long long pack =
            ((unsigned long long)fkey(bv) << 32) | (unsigned long long)(0xFFFFFFFFu - (uint32_t)bi);
        atomicMax(&g_merge[s_tok[t]], pack);
    }
}

// ---------------------------------------------------------------------------
// Apply: write out_idx / out_hard for flagged tokens from g_merge.
// ---------------------------------------------------------------------------
__global__ __launch_bounds__(256)
void apply_kernel(const float* __restrict__ cb,
                  float* __restrict__ out_idx, float* __restrict__ out_hard) {
    __shared__ int s_tok[128];
    __shared__ int s_code[128];
    const int t = threadIdx.x;
    const int count = g_flag_count;
    const int base = blockIdx.x * 128;
    if (base >= count) return;

    if (t < 128) {
        int idx = base + t;
        if (idx > count - 1) idx = count - 1;
        int token = g_flag_list[idx];
        unsigned long long m = g_merge[token];
        int code = (int)(0xFFFFFFFFu - (uint32_t)(m & 0xFFFFFFFFull));
        s_tok[t] = token;
        s_code[t] = code;
        out_idx[token] = (float)code;
    }
    __syncthreads();

    for (int r = 0; r < 128; r++) {
        int code  = s_code[r];
        int token = s_tok[r];
        out_hard[(size_t)token * CD + t] = __ldg(&cb[(size_t)code * CD + t]);
    }
}

// ---------------------------------------------------------------------------
// Launch
// ---------------------------------------------------------------------------
extern "C" void kernel_launch(void* const* d_in, const int* in_sizes, int n_in,
                              void* d_out, int out_size) {
    const float* x  = (const float*)d_in[0];   // [32768, 1024]
    const float* cb = (const float*)d_in[1];   // [4096, 256]
    const float* W  = (const float*)d_in[2];   // [1024, 256]
    const float* b  = (const float*)d_in[3];   // [256]

    float* out   = (float*)d_out;
    float* z     = out;                              // [32768, 256]
    float* oidx  = out + (size_t)M_TOK * CD;         // [32768]
    float* ohard = oidx + M_TOK;                     // [32768, 256]

    cudaFuncSetAttribute(gemm1_mma_kernel, cudaFuncAttributeMaxDynamicSharedMemorySize, G1_SMEM);
    cudaFuncSetAttribute(quant_mma_kernel, cudaFuncAttributeMaxDynamicSharedMemorySize, Q_SMEM);
    cudaFuncSetAttribute(fixup_mma_kernel, cudaFuncAttributeMaxDynamicSharedMemorySize, F_SMEM);

    conv_w_kernel<<<(CD * DMODEL) / 256, 256>>>(W);
    cb_prep_kernel<<<NC / 8, 256>>>(cb);

    gemm1_mma_kernel<<<dim3(M_TOK / 64, CD / 128), 256, G1_SMEM>>>(x, b, z);
    normalize_kernel<<<M_TOK / 8, 256>>>(z);

    quant_mma_kernel<<<M_TOK / 128, 256, Q_SMEM>>>(cb, oidx, ohard);
    fixup_mma_kernel<<<(M_TOK / 128) * 8, 256, F_SMEM>>>(oidx);
    apply_kernel<<<M_TOK / 128, 256>>>(cb, oidx, ohard);
}